// round 6
// baseline (speedup 1.0000x reference)
#include <cuda_runtime.h>
#include <cuda_bf16.h>
#include <mma.h>
#include <math.h>
#include <cstdint>

using namespace nvcuda;

// ---------------------------------------------------------------------------
// Shapes: B=2, H=W=256, C=128, S=16 -> G=256, N=256, CI=64, F1=384, HF=192
// R = 2 branches * B * G = 1024
// ---------------------------------------------------------------------------
#define R_TOT   1024
#define NPATCH  256
#define CI_DIM  64
#define HF_DIM  192

__device__ float g_bufin[R_TOT * NPATCH * CI_DIM];   // blocked gmlp input
__device__ float g_upre [R_TOT * NPATCH * HF_DIM];   // u pre-ln3; reused as gate [R][HF][N]
__device__ float g_v    [R_TOT * NPATCH * HF_DIM];   // v
__device__ float g_ut   [R_TOT * HF_DIM * NPATCH];   // reused as uv [R][N][HF]
__device__ float g_z    [R_TOT * NPATCH * CI_DIM];   // gmlp output
__device__ __nv_bfloat16 g_utb   [R_TOT * HF_DIM * NPATCH];   // ln3'd u^T, bf16
__device__ __nv_bfloat16 g_wsgub [HF_DIM * NPATCH * NPATCH];  // Wsgu^T bf16 [c][m][k]

__device__ __forceinline__ float gelu_exact(float x) {
    return 0.5f * x * (1.0f + erff(x * 0.7071067811865476f));
}

// ---- packed fp32 helpers ----
__device__ __forceinline__ unsigned long long pack2(float lo, float hi) {
    unsigned long long r;
    asm("mov.b64 %0, {%1, %2};" : "=l"(r) : "f"(lo), "f"(hi));
    return r;
}
__device__ __forceinline__ void fma2(unsigned long long& d,
                                     unsigned long long a, unsigned long long b) {
    asm("fma.rn.f32x2 %0, %1, %2, %0;" : "+l"(d) : "l"(a), "l"(b));
}
__device__ __forceinline__ void unpack2(float& lo, float& hi, unsigned long long v) {
    asm("mov.b64 {%0, %1}, %2;" : "=f"(lo), "=f"(hi) : "l"(v));
}

// ---------------------------------------------------------------------------
// K0: Wsgu [c][n][m] fp32 -> g_wsgub [c][m][n] bf16 (transpose + convert)
// ---------------------------------------------------------------------------
__global__ __launch_bounds__(256) void k0_wsgu_t(const float* __restrict__ Wsgu)
{
    __shared__ float tile[32][33];
    const int c  = blockIdx.z;
    const int mb = blockIdx.x * 32;
    const int nb = blockIdx.y * 32;
    const int tx = threadIdx.x, ty = threadIdx.y;
#pragma unroll
    for (int j = 0; j < 4; ++j) {
        int n = ty + j * 8;
        tile[n][tx] = Wsgu[(((size_t)c << 8) + nb + n) * 256 + mb + tx];
    }
    __syncthreads();
#pragma unroll
    for (int j = 0; j < 4; ++j) {
        int m = ty + j * 8;
        g_wsgub[(((size_t)c << 8) + mb + m) * 256 + nb + tx] =
            __float2bfloat16(tile[tx][m]);
    }
}

// ---------------------------------------------------------------------------
// K1: ln1 + Dense(W_proj) + GELU, scatter into blocked layout
// ---------------------------------------------------------------------------
__global__ __launch_bounds__(256) void k1_ln_proj(
    const float* __restrict__ x, const float* __restrict__ ln1g,
    const float* __restrict__ ln1b, const float* __restrict__ Wp,
    const float* __restrict__ bp)
{
    __shared__ float sR[16][132];
    __shared__ float sg[128], sb[128];
    __shared__ float smean[16], srs[16];
    const int t = threadIdx.x;
    const int pbase = blockIdx.x * 16;

    if (t < 128) { sg[t] = ln1g[t]; sb[t] = ln1b[t]; }
    const float* xblk = x + (size_t)pbase * 128;
#pragma unroll
    for (int it = 0; it < 8; ++it) {
        int lin = t + it * 256;
        sR[lin >> 7][lin & 127] = xblk[lin];
    }
    __syncthreads();

    const int warp = t >> 5, lane = t & 31;
#pragma unroll
    for (int rr = 0; rr < 2; ++rr) {
        int p = warp * 2 + rr;
        float s = 0.f, s2 = 0.f;
#pragma unroll
        for (int j = 0; j < 4; ++j) {
            float v = sR[p][lane + j * 32];
            s += v; s2 += v * v;
        }
#pragma unroll
        for (int off = 16; off > 0; off >>= 1) {
            s  += __shfl_xor_sync(0xffffffffu, s,  off);
            s2 += __shfl_xor_sync(0xffffffffu, s2, off);
        }
        if (lane == 0) {
            float m = s * (1.f / 128.f);
            smean[p] = m;
            srs[p]   = rsqrtf(s2 * (1.f / 128.f) - m * m + 1e-3f);
        }
    }
    __syncthreads();
#pragma unroll
    for (int it = 0; it < 8; ++it) {
        int lin = t + it * 256;
        int p = lin >> 7, c = lin & 127;
        sR[p][c] = (sR[p][c] - smean[p]) * srs[p] * sg[c] + sb[c];
    }
    __syncthreads();

    const int f2 = t & 63;
    const int pg = t >> 6;
    float acc0[4], acc1[4];
#pragma unroll
    for (int i = 0; i < 4; ++i) { acc0[i] = 0.f; acc1[i] = 0.f; }
    const float2* Wp2 = (const float2*)Wp;
    for (int cc = 0; cc < 128; cc += 4) {
        float4 a0 = *(const float4*)&sR[pg * 4 + 0][cc];
        float4 a1 = *(const float4*)&sR[pg * 4 + 1][cc];
        float4 a2 = *(const float4*)&sR[pg * 4 + 2][cc];
        float4 a3 = *(const float4*)&sR[pg * 4 + 3][cc];
        float2 w0 = Wp2[(cc + 0) * 64 + f2];
        float2 w1 = Wp2[(cc + 1) * 64 + f2];
        float2 w2 = Wp2[(cc + 2) * 64 + f2];
        float2 w3 = Wp2[(cc + 3) * 64 + f2];
        float4 av[4] = {a0, a1, a2, a3};
#pragma unroll
        for (int i = 0; i < 4; ++i) {
            acc0[i] = fmaf(av[i].x, w0.x, acc0[i]); acc1[i] = fmaf(av[i].x, w0.y, acc1[i]);
            acc0[i] = fmaf(av[i].y, w1.x, acc0[i]); acc1[i] = fmaf(av[i].y, w1.y, acc1[i]);
            acc0[i] = fmaf(av[i].z, w2.x, acc0[i]); acc1[i] = fmaf(av[i].z, w2.y, acc1[i]);
            acc0[i] = fmaf(av[i].w, w3.x, acc0[i]); acc1[i] = fmaf(av[i].w, w3.y, acc1[i]);
        }
    }
    const float2 wb = ((const float2*)bp)[f2];
    const int branch = (f2 >= 32) ? 1 : 0;
    const int cloc = 2 * (f2 & 31);
#pragma unroll
    for (int i = 0; i < 4; ++i) {
        int p = pbase + pg * 4 + i;
        int b = p >> 16, h = (p >> 8) & 255, w = p & 255;
        int g  = ((h >> 4) << 4) | (w >> 4);
        int nn = ((h & 15) << 4) | (w & 15);
        float v0 = gelu_exact(acc0[i] + wb.x);
        float v1 = gelu_exact(acc1[i] + wb.y);
        int r = branch * 512 + (b << 8) + g;
        *(float2*)&g_bufin[(((r << 8) + nn) << 6) + cloc] = make_float2(v0, v1);
    }
}

// ---------------------------------------------------------------------------
// K2: ln2 + y = gelu(lnx @ W1[n] + b1[n]); split -> u_pre / v  (FFMA2)
// ---------------------------------------------------------------------------
__global__ __launch_bounds__(256) void k2_gmlp_in(
    const float* __restrict__ W1, const float* __restrict__ b1_,
    const float* __restrict__ ln2g, const float* __restrict__ ln2b)
{
    __shared__ float As[64][132];
    __shared__ float Bs[16][132];
    __shared__ float sg[64], sb[64];
    const int t = threadIdx.x;
    const int fbase = blockIdx.x * 128;
    const int rbase = blockIdx.y * 128;
    const int n = blockIdx.z;

    if (t < 64) { sg[t] = ln2g[t]; sb[t] = ln2b[t]; }

    {
        const int row = t >> 1, bsel = t & 1;
        const float* src = g_bufin + ((size_t)((rbase + row) << 8) + n) * 64;
        float4 va[8];
        float s = 0.f, s2 = 0.f;
#pragma unroll
        for (int j = 0; j < 8; ++j) {
            va[j] = *(const float4*)&src[bsel * 4 + j * 8];
            s  += va[j].x + va[j].y + va[j].z + va[j].w;
            s2 += va[j].x * va[j].x + va[j].y * va[j].y
                + va[j].z * va[j].z + va[j].w * va[j].w;
        }
        s  += __shfl_xor_sync(0xffffffffu, s,  1);
        s2 += __shfl_xor_sync(0xffffffffu, s2, 1);
        float m  = s * (1.f / 64.f);
        float rs = rsqrtf(s2 * (1.f / 64.f) - m * m + 1e-3f);
        __syncthreads();
#pragma unroll
        for (int j = 0; j < 8; ++j) {
            int k = bsel * 4 + j * 8;
            As[k + 0][row] = (va[j].x - m) * rs * sg[k + 0] + sb[k + 0];
            As[k + 1][row] = (va[j].y - m) * rs * sg[k + 1] + sb[k + 1];
            As[k + 2][row] = (va[j].z - m) * rs * sg[k + 2] + sb[k + 2];
            As[k + 3][row] = (va[j].w - m) * rs * sg[k + 3] + sb[k + 3];
        }
    }

    const int tx = t & 15, ty = t >> 4;
    const int m0 = tx * 4, r0 = ty * 4;
    unsigned long long acc2[4][8] = {};

    const int bm4 = (t & 31) * 4, bk0 = t >> 5;
    const float* Wn = W1 + (size_t)n * 64 * 384 + fbase;

    for (int kb = 0; kb < 4; ++kb) {
        __syncthreads();
        *(float4*)&Bs[bk0    ][bm4] = *(const float4*)&Wn[(kb * 16 + bk0    ) * 384 + bm4];
        *(float4*)&Bs[bk0 + 8][bm4] = *(const float4*)&Wn[(kb * 16 + bk0 + 8) * 384 + bm4];
        __syncthreads();
#pragma unroll
        for (int kk = 0; kk < 16; ++kk) {
            int k = kb * 16 + kk;
            ulonglong2 a01 = *(const ulonglong2*)&As[k][r0];
            ulonglong2 a23 = *(const ulonglong2*)&As[k][r0 + 64];
            float4 b0 = *(const float4*)&Bs[kk][m0];
            float4 b1 = *(const float4*)&Bs[kk][m0 + 64];
            unsigned long long ap[4] = {a01.x, a01.y, a23.x, a23.y};
            float brr[8] = {b0.x, b0.y, b0.z, b0.w, b1.x, b1.y, b1.z, b1.w};
#pragma unroll
            for (int j = 0; j < 8; ++j) {
                unsigned long long bb = pack2(brr[j], brr[j]);
                fma2(acc2[0][j], ap[0], bb);
                fma2(acc2[1][j], ap[1], bb);
                fma2(acc2[2][j], ap[2], bb);
                fma2(acc2[3][j], ap[3], bb);
            }
        }
    }

    float accf[8][8];
#pragma unroll
    for (int ip = 0; ip < 4; ++ip)
#pragma unroll
        for (int j = 0; j < 8; ++j)
            unpack2(accf[2 * ip][j], accf[2 * ip + 1][j], acc2[ip][j]);

#pragma unroll
    for (int jg = 0; jg < 2; ++jg) {
        int fg = fbase + m0 + jg * 64;
        float4 bias = *(const float4*)&b1_[n * 384 + fg];
        float* dst; int fo;
        if (fg < 192) { dst = g_upre; fo = fg; }
        else          { dst = g_v;    fo = fg - 192; }
#pragma unroll
        for (int i = 0; i < 8; ++i) {
            int row = rbase + (i < 4 ? r0 + i : 64 + r0 + i - 4);
            float4 o;
            o.x = gelu_exact(accf[i][jg * 4 + 0] + bias.x);
            o.y = gelu_exact(accf[i][jg * 4 + 1] + bias.y);
            o.z = gelu_exact(accf[i][jg * 4 + 2] + bias.z);
            o.w = gelu_exact(accf[i][jg * 4 + 3] + bias.w);
            *(float4*)&dst[((row << 8) + n) * 192 + fo] = o;
        }
    }
}

// ---------------------------------------------------------------------------
// K2b: ln3 over u (HF=192) + transpose -> g_utb[r][c][n] (bf16)
// ---------------------------------------------------------------------------
__global__ __launch_bounds__(256) void k2b_ln3_t(
    const float* __restrict__ ln3g, const float* __restrict__ ln3b)
{
    __shared__ float s[32][193];
    __shared__ float sm[32], sr[32];
    const int t = threadIdx.x;
    const int r = blockIdx.x;
    const int nb = blockIdx.y * 32;
    const float* src = g_upre + (((size_t)r << 8) + nb) * 192;
#pragma unroll
    for (int it = 0; it < 24; ++it) {
        int lin = t + it * 256;
        s[lin / 192][lin % 192] = src[lin];
    }
    __syncthreads();
    const int warp = t >> 5, lane = t & 31;
#pragma unroll
    for (int j = 0; j < 4; ++j) {
        int row = warp * 4 + j;
        float su = 0.f, s2 = 0.f;
#pragma unroll
        for (int k = 0; k < 6; ++k) { float v = s[row][lane + k * 32]; su += v; s2 += v * v; }
#pragma unroll
        for (int off = 16; off > 0; off >>= 1) {
            su += __shfl_xor_sync(0xffffffffu, su, off);
            s2 += __shfl_xor_sync(0xffffffffu, s2, off);
        }
        if (lane == 0) {
            float m = su * (1.f / 192.f);
            sm[row] = m;
            sr[row] = rsqrtf(s2 * (1.f / 192.f) - m * m + 1e-3f);
        }
    }
    __syncthreads();
    const int n_l = t & 31, c0 = t >> 5;
#pragma unroll
    for (int it = 0; it < 24; ++it) {
        int c = c0 + it * 8;
        float v = (s[n_l][c] - sm[n_l]) * sr[n_l] * ln3g[c] + ln3b[c];
        g_utb[((r * 192 + c) << 8) + nb + n_l] = __float2bfloat16(v);
    }
}

// ---------------------------------------------------------------------------
// K3: spatial gating via wmma bf16 (HMMA tensor path; tcgen05 PTX is not
// accepted at compute_103 virtual arch).  Per (rtile, c):
//   gate[128 rows][256 m] = utb[rows][c][:256] @ wsgubT[c][m][:256]
// Bias is folded into K3b. grid (8 rtiles, 192 c) x 512 thr.
// Warp grid 4x4; warp tile 32x64; BK=32 staged in padded smem.
// ---------------------------------------------------------------------------
#define K3_PA 40
#define K3_PB 40
__global__ __launch_bounds__(512) void k3_wmma()
{
    __shared__ __nv_bfloat16 sA[128 * K3_PA];
    __shared__ __nv_bfloat16 sB[256 * K3_PB];
    const int t = threadIdx.x;
    const int wid = t >> 5;
    const int wr = wid & 3;        // row group (32 rows)
    const int wc = wid >> 2;       // col group (64 m)
    const int rbase = blockIdx.x * 128;
    const int c = blockIdx.y;

    wmma::fragment<wmma::accumulator, 16, 16, 16, float> acc[2][4];
#pragma unroll
    for (int i = 0; i < 2; ++i)
#pragma unroll
        for (int j = 0; j < 4; ++j)
            wmma::fill_fragment(acc[i][j], 0.0f);

    const __nv_bfloat16* abase = g_utb + ((size_t)rbase * 192 + c) * 256;
    const __nv_bfloat16* bbase = g_wsgub + ((size_t)c << 16);

    const int ar = t >> 2,  ak = (t & 3) * 8;    // A loader: 4 thr/row
    const int br = t >> 1,  bk = (t & 1) * 16;   // B loader: 2 thr/row

    for (int kb = 0; kb < 256; kb += 32) {
        *(uint4*)&sA[ar * K3_PA + ak] =
            *(const uint4*)&abase[(size_t)ar * (192 * 256) + kb + ak];
        *(uint4*)&sB[br * K3_PB + bk] =
            *(const uint4*)&bbase[(size_t)br * 256 + kb + bk];
        *(uint4*)&sB[br * K3_PB + bk + 8] =
            *(const uint4*)&bbase[(size_t)br * 256 + kb + bk + 8];
        __syncthreads();

        wmma::fragment<wmma::matrix_a, 16, 16, 16, __nv_bfloat16, wmma::row_major> fa[2][2];
#pragma unroll
        for (int fr = 0; fr < 2; ++fr)
#pragma unroll
            for (int kk = 0; kk < 2; ++kk)
                wmma::load_matrix_sync(fa[fr][kk],
                    &sA[(wr * 32 + fr * 16) * K3_PA + kk * 16], K3_PA);

#pragma unroll
        for (int fc = 0; fc < 4; ++fc) {
            wmma::fragment<wmma::matrix_b, 16, 16, 16, __nv_bfloat16, wmma::col_major> fb0, fb1;
            wmma::load_matrix_sync(fb0, &sB[(wc * 64 + fc * 16) * K3_PB +  0], K3_PB);
            wmma::load_matrix_sync(fb1, &sB[(wc * 64 + fc * 16) * K3_PB + 16], K3_PB);
#pragma unroll
            for (int fr = 0; fr < 2; ++fr) {
                wmma::mma_sync(acc[fr][fc], fa[fr][0], fb0, acc[fr][fc]);
                wmma::mma_sync(acc[fr][fc], fa[fr][1], fb1, acc[fr][fc]);
            }
        }
        __syncthreads();
    }

    // store: gate[grow][c][m], row stride 192*256, cols contiguous
#pragma unroll
    for (int fr = 0; fr < 2; ++fr) {
#pragma unroll
        for (int fc = 0; fc < 4; ++fc) {
            int grow = rbase + wr * 32 + fr * 16;
            float* dst = g_upre + ((size_t)grow * 192 + c) * 256 + wc * 64 + fc * 16;
            wmma::store_matrix_sync(dst, acc[fr][fc], 192 * 256, wmma::mem_row_major);
        }
    }
}

// ---------------------------------------------------------------------------
// K3b: uv[r][n][c] = (gate[r][c][n] + bsgu[c][n]) * v[r][n][c]
// ---------------------------------------------------------------------------
__global__ __launch_bounds__(256) void k3b_gate_mul(const float* __restrict__ bsgu)
{
    __shared__ float s[32][33];
    const int t = threadIdx.x;
    const int r = blockIdx.x;
    const int nb = blockIdx.y * 32;
    const int cb = blockIdx.z * 32;
    {
        int n_l = t & 31, c0 = t >> 5;
#pragma unroll
        for (int it = 0; it < 4; ++it) {
            int cc = c0 + it * 8;
            s[cc][n_l] = g_upre[((r * 192 + cb + cc) << 8) + nb + n_l]
                       + bsgu[((cb + cc) << 8) + nb + n_l];
        }
    }
    __syncthreads();
    {
        int c_l = t & 31, n0 = t >> 5;
#pragma unroll
        for (int it = 0; it < 4; ++it) {
            int nn = n0 + it * 8;
            int idx = (((r << 8) + nb + nn) * 192) + cb + c_l;
            g_ut[idx] = s[c_l][nn] * g_v[idx];
        }
    }
}

// ---------------------------------------------------------------------------
// K4: z = uv @ W2[n] + b2[n] + bufin  (FFMA2)
// ---------------------------------------------------------------------------
__global__ __launch_bounds__(256) void k4_gmlp_out(
    const float* __restrict__ W2, const float* __restrict__ b2_)
{
    __shared__ float As[16][132];
    __shared__ float Bs[16][68];
    const int t = threadIdx.x;
    const int rbase = blockIdx.x * 128;
    const int n = blockIdx.y;

    const int tx = t & 15, ty = t >> 4;
    const int f0 = tx * 4, r0 = ty * 4;
    unsigned long long acc2[4][4] = {};

    const int a_row = t >> 1, a_b = t & 1;
    const float* a_src = g_ut + ((size_t)((rbase + a_row) << 8) + n) * 192;
    const int bf4 = (t & 15) * 4, bk = t >> 4;
    const float* b_src = W2 + (size_t)n * 192 * 64;

    for (int kb = 0; kb < 192; kb += 16) {
        float4 v0 = *(const float4*)&a_src[kb + a_b * 4];
        float4 v1 = *(const float4*)&a_src[kb + a_b * 4 + 8];
        float4 w0 = *(const float4*)&b_src[(kb + bk) * 64 + bf4];
        __syncthreads();
        {
            int k0 = a_b * 4;
            As[k0 + 0][a_row] = v0.x; As[k0 + 1][a_row] = v0.y;
            As[k0 + 2][a_row] = v0.z; As[k0 + 3][a_row] = v0.w;
            As[k0 + 8][a_row] = v1.x; As[k0 + 9][a_row] = v1.y;
            As[k0 +10][a_row] = v1.z; As[k0 +11][a_row] = v1.w;
            *(float4*)&Bs[bk][bf4] = w0;
        }
        __syncthreads();
#pragma unroll
        for (int k = 0; k < 16; ++k) {
            ulonglong2 a01 = *(const ulonglong2*)&As[k][r0];
            ulonglong2 a23 = *(const ulonglong2*)&As[k][r0 + 64];
            float4 b0 = *(const float4*)&Bs[k][f0];
            unsigned long long ap[4] = {a01.x, a01.y, a23.x, a23.y};
            float brr[4] = {b0.x, b0.y, b0.z, b0.w};
#pragma unroll
            for (int j = 0; j < 4; ++j) {
                unsigned long long bb = pack2(brr[j], brr[j]);
                fma2(acc2[0][j], ap[0], bb);
                fma2(acc2[1][j], ap[1], bb);
                fma2(acc2[2][j], ap[2], bb);
                fma2(acc2[3][j], ap[3], bb);
            }
        }
    }

    float accf[8][4];
#pragma unroll
    for (int ip = 0; ip < 4; ++ip)
#pragma unroll
        for (int j = 0; j < 4; ++j)
            unpack2(accf[2 * ip][j], accf[2 * ip + 1][j], acc2[ip][j]);

    float4 bias = *(const float4*)&b2_[(n << 6) + f0];
#pragma unroll
    for (int i = 0; i < 8; ++i) {
        int row = rbase + (i < 4 ? r0 + i : 64 + r0 + i - 4);
        int idx = (((row << 8) + n) << 6) + f0;
        float4 xin = *(const float4*)&g_bufin[idx];
        *(float4*)&g_z[idx] = make_float4(accf[i][0] + bias.x + xin.x,
                                          accf[i][1] + bias.y + xin.y,
                                          accf[i][2] + bias.z + xin.z,
                                          accf[i][3] + bias.w + xin.w);
    }
}

// ---------------------------------------------------------------------------
// K5: recon + concat + outer residual; glob out
// ---------------------------------------------------------------------------
__global__ __launch_bounds__(256) void k5_assemble(
    const float* __restrict__ x, float* __restrict__ out,
    float* __restrict__ gout, int write_glob)
{
    const int t = threadIdx.x;
    const int pix = blockIdx.x * 16 + (t >> 4);
    const int c = (t & 15) * 4;
    const int b = pix >> 16, h = (pix >> 8) & 255, w = pix & 255;
    const int gb  = ((h >> 4) << 4) | (w >> 4);
    const int nb2 = ((h & 15) << 4) | (w & 15);
    const int rl = (b << 8) + nb2;
    const int rg = 512 + (b << 8) + gb;
    float4 zl = *(const float4*)&g_z[(((rl << 8) + gb)  << 6) + c];
    float4 zg = *(const float4*)&g_z[(((rg << 8) + nb2) << 6) + c];
    float4 xa = *(const float4*)&x[pix * 128 + c];
    float4 xb = *(const float4*)&x[pix * 128 + 64 + c];
    *(float4*)&out[pix * 128 + c] =
        make_float4(zl.x + xa.x, zl.y + xa.y, zl.z + xa.z, zl.w + xa.w);
    *(float4*)&out[pix * 128 + 64 + c] =
        make_float4(zg.x + xb.x, zg.y + xb.y, zg.z + xb.z, zg.w + xb.w);
    if (write_glob)
        *(float4*)&gout[pix * 64 + c] = zg;
}

// ---------------------------------------------------------------------------
extern "C" void kernel_launch(void* const* d_in, const int* in_sizes, int n_in,
                              void* d_out, int out_size)
{
    const float* x    = (const float*)d_in[0];
    const float* ln1g = (const float*)d_in[1];
    const float* ln1b = (const float*)d_in[2];
    const float* Wp   = (const float*)d_in[3];
    const float* bp   = (const float*)d_in[4];
    const float* ln2g = (const float*)d_in[5];
    const float* ln2b = (const float*)d_in[6];
    const float* W1   = (const float*)d_in[7];
    const float* b1   = (const float*)d_in[8];
    const float* ln3g = (const float*)d_in[9];
    const float* ln3b = (const float*)d_in[10];
    const float* Wsgu = (const float*)d_in[11];
    const float* bsgu = (const float*)d_in[12];
    const float* W2   = (const float*)d_in[13];
    const float* b2   = (const float*)d_in[14];

    float* out = (float*)d_out;
    const int OUT_MAIN = 2 * 256 * 256 * 128;
    const int OUT_GLOB = 2 * 256 * 256 * 64;
    int write_glob = (out_size >= OUT_MAIN + OUT_GLOB) ? 1 : 0;
    float* gout = out + OUT_MAIN;

    k0_wsgu_t    <<<dim3(8, 8, 192), dim3(32, 8)>>>(Wsgu);
    k1_ln_proj   <<<8192, 256>>>(x, ln1g, ln1b, Wp, bp);
    k2_gmlp_in   <<<dim3(3, 8, 256), 256>>>(W1, b1, ln2g, ln2b);
    k2b_ln3_t    <<<dim3(1024, 8, 1), 256>>>(ln3g, ln3b);
    k3_wmma      <<<dim3(8, 192), 512>>>();
    k3b_gate_mul <<<dim3(1024, 8, 6), 256>>>(bsgu);
    k4_gmlp_out  <<<dim3(8, 256, 1), 256>>>(W2, b2);
    k5_assemble  <<<8192, 256>>>(x, out, gout, write_glob);
}

// round 8
// speedup vs baseline: 1.5217x; 1.5217x over previous
#include <cuda_runtime.h>
#include <cuda_bf16.h>
#include <mma.h>
#include <math.h>
#include <cstdint>

using namespace nvcuda;

// ---------------------------------------------------------------------------
// Shapes: B=2, H=W=256, C=128, S=16 -> G=256, N=256, CI=64, F1=384, HF=192
// R = 2 branches * B * G = 1024
// ---------------------------------------------------------------------------
#define R_TOT   1024
#define NPATCH  256
#define CI_DIM  64
#define HF_DIM  192

__device__ float g_bufin[R_TOT * NPATCH * CI_DIM];   // blocked gmlp input
__device__ float g_upre [R_TOT * NPATCH * HF_DIM];   // u pre-ln3; reused as gate [R][HF][N]
__device__ float g_v    [R_TOT * NPATCH * HF_DIM];   // v
__device__ float g_ut   [R_TOT * HF_DIM * NPATCH];   // reused as uv [R][N][HF]
__device__ float g_z    [R_TOT * NPATCH * CI_DIM];   // gmlp output
__device__ __nv_bfloat16 g_utb   [R_TOT * HF_DIM * NPATCH];   // ln3'd u^T, bf16
__device__ __nv_bfloat16 g_wsgub [HF_DIM * NPATCH * NPATCH];  // Wsgu^T bf16 [c][m][k]

__device__ __forceinline__ float gelu_exact(float x) {
    return 0.5f * x * (1.0f + erff(x * 0.7071067811865476f));
}

// ---- packed fp32 helpers ----
__device__ __forceinline__ unsigned long long pack2(float lo, float hi) {
    unsigned long long r;
    asm("mov.b64 %0, {%1, %2};" : "=l"(r) : "f"(lo), "f"(hi));
    return r;
}
__device__ __forceinline__ void fma2(unsigned long long& d,
                                     unsigned long long a, unsigned long long b) {
    asm("fma.rn.f32x2 %0, %1, %2, %0;" : "+l"(d) : "l"(a), "l"(b));
}
__device__ __forceinline__ void unpack2(float& lo, float& hi, unsigned long long v) {
    asm("mov.b64 {%0, %1}, %2;" : "=f"(lo), "=f"(hi) : "l"(v));
}

// ---- cp.async helpers ----
__device__ __forceinline__ void cp16(void* smem_dst, const void* gsrc) {
    uint32_t d = (uint32_t)__cvta_generic_to_shared(smem_dst);
    asm volatile("cp.async.cg.shared.global [%0], [%1], 16;"
                 :: "r"(d), "l"(gsrc) : "memory");
}
#define CP_COMMIT()  asm volatile("cp.async.commit_group;" ::: "memory")
#define CP_WAIT(n)   asm volatile("cp.async.wait_group %0;" :: "n"(n) : "memory")

// ---------------------------------------------------------------------------
// K0: Wsgu [c][n][m] fp32 -> g_wsgub [c][m][n] bf16 (transpose + convert)
// ---------------------------------------------------------------------------
__global__ __launch_bounds__(256) void k0_wsgu_t(const float* __restrict__ Wsgu)
{
    __shared__ float tile[32][33];
    const int c  = blockIdx.z;
    const int mb = blockIdx.x * 32;
    const int nb = blockIdx.y * 32;
    const int tx = threadIdx.x, ty = threadIdx.y;
#pragma unroll
    for (int j = 0; j < 4; ++j) {
        int n = ty + j * 8;
        tile[n][tx] = Wsgu[(((size_t)c << 8) + nb + n) * 256 + mb + tx];
    }
    __syncthreads();
#pragma unroll
    for (int j = 0; j < 4; ++j) {
        int m = ty + j * 8;
        g_wsgub[(((size_t)c << 8) + mb + m) * 256 + nb + tx] =
            __float2bfloat16(tile[tx][m]);
    }
}

// ---------------------------------------------------------------------------
// K1: ln1 + Dense(W_proj) + GELU, scatter into blocked layout
// ---------------------------------------------------------------------------
__global__ __launch_bounds__(256) void k1_ln_proj(
    const float* __restrict__ x, const float* __restrict__ ln1g,
    const float* __restrict__ ln1b, const float* __restrict__ Wp,
    const float* __restrict__ bp)
{
    __shared__ float sR[16][132];
    __shared__ float sg[128], sb[128];
    __shared__ float smean[16], srs[16];
    const int t = threadIdx.x;
    const int pbase = blockIdx.x * 16;

    if (t < 128) { sg[t] = ln1g[t]; sb[t] = ln1b[t]; }
    const float* xblk = x + (size_t)pbase * 128;
#pragma unroll
    for (int it = 0; it < 8; ++it) {
        int lin = t + it * 256;
        sR[lin >> 7][lin & 127] = xblk[lin];
    }
    __syncthreads();

    const int warp = t >> 5, lane = t & 31;
#pragma unroll
    for (int rr = 0; rr < 2; ++rr) {
        int p = warp * 2 + rr;
        float s = 0.f, s2 = 0.f;
#pragma unroll
        for (int j = 0; j < 4; ++j) {
            float v = sR[p][lane + j * 32];
            s += v; s2 += v * v;
        }
#pragma unroll
        for (int off = 16; off > 0; off >>= 1) {
            s  += __shfl_xor_sync(0xffffffffu, s,  off);
            s2 += __shfl_xor_sync(0xffffffffu, s2, off);
        }
        if (lane == 0) {
            float m = s * (1.f / 128.f);
            smean[p] = m;
            srs[p]   = rsqrtf(s2 * (1.f / 128.f) - m * m + 1e-3f);
        }
    }
    __syncthreads();
#pragma unroll
    for (int it = 0; it < 8; ++it) {
        int lin = t + it * 256;
        int p = lin >> 7, c = lin & 127;
        sR[p][c] = (sR[p][c] - smean[p]) * srs[p] * sg[c] + sb[c];
    }
    __syncthreads();

    const int f2 = t & 63;
    const int pg = t >> 6;
    float acc0[4], acc1[4];
#pragma unroll
    for (int i = 0; i < 4; ++i) { acc0[i] = 0.f; acc1[i] = 0.f; }
    const float2* Wp2 = (const float2*)Wp;
    for (int cc = 0; cc < 128; cc += 4) {
        float4 a0 = *(const float4*)&sR[pg * 4 + 0][cc];
        float4 a1 = *(const float4*)&sR[pg * 4 + 1][cc];
        float4 a2 = *(const float4*)&sR[pg * 4 + 2][cc];
        float4 a3 = *(const float4*)&sR[pg * 4 + 3][cc];
        float2 w0 = Wp2[(cc + 0) * 64 + f2];
        float2 w1 = Wp2[(cc + 1) * 64 + f2];
        float2 w2 = Wp2[(cc + 2) * 64 + f2];
        float2 w3 = Wp2[(cc + 3) * 64 + f2];
        float4 av[4] = {a0, a1, a2, a3};
#pragma unroll
        for (int i = 0; i < 4; ++i) {
            acc0[i] = fmaf(av[i].x, w0.x, acc0[i]); acc1[i] = fmaf(av[i].x, w0.y, acc1[i]);
            acc0[i] = fmaf(av[i].y, w1.x, acc0[i]); acc1[i] = fmaf(av[i].y, w1.y, acc1[i]);
            acc0[i] = fmaf(av[i].z, w2.x, acc0[i]); acc1[i] = fmaf(av[i].z, w2.y, acc1[i]);
            acc0[i] = fmaf(av[i].w, w3.x, acc0[i]); acc1[i] = fmaf(av[i].w, w3.y, acc1[i]);
        }
    }
    const float2 wb = ((const float2*)bp)[f2];
    const int branch = (f2 >= 32) ? 1 : 0;
    const int cloc = 2 * (f2 & 31);
#pragma unroll
    for (int i = 0; i < 4; ++i) {
        int p = pbase + pg * 4 + i;
        int b = p >> 16, h = (p >> 8) & 255, w = p & 255;
        int g  = ((h >> 4) << 4) | (w >> 4);
        int nn = ((h & 15) << 4) | (w & 15);
        float v0 = gelu_exact(acc0[i] + wb.x);
        float v1 = gelu_exact(acc1[i] + wb.y);
        int r = branch * 512 + (b << 8) + g;
        *(float2*)&g_bufin[(((r << 8) + nn) << 6) + cloc] = make_float2(v0, v1);
    }
}

// ---------------------------------------------------------------------------
// K2: ln2 + y = gelu(lnx @ W1[n] + b1[n]); split -> u_pre / v  (FFMA2)
// ---------------------------------------------------------------------------
__global__ __launch_bounds__(256) void k2_gmlp_in(
    const float* __restrict__ W1, const float* __restrict__ b1_,
    const float* __restrict__ ln2g, const float* __restrict__ ln2b)
{
    __shared__ float As[64][132];
    __shared__ float Bs[16][132];
    __shared__ float sg[64], sb[64];
    const int t = threadIdx.x;
    const int fbase = blockIdx.x * 128;
    const int rbase = blockIdx.y * 128;
    const int n = blockIdx.z;

    if (t < 64) { sg[t] = ln2g[t]; sb[t] = ln2b[t]; }

    {
        const int row = t >> 1, bsel = t & 1;
        const float* src = g_bufin + ((size_t)((rbase + row) << 8) + n) * 64;
        float4 va[8];
        float s = 0.f, s2 = 0.f;
#pragma unroll
        for (int j = 0; j < 8; ++j) {
            va[j] = *(const float4*)&src[bsel * 4 + j * 8];
            s  += va[j].x + va[j].y + va[j].z + va[j].w;
            s2 += va[j].x * va[j].x + va[j].y * va[j].y
                + va[j].z * va[j].z + va[j].w * va[j].w;
        }
        s  += __shfl_xor_sync(0xffffffffu, s,  1);
        s2 += __shfl_xor_sync(0xffffffffu, s2, 1);
        float m  = s * (1.f / 64.f);
        float rs = rsqrtf(s2 * (1.f / 64.f) - m * m + 1e-3f);
        __syncthreads();
#pragma unroll
        for (int j = 0; j < 8; ++j) {
            int k = bsel * 4 + j * 8;
            As[k + 0][row] = (va[j].x - m) * rs * sg[k + 0] + sb[k + 0];
            As[k + 1][row] = (va[j].y - m) * rs * sg[k + 1] + sb[k + 1];
            As[k + 2][row] = (va[j].z - m) * rs * sg[k + 2] + sb[k + 2];
            As[k + 3][row] = (va[j].w - m) * rs * sg[k + 3] + sb[k + 3];
        }
    }

    const int tx = t & 15, ty = t >> 4;
    const int m0 = tx * 4, r0 = ty * 4;
    unsigned long long acc2[4][8] = {};

    const int bm4 = (t & 31) * 4, bk0 = t >> 5;
    const float* Wn = W1 + (size_t)n * 64 * 384 + fbase;

    for (int kb = 0; kb < 4; ++kb) {
        __syncthreads();
        *(float4*)&Bs[bk0    ][bm4] = *(const float4*)&Wn[(kb * 16 + bk0    ) * 384 + bm4];
        *(float4*)&Bs[bk0 + 8][bm4] = *(const float4*)&Wn[(kb * 16 + bk0 + 8) * 384 + bm4];
        __syncthreads();
#pragma unroll
        for (int kk = 0; kk < 16; ++kk) {
            int k = kb * 16 + kk;
            ulonglong2 a01 = *(const ulonglong2*)&As[k][r0];
            ulonglong2 a23 = *(const ulonglong2*)&As[k][r0 + 64];
            float4 b0 = *(const float4*)&Bs[kk][m0];
            float4 b1 = *(const float4*)&Bs[kk][m0 + 64];
            unsigned long long ap[4] = {a01.x, a01.y, a23.x, a23.y};
            float brr[8] = {b0.x, b0.y, b0.z, b0.w, b1.x, b1.y, b1.z, b1.w};
#pragma unroll
            for (int j = 0; j < 8; ++j) {
                unsigned long long bb = pack2(brr[j], brr[j]);
                fma2(acc2[0][j], ap[0], bb);
                fma2(acc2[1][j], ap[1], bb);
                fma2(acc2[2][j], ap[2], bb);
                fma2(acc2[3][j], ap[3], bb);
            }
        }
    }

    float accf[8][8];
#pragma unroll
    for (int ip = 0; ip < 4; ++ip)
#pragma unroll
        for (int j = 0; j < 8; ++j)
            unpack2(accf[2 * ip][j], accf[2 * ip + 1][j], acc2[ip][j]);

#pragma unroll
    for (int jg = 0; jg < 2; ++jg) {
        int fg = fbase + m0 + jg * 64;
        float4 bias = *(const float4*)&b1_[n * 384 + fg];
        float* dst; int fo;
        if (fg < 192) { dst = g_upre; fo = fg; }
        else          { dst = g_v;    fo = fg - 192; }
#pragma unroll
        for (int i = 0; i < 8; ++i) {
            int row = rbase + (i < 4 ? r0 + i : 64 + r0 + i - 4);
            float4 o;
            o.x = gelu_exact(accf[i][jg * 4 + 0] + bias.x);
            o.y = gelu_exact(accf[i][jg * 4 + 1] + bias.y);
            o.z = gelu_exact(accf[i][jg * 4 + 2] + bias.z);
            o.w = gelu_exact(accf[i][jg * 4 + 3] + bias.w);
            *(float4*)&dst[((row << 8) + n) * 192 + fo] = o;
        }
    }
}

// ---------------------------------------------------------------------------
// K2b: ln3 over u (HF=192) + transpose -> g_utb[r][c][n] (bf16)
// ---------------------------------------------------------------------------
__global__ __launch_bounds__(256) void k2b_ln3_t(
    const float* __restrict__ ln3g, const float* __restrict__ ln3b)
{
    __shared__ float s[32][193];
    __shared__ float sm[32], sr[32];
    const int t = threadIdx.x;
    const int r = blockIdx.x;
    const int nb = blockIdx.y * 32;
    const float* src = g_upre + (((size_t)r << 8) + nb) * 192;
#pragma unroll
    for (int it = 0; it < 24; ++it) {
        int lin = t + it * 256;
        s[lin / 192][lin % 192] = src[lin];
    }
    __syncthreads();
    const int warp = t >> 5, lane = t & 31;
#pragma unroll
    for (int j = 0; j < 4; ++j) {
        int row = warp * 4 + j;
        float su = 0.f, s2 = 0.f;
#pragma unroll
        for (int k = 0; k < 6; ++k) { float v = s[row][lane + k * 32]; su += v; s2 += v * v; }
#pragma unroll
        for (int off = 16; off > 0; off >>= 1) {
            su += __shfl_xor_sync(0xffffffffu, su, off);
            s2 += __shfl_xor_sync(0xffffffffu, s2, off);
        }
        if (lane == 0) {
            float m = su * (1.f / 192.f);
            sm[row] = m;
            sr[row] = rsqrtf(s2 * (1.f / 192.f) - m * m + 1e-3f);
        }
    }
    __syncthreads();
    const int n_l = t & 31, c0 = t >> 5;
#pragma unroll
    for (int it = 0; it < 24; ++it) {
        int c = c0 + it * 8;
        float v = (s[n_l][c] - sm[n_l]) * sr[n_l] * ln3g[c] + ln3b[c];
        g_utb[((r * 192 + c) << 8) + nb + n_l] = __float2bfloat16(v);
    }
}

// ---------------------------------------------------------------------------
// K3: spatial gating via wmma bf16, cp.async double-buffered.
//   gate[128 rows][128 m] per CTA = utb[rows][c][:256] @ wsgubT[c][m][:256]
// 256 thr (reg cap 255 -> no accumulator spills), 8 warps 4x2,
// warp tile 32x64, BK=32, 2 smem stages. Bias folded into K3b.
// grid (8 rtiles, 2 mtiles, 192 c).
// ---------------------------------------------------------------------------
#define K3_LD 40
__global__ __launch_bounds__(256) void k3_wmma()
{
    __shared__ __nv_bfloat16 sA[2][128 * K3_LD];
    __shared__ __nv_bfloat16 sB[2][128 * K3_LD];
    const int t = threadIdx.x;
    const int wid = t >> 5;
    const int rbase = blockIdx.x * 128;
    const int mbase = blockIdx.y * 128;
    const int c = blockIdx.z;

    const __nv_bfloat16* abase = g_utb + ((size_t)rbase * 192 + c) * 256;
    const __nv_bfloat16* bbase = g_wsgub + ((size_t)c << 16) + (size_t)mbase * 256;

    const int lr = t >> 1;            // 0..127
    const int lk = (t & 1) * 16;      // 0 / 16

    wmma::fragment<wmma::accumulator, 16, 16, 16, float> acc[2][4];
#pragma unroll
    for (int i = 0; i < 2; ++i)
#pragma unroll
        for (int j = 0; j < 4; ++j)
            wmma::fill_fragment(acc[i][j], 0.0f);

    const int wr = (wid >> 1) * 32;   // warp row offset
    const int wm = (wid & 1) * 64;    // warp m offset

    // prefetch stage 0
    {
        const __nv_bfloat16* as = abase + (size_t)lr * (192 * 256) + lk;
        cp16(&sA[0][lr * K3_LD + lk], as);
        cp16(&sA[0][lr * K3_LD + lk + 8], as + 8);
        const __nv_bfloat16* bs = bbase + (size_t)lr * 256 + lk;
        cp16(&sB[0][lr * K3_LD + lk], bs);
        cp16(&sB[0][lr * K3_LD + lk + 8], bs + 8);
        CP_COMMIT();
    }

#pragma unroll
    for (int kb = 0; kb < 8; ++kb) {
        const int st = kb & 1;
        if (kb < 7) {
            const int kn = (kb + 1) * 32;
            const __nv_bfloat16* as = abase + (size_t)lr * (192 * 256) + kn + lk;
            cp16(&sA[st ^ 1][lr * K3_LD + lk], as);
            cp16(&sA[st ^ 1][lr * K3_LD + lk + 8], as + 8);
            const __nv_bfloat16* bs = bbase + (size_t)lr * 256 + kn + lk;
            cp16(&sB[st ^ 1][lr * K3_LD + lk], bs);
            cp16(&sB[st ^ 1][lr * K3_LD + lk + 8], bs + 8);
            CP_COMMIT();
            CP_WAIT(1);
        } else {
            CP_WAIT(0);
        }
        __syncthreads();

#pragma unroll
        for (int kk = 0; kk < 32; kk += 16) {
            wmma::fragment<wmma::matrix_a, 16, 16, 16, __nv_bfloat16, wmma::row_major> fa[2];
            wmma::load_matrix_sync(fa[0], &sA[st][(wr     ) * K3_LD + kk], K3_LD);
            wmma::load_matrix_sync(fa[1], &sA[st][(wr + 16) * K3_LD + kk], K3_LD);
#pragma unroll
            for (int j = 0; j < 4; ++j) {
                wmma::fragment<wmma::matrix_b, 16, 16, 16, __nv_bfloat16, wmma::col_major> fb;
                wmma::load_matrix_sync(fb, &sB[st][(wm + j * 16) * K3_LD + kk], K3_LD);
                wmma::mma_sync(acc[0][j], fa[0], fb, acc[0][j]);
                wmma::mma_sync(acc[1][j], fa[1], fb, acc[1][j]);
            }
        }
        __syncthreads();
    }

    // store: gate[grow][c][m], row stride 192*256, cols contiguous
#pragma unroll
    for (int fr = 0; fr < 2; ++fr) {
#pragma unroll
        for (int fc = 0; fc < 4; ++fc) {
            int grow = rbase + wr + fr * 16;
            float* dst = g_upre + ((size_t)grow * 192 + c) * 256 + mbase + wm + fc * 16;
            wmma::store_matrix_sync(dst, acc[fr][fc], 192 * 256, wmma::mem_row_major);
        }
    }
}

// ---------------------------------------------------------------------------
// K3b: uv[r][n][c] = (gate[r][c][n] + bsgu[c][n]) * v[r][n][c]
// ---------------------------------------------------------------------------
__global__ __launch_bounds__(256) void k3b_gate_mul(const float* __restrict__ bsgu)
{
    __shared__ float s[32][33];
    const int t = threadIdx.x;
    const int r = blockIdx.x;
    const int nb = blockIdx.y * 32;
    const int cb = blockIdx.z * 32;
    {
        int n_l = t & 31, c0 = t >> 5;
#pragma unroll
        for (int it = 0; it < 4; ++it) {
            int cc = c0 + it * 8;
            s[cc][n_l] = g_upre[((r * 192 + cb + cc) << 8) + nb + n_l]
                       + bsgu[((cb + cc) << 8) + nb + n_l];
        }
    }
    __syncthreads();
    {
        int c_l = t & 31, n0 = t >> 5;
#pragma unroll
        for (int it = 0; it < 4; ++it) {
            int nn = n0 + it * 8;
            int idx = (((r << 8) + nb + nn) * 192) + cb + c_l;
            g_ut[idx] = s[c_l][nn] * g_v[idx];
        }
    }
}

// ---------------------------------------------------------------------------
// K4: z = uv @ W2[n] + b2[n] + bufin  (FFMA2)
// ---------------------------------------------------------------------------
__global__ __launch_bounds__(256) void k4_gmlp_out(
    const float* __restrict__ W2, const float* __restrict__ b2_)
{
    __shared__ float As[16][132];
    __shared__ float Bs[16][68];
    const int t = threadIdx.x;
    const int rbase = blockIdx.x * 128;
    const int n = blockIdx.y;

    const int tx = t & 15, ty = t >> 4;
    const int f0 = tx * 4, r0 = ty * 4;
    unsigned long long acc2[4][4] = {};

    const int a_row = t >> 1, a_b = t & 1;
    const float* a_src = g_ut + ((size_t)((rbase + a_row) << 8) + n) * 192;
    const int bf4 = (t & 15) * 4, bk = t >> 4;
    const float* b_src = W2 + (size_t)n * 192 * 64;

    for (int kb = 0; kb < 192; kb += 16) {
        float4 v0 = *(const float4*)&a_src[kb + a_b * 4];
        float4 v1 = *(const float4*)&a_src[kb + a_b * 4 + 8];
        float4 w0 = *(const float4*)&b_src[(kb + bk) * 64 + bf4];
        __syncthreads();
        {
            int k0 = a_b * 4;
            As[k0 + 0][a_row] = v0.x; As[k0 + 1][a_row] = v0.y;
            As[k0 + 2][a_row] = v0.z; As[k0 + 3][a_row] = v0.w;
            As[k0 + 8][a_row] = v1.x; As[k0 + 9][a_row] = v1.y;
            As[k0 +10][a_row] = v1.z; As[k0 +11][a_row] = v1.w;
            *(float4*)&Bs[bk][bf4] = w0;
        }
        __syncthreads();
#pragma unroll
        for (int k = 0; k < 16; ++k) {
            ulonglong2 a01 = *(const ulonglong2*)&As[k][r0];
            ulonglong2 a23 = *(const ulonglong2*)&As[k][r0 + 64];
            float4 b0 = *(const float4*)&Bs[k][f0];
            unsigned long long ap[4] = {a01.x, a01.y, a23.x, a23.y};
            float brr[4] = {b0.x, b0.y, b0.z, b0.w};
#pragma unroll
            for (int j = 0; j < 4; ++j) {
                unsigned long long bb = pack2(brr[j], brr[j]);
                fma2(acc2[0][j], ap[0], bb);
                fma2(acc2[1][j], ap[1], bb);
                fma2(acc2[2][j], ap[2], bb);
                fma2(acc2[3][j], ap[3], bb);
            }
        }
    }

    float accf[8][4];
#pragma unroll
    for (int ip = 0; ip < 4; ++ip)
#pragma unroll
        for (int j = 0; j < 4; ++j)
            unpack2(accf[2 * ip][j], accf[2 * ip + 1][j], acc2[ip][j]);

    float4 bias = *(const float4*)&b2_[(n << 6) + f0];
#pragma unroll
    for (int i = 0; i < 8; ++i) {
        int row = rbase + (i < 4 ? r0 + i : 64 + r0 + i - 4);
        int idx = (((row << 8) + n) << 6) + f0;
        float4 xin = *(const float4*)&g_bufin[idx];
        *(float4*)&g_z[idx] = make_float4(accf[i][0] + bias.x + xin.x,
                                          accf[i][1] + bias.y + xin.y,
                                          accf[i][2] + bias.z + xin.z,
                                          accf[i][3] + bias.w + xin.w);
    }
}

// ---------------------------------------------------------------------------
// K5: recon + concat + outer residual; glob out
// ---------------------------------------------------------------------------
__global__ __launch_bounds__(256) void k5_assemble(
    const float* __restrict__ x, float* __restrict__ out,
    float* __restrict__ gout, int write_glob)
{
    const int t = threadIdx.x;
    const int pix = blockIdx.x * 16 + (t >> 4);
    const int c = (t & 15) * 4;
    const int b = pix >> 16, h = (pix >> 8) & 255, w = pix & 255;
    const int gb  = ((h >> 4) << 4) | (w >> 4);
    const int nb2 = ((h & 15) << 4) | (w & 15);
    const int rl = (b << 8) + nb2;
    const int rg = 512 + (b << 8) + gb;
    float4 zl = *(const float4*)&g_z[(((rl << 8) + gb)  << 6) + c];
    float4 zg = *(const float4*)&g_z[(((rg << 8) + nb2) << 6) + c];
    float4 xa = *(const float4*)&x[pix * 128 + c];
    float4 xb = *(const float4*)&x[pix * 128 + 64 + c];
    *(float4*)&out[pix * 128 + c] =
        make_float4(zl.x + xa.x, zl.y + xa.y, zl.z + xa.z, zl.w + xa.w);
    *(float4*)&out[pix * 128 + 64 + c] =
        make_float4(zg.x + xb.x, zg.y + xb.y, zg.z + xb.z, zg.w + xb.w);
    if (write_glob)
        *(float4*)&gout[pix * 64 + c] = zg;
}

// ---------------------------------------------------------------------------
extern "C" void kernel_launch(void* const* d_in, const int* in_sizes, int n_in,
                              void* d_out, int out_size)
{
    const float* x    = (const float*)d_in[0];
    const float* ln1g = (const float*)d_in[1];
    const float* ln1b = (const float*)d_in[2];
    const float* Wp   = (const float*)d_in[3];
    const float* bp   = (const float*)d_in[4];
    const float* ln2g = (const float*)d_in[5];
    const float* ln2b = (const float*)d_in[6];
    const float* W1   = (const float*)d_in[7];
    const float* b1   = (const float*)d_in[8];
    const float* ln3g = (const float*)d_in[9];
    const float* ln3b = (const float*)d_in[10];
    const float* Wsgu = (const float*)d_in[11];
    const float* bsgu = (const float*)d_in[12];
    const float* W2   = (const float*)d_in[13];
    const float* b2   = (const float*)d_in[14];

    float* out = (float*)d_out;
    const int OUT_MAIN = 2 * 256 * 256 * 128;
    const int OUT_GLOB = 2 * 256 * 256 * 64;
    int write_glob = (out_size >= OUT_MAIN + OUT_GLOB) ? 1 : 0;
    float* gout = out + OUT_MAIN;

    k0_wsgu_t    <<<dim3(8, 8, 192), dim3(32, 8)>>>(Wsgu);
    k1_ln_proj   <<<8192, 256>>>(x, ln1g, ln1b, Wp, bp);
    k2_gmlp_in   <<<dim3(3, 8, 256), 256>>>(W1, b1, ln2g, ln2b);
    k2b_ln3_t    <<<dim3(1024, 8, 1), 256>>>(ln3g, ln3b);
    k3_wmma      <<<dim3(8, 2, 192), 256>>>();
    k3b_gate_mul <<<dim3(1024, 8, 6), 256>>>(bsgu);
    k4_gmlp_out  <<<dim3(8, 256, 1), 256>>>(W2, b2);
    k5_assemble  <<<8192, 256>>>(x, out, gout, write_glob);
}

// round 9
// speedup vs baseline: 1.5280x; 1.0041x over previous
#include <cuda_runtime.h>
#include <cuda_bf16.h>
#include <mma.h>
#include <math.h>
#include <cstdint>

using namespace nvcuda;

// ---------------------------------------------------------------------------
// Shapes: B=2, H=W=256, C=128, S=16 -> G=256, N=256, CI=64, F1=384, HF=192
// R = 2 branches * B * G = 1024
// ---------------------------------------------------------------------------
#define R_TOT   1024
#define NPATCH  256
#define CI_DIM  64
#define HF_DIM  192

__device__ float  g_bufin[R_TOT * NPATCH * CI_DIM];   // blocked gmlp input (fp32, exact)
__device__ float2 g_stat [R_TOT * NPATCH];            // ln2 (mean, rstd) per (r,n)
__device__ float  g_v    [R_TOT * NPATCH * HF_DIM];   // v (fp32)
__device__ float  g_ut   [R_TOT * HF_DIM * NPATCH];   // uv [R][N][HF] (fp32)
__device__ float  g_z    [R_TOT * NPATCH * CI_DIM];   // gmlp output
__device__ __align__(16) __nv_bfloat16 g_upreb [R_TOT * NPATCH * HF_DIM]; // u bf16; later raw gate [r][c][n]
__device__ __align__(16) __nv_bfloat16 g_utb   [R_TOT * HF_DIM * NPATCH]; // ln3'd u^T bf16
__device__ __align__(16) __nv_bfloat16 g_wsgub [HF_DIM * NPATCH * NPATCH];// Wsgu^T bf16 [c][m][k]

__device__ __forceinline__ float gelu_exact(float x) {
    return 0.5f * x * (1.0f + erff(x * 0.7071067811865476f));
}

// ---- cp.async helpers (K3) ----
__device__ __forceinline__ void cp16(void* smem_dst, const void* gsrc) {
    uint32_t d = (uint32_t)__cvta_generic_to_shared(smem_dst);
    asm volatile("cp.async.cg.shared.global [%0], [%1], 16;"
                 :: "r"(d), "l"(gsrc) : "memory");
}
#define CP_COMMIT()  asm volatile("cp.async.commit_group;" ::: "memory")
#define CP_WAIT(n)   asm volatile("cp.async.wait_group %0;" :: "n"(n) : "memory")

// pack 8 floats -> 8 bf16 (uint4)
__device__ __forceinline__ uint4 pack8bf(const float* v) {
    union { __nv_bfloat16 h[8]; uint4 u; } r;
#pragma unroll
    for (int i = 0; i < 8; ++i) r.h[i] = __float2bfloat16(v[i]);
    return r.u;
}

// ---------------------------------------------------------------------------
// K0: Wsgu [c][n][m] fp32 -> g_wsgub [c][m][n] bf16
// ---------------------------------------------------------------------------
__global__ __launch_bounds__(256) void k0_wsgu_t(const float* __restrict__ Wsgu)
{
    __shared__ float tile[32][33];
    const int c  = blockIdx.z;
    const int mb = blockIdx.x * 32;
    const int nb = blockIdx.y * 32;
    const int tx = threadIdx.x, ty = threadIdx.y;
#pragma unroll
    for (int j = 0; j < 4; ++j) {
        int n = ty + j * 8;
        tile[n][tx] = Wsgu[(((size_t)c << 8) + nb + n) * 256 + mb + tx];
    }
    __syncthreads();
#pragma unroll
    for (int j = 0; j < 4; ++j) {
        int m = ty + j * 8;
        g_wsgub[(((size_t)c << 8) + mb + m) * 256 + nb + tx] =
            __float2bfloat16(tile[tx][m]);
    }
}

// ---------------------------------------------------------------------------
// K1: ln1 + Dense(W_proj) + GELU, scatter into blocked layout + ln2 stats
// ---------------------------------------------------------------------------
__global__ __launch_bounds__(256) void k1_ln_proj(
    const float* __restrict__ x, const float* __restrict__ ln1g,
    const float* __restrict__ ln1b, const float* __restrict__ Wp,
    const float* __restrict__ bp)
{
    __shared__ float sR[16][132];
    __shared__ float sg[128], sb[128];
    __shared__ float smean[16], srs[16];
    const int t = threadIdx.x;
    const int pbase = blockIdx.x * 16;

    if (t < 128) { sg[t] = ln1g[t]; sb[t] = ln1b[t]; }
    const float* xblk = x + (size_t)pbase * 128;
#pragma unroll
    for (int it = 0; it < 8; ++it) {
        int lin = t + it * 256;
        sR[lin >> 7][lin & 127] = xblk[lin];
    }
    __syncthreads();

    const int warp = t >> 5, lane = t & 31;
#pragma unroll
    for (int rr = 0; rr < 2; ++rr) {
        int p = warp * 2 + rr;
        float s = 0.f, s2 = 0.f;
#pragma unroll
        for (int j = 0; j < 4; ++j) {
            float v = sR[p][lane + j * 32];
            s += v; s2 += v * v;
        }
#pragma unroll
        for (int off = 16; off > 0; off >>= 1) {
            s  += __shfl_xor_sync(0xffffffffu, s,  off);
            s2 += __shfl_xor_sync(0xffffffffu, s2, off);
        }
        if (lane == 0) {
            float m = s * (1.f / 128.f);
            smean[p] = m;
            srs[p]   = rsqrtf(s2 * (1.f / 128.f) - m * m + 1e-3f);
        }
    }
    __syncthreads();
#pragma unroll
    for (int it = 0; it < 8; ++it) {
        int lin = t + it * 256;
        int p = lin >> 7, c = lin & 127;
        sR[p][c] = (sR[p][c] - smean[p]) * srs[p] * sg[c] + sb[c];
    }
    __syncthreads();

    const int f2 = t & 63;
    const int pg = t >> 6;
    float acc0[4], acc1[4];
#pragma unroll
    for (int i = 0; i < 4; ++i) { acc0[i] = 0.f; acc1[i] = 0.f; }
    const float2* Wp2 = (const float2*)Wp;
    for (int cc = 0; cc < 128; cc += 4) {
        float4 a0 = *(const float4*)&sR[pg * 4 + 0][cc];
        float4 a1 = *(const float4*)&sR[pg * 4 + 1][cc];
        float4 a2 = *(const float4*)&sR[pg * 4 + 2][cc];
        float4 a3 = *(const float4*)&sR[pg * 4 + 3][cc];
        float2 w0 = Wp2[(cc + 0) * 64 + f2];
        float2 w1 = Wp2[(cc + 1) * 64 + f2];
        float2 w2 = Wp2[(cc + 2) * 64 + f2];
        float2 w3 = Wp2[(cc + 3) * 64 + f2];
        float4 av[4] = {a0, a1, a2, a3};
#pragma unroll
        for (int i = 0; i < 4; ++i) {
            acc0[i] = fmaf(av[i].x, w0.x, acc0[i]); acc1[i] = fmaf(av[i].x, w0.y, acc1[i]);
            acc0[i] = fmaf(av[i].y, w1.x, acc0[i]); acc1[i] = fmaf(av[i].y, w1.y, acc1[i]);
            acc0[i] = fmaf(av[i].z, w2.x, acc0[i]); acc1[i] = fmaf(av[i].z, w2.y, acc1[i]);
            acc0[i] = fmaf(av[i].w, w3.x, acc0[i]); acc1[i] = fmaf(av[i].w, w3.y, acc1[i]);
        }
    }
    const float2 wb = ((const float2*)bp)[f2];
    const int branch = (f2 >= 32) ? 1 : 0;
    const int cloc = 2 * (f2 & 31);

    float vv0[4], vv1[4];
    int ridx[4], nidx[4];
#pragma unroll
    for (int i = 0; i < 4; ++i) {
        int p = pbase + pg * 4 + i;
        int b = p >> 16, h = (p >> 8) & 255, w = p & 255;
        int g  = ((h >> 4) << 4) | (w >> 4);
        int nn = ((h & 15) << 4) | (w & 15);
        vv0[i] = gelu_exact(acc0[i] + wb.x);
        vv1[i] = gelu_exact(acc1[i] + wb.y);
        int r = branch * 512 + (b << 8) + g;
        ridx[i] = r; nidx[i] = nn;
        *(float2*)&g_bufin[(((r << 8) + nn) << 6) + cloc] = make_float2(vv0[i], vv1[i]);
    }
    // ln2 stats: this warp holds all 64 channels of (pixel i, branch)
#pragma unroll
    for (int i = 0; i < 4; ++i) {
        float s  = vv0[i] + vv1[i];
        float s2 = vv0[i] * vv0[i] + vv1[i] * vv1[i];
#pragma unroll
        for (int off = 16; off > 0; off >>= 1) {
            s  += __shfl_xor_sync(0xffffffffu, s,  off);
            s2 += __shfl_xor_sync(0xffffffffu, s2, off);
        }
        if (lane == 0) {
            float m  = s * (1.f / 64.f);
            float rs = rsqrtf(s2 * (1.f / 64.f) - m * m + 1e-3f);
            g_stat[(ridx[i] << 8) + nidx[i]] = make_float2(m, rs);
        }
    }
}

// ---------------------------------------------------------------------------
// K2: tf32 wmma: y = gelu(ln2(bufin) @ W1[n] + b1[n]); u -> bf16, v -> fp32
// grid (3 ftiles, 8 rtiles, 256 n) x 256 thr.  Block 128 rows x 128 f, K=64.
// A resident (ln2 applied via precomputed stats); B staged BK=16 via regs.
// ---------------------------------------------------------------------------
__global__ __launch_bounds__(256) void k2_gmlp_in(
    const float* __restrict__ W1, const float* __restrict__ b1_,
    const float* __restrict__ ln2g, const float* __restrict__ ln2b)
{
    __shared__ float sA[64 * 128];     // A^T [k][row]; reused as epilogue scratch
    __shared__ float sB[16 * 128];     // B stage [k][f]
    __shared__ float sg[64], sb[64];
    const int t = threadIdx.x;
    const int wid = t >> 5, lane = t & 31;
    const int fbase = blockIdx.x * 128;
    const int rbase = blockIdx.y * 128;
    const int n = blockIdx.z;

    if (t < 64) { sg[t] = ln2g[t]; sb[t] = ln2b[t]; }
    __syncthreads();

    // A load + ln2 (2 threads/row; each does 32 k-values)
    {
        const int row = t >> 1, half = t & 1;
        const float* src = g_bufin + ((size_t)((rbase + row) << 8) + n) * 64;
        float2 st = g_stat[((rbase + row) << 8) + n];
#pragma unroll
        for (int j = 0; j < 8; ++j) {
            int k = j * 8 + half * 4;
            float4 v = *(const float4*)&src[k];
            sA[(k + 0) * 128 + row] = (v.x - st.x) * st.y * sg[k + 0] + sb[k + 0];
            sA[(k + 1) * 128 + row] = (v.y - st.x) * st.y * sg[k + 1] + sb[k + 1];
            sA[(k + 2) * 128 + row] = (v.z - st.x) * st.y * sg[k + 2] + sb[k + 2];
            sA[(k + 3) * 128 + row] = (v.w - st.x) * st.y * sg[k + 3] + sb[k + 3];
        }
    }

    const int wr = (wid >> 1) * 32;    // warp rows
    const int wm = (wid & 1) * 64;     // warp f
    wmma::fragment<wmma::accumulator, 16, 16, 8, float> acc[2][4];
#pragma unroll
    for (int i = 0; i < 2; ++i)
#pragma unroll
        for (int j = 0; j < 4; ++j) wmma::fill_fragment(acc[i][j], 0.0f);

    const float* Wn = W1 + (size_t)n * 64 * 384 + fbase;
    const int bk = t >> 4, bf8 = (t & 15) * 8;
    float4 rB0 = *(const float4*)&Wn[bk * 384 + bf8];
    float4 rB1 = *(const float4*)&Wn[bk * 384 + bf8 + 4];

    for (int s = 0; s < 4; ++s) {
        __syncthreads();
        *(float4*)&sB[bk * 128 + bf8]     = rB0;
        *(float4*)&sB[bk * 128 + bf8 + 4] = rB1;
        __syncthreads();
        if (s < 3) {
            rB0 = *(const float4*)&Wn[((s + 1) * 16 + bk) * 384 + bf8];
            rB1 = *(const float4*)&Wn[((s + 1) * 16 + bk) * 384 + bf8 + 4];
        }
#pragma unroll
        for (int kk = 0; kk < 2; ++kk) {
            wmma::fragment<wmma::matrix_a, 16, 16, 8, wmma::precision::tf32, wmma::col_major> fa[2];
#pragma unroll
            for (int fr = 0; fr < 2; ++fr) {
                wmma::load_matrix_sync(fa[fr], &sA[(s * 16 + kk * 8) * 128 + wr + fr * 16], 128);
#pragma unroll
                for (int e = 0; e < fa[fr].num_elements; ++e)
                    fa[fr].x[e] = wmma::__float_to_tf32(fa[fr].x[e]);
            }
#pragma unroll
            for (int fc = 0; fc < 4; ++fc) {
                wmma::fragment<wmma::matrix_b, 16, 16, 8, wmma::precision::tf32, wmma::row_major> fb;
                wmma::load_matrix_sync(fb, &sB[(kk * 8) * 128 + wm + fc * 16], 128);
#pragma unroll
                for (int e = 0; e < fb.num_elements; ++e)
                    fb.x[e] = wmma::__float_to_tf32(fb.x[e]);
                wmma::mma_sync(acc[0][fc], fa[0], fb, acc[0][fc]);
                wmma::mma_sync(acc[1][fc], fa[1], fb, acc[1][fc]);
            }
        }
    }
    __syncthreads();   // all mma done before scratch aliases sA

    // epilogue: per-fragment via scratch, bias + gelu, route u(bf16)/v(fp32)
    float* scr = sA + wid * 320;   // 16x20 per warp
#pragma unroll
    for (int fr = 0; fr < 2; ++fr) {
#pragma unroll
        for (int fc = 0; fc < 4; ++fc) {
            wmma::store_matrix_sync(scr, acc[fr][fc], 20, wmma::mem_row_major);
            __syncwarp();
            int rl = lane >> 1, half = lane & 1;
            int grow = rbase + wr + fr * 16 + rl;
            int f0 = fbase + wm + fc * 16 + half * 8;
            float vals[8];
            float4 b0 = *(const float4*)&b1_[n * 384 + f0];
            float4 b1v = *(const float4*)&b1_[n * 384 + f0 + 4];
            const float bias[8] = {b0.x, b0.y, b0.z, b0.w, b1v.x, b1v.y, b1v.z, b1v.w};
#pragma unroll
            for (int e = 0; e < 8; ++e)
                vals[e] = gelu_exact(scr[rl * 20 + half * 8 + e] + bias[e]);
            if (f0 < 192) {
                *(uint4*)&g_upreb[((size_t)(grow << 8) + n) * 192 + f0] = pack8bf(vals);
            } else {
                int fo = f0 - 192;
                float* dst = &g_v[((size_t)(grow << 8) + n) * 192 + fo];
                *(float4*)&dst[0] = make_float4(vals[0], vals[1], vals[2], vals[3]);
                *(float4*)&dst[4] = make_float4(vals[4], vals[5], vals[6], vals[7]);
            }
            __syncwarp();
        }
    }
}

// ---------------------------------------------------------------------------
// K2b: ln3 over u bf16 (HF=192) + transpose -> g_utb[r][c][n] (bf16)
// ---------------------------------------------------------------------------
__global__ __launch_bounds__(256) void k2b_ln3_t(
    const float* __restrict__ ln3g, const float* __restrict__ ln3b)
{
    __shared__ float s[32][193];
    __shared__ float sm[32], sr[32];
    const int t = threadIdx.x;
    const int r = blockIdx.x;
    const int nb = blockIdx.y * 32;
    const __nv_bfloat16* src = g_upreb + (((size_t)r << 8) + nb) * 192;
#pragma unroll
    for (int it = 0; it < 24; ++it) {
        int lin = t + it * 256;
        s[lin / 192][lin % 192] = __bfloat162float(src[lin]);
    }
    __syncthreads();
    const int warp = t >> 5, lane = t & 31;
#pragma unroll
    for (int j = 0; j < 4; ++j) {
        int row = warp * 4 + j;
        float su = 0.f, s2 = 0.f;
#pragma unroll
        for (int k = 0; k < 6; ++k) { float v = s[row][lane + k * 32]; su += v; s2 += v * v; }
#pragma unroll
        for (int off = 16; off > 0; off >>= 1) {
            su += __shfl_xor_sync(0xffffffffu, su, off);
            s2 += __shfl_xor_sync(0xffffffffu, s2, off);
        }
        if (lane == 0) {
            float m = su * (1.f / 192.f);
            sm[row] = m;
            sr[row] = rsqrtf(s2 * (1.f / 192.f) - m * m + 1e-3f);
        }
    }
    __syncthreads();
    const int n_l = t & 31, c0 = t >> 5;
#pragma unroll
    for (int it = 0; it < 24; ++it) {
        int c = c0 + it * 8;
        float v = (s[n_l][c] - sm[n_l]) * sr[n_l] * ln3g[c] + ln3b[c];
        g_utb[((r * 192 + c) << 8) + nb + n_l] = __float2bfloat16(v);
    }
}

// ---------------------------------------------------------------------------
// K3: spatial gating via wmma bf16, cp.async double-buffered.
// raw gate (no bias) -> g_upreb bf16 [r][c][n].
// grid (8 rtiles, 2 mtiles, 192 c) x 256 thr.
// ---------------------------------------------------------------------------
#define K3_LD 40
__global__ __launch_bounds__(256) void k3_wmma()
{
    __shared__ __align__(16) char smemraw[2 * 128 * K3_LD * 2 * 2];  // sA[2]+sB[2] bf16
    __nv_bfloat16* sA = (__nv_bfloat16*)smemraw;                  // [2][128*K3_LD]
    __nv_bfloat16* sB = sA + 2 * 128 * K3_LD;
    const int t = threadIdx.x;
    const int wid = t >> 5, lane = t & 31;
    const int rbase = blockIdx.x * 128;
    const int mbase = blockIdx.y * 128;
    const int c = blockIdx.z;

    const __nv_bfloat16* abase = g_utb + ((size_t)rbase * 192 + c) * 256;
    const __nv_bfloat16* bbase = g_wsgub + ((size_t)c << 16) + (size_t)mbase * 256;

    const int lr = t >> 1;
    const int lk = (t & 1) * 16;

    wmma::fragment<wmma::accumulator, 16, 16, 16, float> acc[2][4];
#pragma unroll
    for (int i = 0; i < 2; ++i)
#pragma unroll
        for (int j = 0; j < 4; ++j)
            wmma::fill_fragment(acc[i][j], 0.0f);

    const int wr = (wid >> 1) * 32;
    const int wm = (wid & 1) * 64;

    {
        const __nv_bfloat16* as = abase + (size_t)lr * (192 * 256) + lk;
        cp16(&sA[lr * K3_LD + lk], as);
        cp16(&sA[lr * K3_LD + lk + 8], as + 8);
        const __nv_bfloat16* bs = bbase + (size_t)lr * 256 + lk;
        cp16(&sB[lr * K3_LD + lk], bs);
        cp16(&sB[lr * K3_LD + lk + 8], bs + 8);
        CP_COMMIT();
    }

#pragma unroll
    for (int kb = 0; kb < 8; ++kb) {
        const int st = kb & 1;
        if (kb < 7) {
            const int kn = (kb + 1) * 32;
            const __nv_bfloat16* as = abase + (size_t)lr * (192 * 256) + kn + lk;
            cp16(&sA[(st ^ 1) * 128 * K3_LD + lr * K3_LD + lk], as);
            cp16(&sA[(st ^ 1) * 128 * K3_LD + lr * K3_LD + lk + 8], as + 8);
            const __nv_bfloat16* bs = bbase + (size_t)lr * 256 + kn + lk;
            cp16(&sB[(st ^ 1) * 128 * K3_LD + lr * K3_LD + lk], bs);
            cp16(&sB[(st ^ 1) * 128 * K3_LD + lr * K3_LD + lk + 8], bs + 8);
            CP_COMMIT();
            CP_WAIT(1);
        } else {
            CP_WAIT(0);
        }
        __syncthreads();

        const __nv_bfloat16* cA = sA + st * 128 * K3_LD;
        const __nv_bfloat16* cB = sB + st * 128 * K3_LD;
#pragma unroll
        for (int kk = 0; kk < 32; kk += 16) {
            wmma::fragment<wmma::matrix_a, 16, 16, 16, __nv_bfloat16, wmma::row_major> fa[2];
            wmma::load_matrix_sync(fa[0], &cA[(wr     ) * K3_LD + kk], K3_LD);
            wmma::load_matrix_sync(fa[1], &cA[(wr + 16) * K3_LD + kk], K3_LD);
#pragma unroll
            for (int j = 0; j < 4; ++j) {
                wmma::fragment<wmma::matrix_b, 16, 16, 16, __nv_bfloat16, wmma::col_major> fb;
                wmma::load_matrix_sync(fb, &cB[(wm + j * 16) * K3_LD + kk], K3_LD);
                wmma::mma_sync(acc[0][j], fa[0], fb, acc[0][j]);
                wmma::mma_sync(acc[1][j], fa[1], fb, acc[1][j]);
            }
        }
        __syncthreads();
    }

    // epilogue: raw gate -> bf16 via per-warp scratch (aliases smemraw)
    float* scr = (float*)smemraw + wid * 320;
#pragma unroll
    for (int fr = 0; fr < 2; ++fr) {
#pragma unroll
        for (int fc = 0; fc < 4; ++fc) {
            wmma::store_matrix_sync(scr, acc[fr][fc], 20, wmma::mem_row_major);
            __syncwarp();
            int rl = lane >> 1, half = lane & 1;
            int grow = rbase + wr + fr * 16 + rl;
            int m0 = mbase + wm + fc * 16 + half * 8;
            float vals[8];
#pragma unroll
            for (int e = 0; e < 8; ++e) vals[e] = scr[rl * 20 + half * 8 + e];
            *(uint4*)&g_upreb[((size_t)grow * 192 + c) * 256 + m0] = pack8bf(vals);
            __syncwarp();
        }
    }
}

// ---------------------------------------------------------------------------
// K3b: uv[r][n][c] = (gate_bf16[r][c][n] + bsgu[c][n]) * v[r][n][c]
// ---------------------------------------------------------------------------
__global__ __launch_bounds__(256) void k3b_gate_mul(const float* __restrict__ bsgu)
{
    __shared__ float s[32][33];
    const int t = threadIdx.x;
    const int r = blockIdx.x;
    const int nb = blockIdx.y * 32;
    const int cb = blockIdx.z * 32;
    {
        int n_l = t & 31, c0 = t >> 5;
#pragma unroll
        for (int it = 0; it < 4; ++it) {
            int cc = c0 + it * 8;
            s[cc][n_l] = __bfloat162float(
                             g_upreb[((size_t)(r * 192 + cb + cc) << 8) + nb + n_l])
                       + bsgu[((cb + cc) << 8) + nb + n_l];
        }
    }
    __syncthreads();
    {
        int c_l = t & 31, n0 = t >> 5;
#pragma unroll
        for (int it = 0; it < 4; ++it) {
            int nn = n0 + it * 8;
            int idx = (((r << 8) + nb + nn) * 192) + cb + c_l;
            g_ut[idx] = s[c_l][nn] * g_v[idx];
        }
    }
}

// ---------------------------------------------------------------------------
// K4: tf32 wmma: z = uv @ W2[n] + b2[n] + bufin.
// grid (8 rtiles, 256 n) x 256 thr. Block 128 x 64, K=192 staged BK=16.
// ---------------------------------------------------------------------------
__global__ __launch_bounds__(256) void k4_gmlp_out(
    const float* __restrict__ W2, const float* __restrict__ b2_)
{
    __shared__ float smemf[16 * 128 + 16 * 64];   // sA^T | sB ; reused as scratch
    float* sA = smemf;            // [k][row] 16x128
    float* sB = smemf + 16 * 128; // [k][f]   16x64
    const int t = threadIdx.x;
    const int wid = t >> 5, lane = t & 31;
    const int rbase = blockIdx.x * 128;
    const int n = blockIdx.y;

    const int wr = (wid >> 1) * 32;
    const int wm = (wid & 1) * 32;
    wmma::fragment<wmma::accumulator, 16, 16, 8, float> acc[2][2];
#pragma unroll
    for (int i = 0; i < 2; ++i)
#pragma unroll
        for (int j = 0; j < 2; ++j) wmma::fill_fragment(acc[i][j], 0.0f);

    const int arow = t >> 1, ahalf = t & 1;
    const float* asrc = g_ut + ((size_t)((rbase + arow) << 8) + n) * 192;
    const int bkr = t >> 4, bf4 = (t & 15) * 4;
    const float* bsrc = W2 + (size_t)n * 192 * 64;

    float4 rA0 = *(const float4*)&asrc[ahalf * 8];
    float4 rA1 = *(const float4*)&asrc[ahalf * 8 + 4];
    float4 rB  = *(const float4*)&bsrc[bkr * 64 + bf4];

    for (int s = 0; s < 12; ++s) {
        __syncthreads();
        {
            int k0 = ahalf * 8;
            sA[(k0 + 0) * 128 + arow] = rA0.x; sA[(k0 + 1) * 128 + arow] = rA0.y;
            sA[(k0 + 2) * 128 + arow] = rA0.z; sA[(k0 + 3) * 128 + arow] = rA0.w;
            sA[(k0 + 4) * 128 + arow] = rA1.x; sA[(k0 + 5) * 128 + arow] = rA1.y;
            sA[(k0 + 6) * 128 + arow] = rA1.z; sA[(k0 + 7) * 128 + arow] = rA1.w;
            *(float4*)&sB[bkr * 64 + bf4] = rB;
        }
        __syncthreads();
        if (s < 11) {
            rA0 = *(const float4*)&asrc[(s + 1) * 16 + ahalf * 8];
            rA1 = *(const float4*)&asrc[(s + 1) * 16 + ahalf * 8 + 4];
            rB  = *(const float4*)&bsrc[((s + 1) * 16 + bkr) * 64 + bf4];
        }
#pragma unroll
        for (int kk = 0; kk < 2; ++kk) {
            wmma::fragment<wmma::matrix_a, 16, 16, 8, wmma::precision::tf32, wmma::col_major> fa[2];
#pragma unroll
            for (int fr = 0; fr < 2; ++fr) {
                wmma::load_matrix_sync(fa[fr], &sA[(kk * 8) * 128 + wr + fr * 16], 128);
#pragma unroll
                for (int e = 0; e < fa[fr].num_elements; ++e)
                    fa[fr].x[e] = wmma::__float_to_tf32(fa[fr].x[e]);
            }
#pragma unroll
            for (int fc = 0; fc < 2; ++fc) {
                wmma::fragment<wmma::matrix_b, 16, 16, 8, wmma::precision::tf32, wmma::row_major> fb;
                wmma::load_matrix_sync(fb, &sB[(kk * 8) * 64 + wm + fc * 16], 64);
#pragma unroll
                for (int e = 0; e < fb.num_elements; ++e)
                    fb.x[e] = wmma::__float_to_tf32(fb.x[e]);
                wmma::mma_sync(acc[0][fc], fa[0], fb, acc[0][fc]);
                wmma::mma_sync(acc[1][fc], fa[1], fb, acc[1][fc]);
            }
        }
    }
    __syncthreads();

    float* scr = smemf + wid * 320;
#pragma unroll
    for (int fr = 0; fr < 2; ++fr) {
#pragma unroll
        for (int fc = 0; fc < 2; ++fc) {
            wmma::store_matrix_sync(scr, acc[fr][fc], 20, wmma::mem_row_major);
            __syncwarp();
            int rl = lane >> 1, half = lane & 1;
            int grow = rbase + wr + fr * 16 + rl;
            int f0 = wm + fc * 16 + half * 8;
            int idx = (((grow << 8) + n) << 6) + f0;
            float4 b0 = *(const float4*)&b2_[(n << 6) + f0];
            float4 b1v = *(const float4*)&b2_[(n << 6) + f0 + 4];
            float4 x0 = *(const float4*)&g_bufin[idx];
            float4 x1 = *(const float4*)&g_bufin[idx + 4];
            *(float4*)&g_z[idx] = make_float4(
                scr[rl * 20 + half * 8 + 0] + b0.x + x0.x,
                scr[rl * 20 + half * 8 + 1] + b0.y + x0.y,
                scr[rl * 20 + half * 8 + 2] + b0.z + x0.z,
                scr[rl * 20 + half * 8 + 3] + b0.w + x0.w);
            *(float4*)&g_z[idx + 4] = make_float4(
                scr[rl * 20 + half * 8 + 4] + b1v.x + x1.x,
                scr[rl * 20 + half * 8 + 5] + b1v.y + x1.y,
                scr[rl * 20 + half * 8 + 6] + b1v.z + x1.z,
                scr[rl * 20 + half * 8 + 7] + b1v.w + x1.w);
            __syncwarp();
        }
    }
}

// ---------------------------------------------------------------------------
// K5: recon + concat + outer residual; glob out
// ---------------------------------------------------------------------------
__global__ __launch_bounds__(256) void k5_assemble(
    const float* __restrict__ x, float* __restrict__ out,
    float* __restrict__ gout, int write_glob)
{
    const int t = threadIdx.x;
    const int pix = blockIdx.x * 16 + (t >> 4);
    const int c = (t & 15) * 4;
    const int b = pix >> 16, h = (pix >> 8) & 255, w = pix & 255;
    const int gb  = ((h >> 4) << 4) | (w >> 4);
    const int nb2 = ((h & 15) << 4) | (w & 15);
    const int rl = (b << 8) + nb2;
    const int rg = 512 + (b << 8) + gb;
    float4 zl = *(const float4*)&g_z[(((rl << 8) + gb)  << 6) + c];
    float4 zg = *(const float4*)&g_z[(((rg << 8) + nb2) << 6) + c];
    float4 xa = *(const float4*)&x[pix * 128 + c];
    float4 xb = *(const float4*)&x[pix * 128 + 64 + c];
    *(float4*)&out[pix * 128 + c] =
        make_float4(zl.x + xa.x, zl.y + xa.y, zl.z + xa.z, zl.w + xa.w);
    *(float4*)&out[pix * 128 + 64 + c] =
        make_float4(zg.x + xb.x, zg.y + xb.y, zg.z + xb.z, zg.w + xb.w);
    if (write_glob)
        *(float4*)&gout[pix * 64 + c] = zg;
}

// ---------------------------------------------------------------------------
extern "C" void kernel_launch(void* const* d_in, const int* in_sizes, int n_in,
                              void* d_out, int out_size)
{
    const float* x    = (const float*)d_in[0];
    const float* ln1g = (const float*)d_in[1];
    const float* ln1b = (const float*)d_in[2];
    const float* Wp   = (const float*)d_in[3];
    const float* bp   = (const float*)d_in[4];
    const float* ln2g = (const float*)d_in[5];
    const float* ln2b = (const float*)d_in[6];
    const float* W1   = (const float*)d_in[7];
    const float* b1   = (const float*)d_in[8];
    const float* ln3g = (const float*)d_in[9];
    const float* ln3b = (const float*)d_in[10];
    const float* Wsgu = (const float*)d_in[11];
    const float* bsgu = (const float*)d_in[12];
    const float* W2   = (const float*)d_in[13];
    const float* b2   = (const float*)d_in[14];

    float* out = (float*)d_out;
    const int OUT_MAIN = 2 * 256 * 256 * 128;
    const int OUT_GLOB = 2 * 256 * 256 * 64;
    int write_glob = (out_size >= OUT_MAIN + OUT_GLOB) ? 1 : 0;
    float* gout = out + OUT_MAIN;

    k0_wsgu_t    <<<dim3(8, 8, 192), dim3(32, 8)>>>(Wsgu);
    k1_ln_proj   <<<8192, 256>>>(x, ln1g, ln1b, Wp, bp);
    k2_gmlp_in   <<<dim3(3, 8, 256), 256>>>(W1, b1, ln2g, ln2b);
    k2b_ln3_t    <<<dim3(1024, 8, 1), 256>>>(ln3g, ln3b);
    k3_wmma      <<<dim3(8, 2, 192), 256>>>();
    k3b_gate_mul <<<dim3(1024, 8, 6), 256>>>(bsgu);
    k4_gmlp_out  <<<dim3(8, 256, 1), 256>>>(W2, b2);
    k5_assemble  <<<8192, 256>>>(x, out, gout, write_glob);
}

// round 11
// speedup vs baseline: 1.5585x; 1.0200x over previous
#include <cuda_runtime.h>
#include <cuda_bf16.h>
#include <mma.h>
#include <math.h>
#include <cstdint>

using namespace nvcuda;

// ---------------------------------------------------------------------------
// Shapes: B=2, H=W=256, C=128, S=16 -> G=256, N=256, CI=64, F1=384, HF=192
// R = 2 branches * B * G = 1024
// ---------------------------------------------------------------------------
#define R_TOT   1024
#define NPATCH  256
#define CI_DIM  64
#define HF_DIM  192

__device__ float  g_bufin[R_TOT * NPATCH * CI_DIM];   // blocked gmlp input (fp32)
__device__ float2 g_stat [R_TOT * NPATCH];            // ln2 (mean, rstd) per (r,n)
__device__ float  g_v    [R_TOT * NPATCH * HF_DIM];   // v (fp32)
__device__ float  g_ut   [R_TOT * HF_DIM * NPATCH];   // uv [R][N][HF] (fp32)
__device__ __align__(16) __nv_bfloat16 g_upreb [R_TOT * NPATCH * HF_DIM]; // u bf16; later raw gate [r][c][n]
__device__ __align__(16) __nv_bfloat16 g_utb   [R_TOT * HF_DIM * NPATCH]; // ln3'd u^T bf16
__device__ __align__(16) __nv_bfloat16 g_wsgub [HF_DIM * NPATCH * NPATCH];// Wsgu^T bf16 [c][m][k]

__device__ __forceinline__ float gelu_exact(float x) {
    return 0.5f * x * (1.0f + erff(x * 0.7071067811865476f));
}

// ---- cp.async helpers ----
__device__ __forceinline__ void cp16(void* smem_dst, const void* gsrc) {
    uint32_t d = (uint32_t)__cvta_generic_to_shared(smem_dst);
    asm volatile("cp.async.cg.shared.global [%0], [%1], 16;"
                 :: "r"(d), "l"(gsrc) : "memory");
}
#define CP_COMMIT()  asm volatile("cp.async.commit_group;" ::: "memory")
#define CP_WAIT(n)   asm volatile("cp.async.wait_group %0;" :: "n"(n) : "memory")

__device__ __forceinline__ uint4 pack8bf(const float* v) {
    union { __nv_bfloat16 h[8]; uint4 u; } r;
#pragma unroll
    for (int i = 0; i < 8; ++i) r.h[i] = __float2bfloat16(v[i]);
    return r.u;
}

// ---------------------------------------------------------------------------
// K0: Wsgu [c][n][m] fp32 -> g_wsgub [c][m][n] bf16
// ---------------------------------------------------------------------------
__global__ __launch_bounds__(256) void k0_wsgu_t(const float* __restrict__ Wsgu)
{
    __shared__ float tile[32][33];
    const int c  = blockIdx.z;
    const int mb = blockIdx.x * 32;
    const int nb = blockIdx.y * 32;
    const int tx = threadIdx.x, ty = threadIdx.y;
#pragma unroll
    for (int j = 0; j < 4; ++j) {
        int n = ty + j * 8;
        tile[n][tx] = Wsgu[(((size_t)c << 8) + nb + n) * 256 + mb + tx];
    }
    __syncthreads();
#pragma unroll
    for (int j = 0; j < 4; ++j) {
        int m = ty + j * 8;
        g_wsgub[(((size_t)c << 8) + mb + m) * 256 + nb + tx] =
            __float2bfloat16(tile[tx][m]);
    }
}

// ---------------------------------------------------------------------------
// K1: ln1 + Dense(W_proj) + GELU (fp32 FFMA), scatter blocked + ln2 stats
// ---------------------------------------------------------------------------
__global__ __launch_bounds__(256) void k1_ln_proj(
    const float* __restrict__ x, const float* __restrict__ ln1g,
    const float* __restrict__ ln1b, const float* __restrict__ Wp,
    const float* __restrict__ bp)
{
    __shared__ float sR[16][132];
    __shared__ float sg[128], sb[128];
    __shared__ float smean[16], srs[16];
    const int t = threadIdx.x;
    const int pbase = blockIdx.x * 16;

    if (t < 128) { sg[t] = ln1g[t]; sb[t] = ln1b[t]; }
    const float* xblk = x + (size_t)pbase * 128;
#pragma unroll
    for (int it = 0; it < 8; ++it) {
        int lin = t + it * 256;
        sR[lin >> 7][lin & 127] = xblk[lin];
    }
    __syncthreads();

    const int warp = t >> 5, lane = t & 31;
#pragma unroll
    for (int rr = 0; rr < 2; ++rr) {
        int p = warp * 2 + rr;
        float s = 0.f, s2 = 0.f;
#pragma unroll
        for (int j = 0; j < 4; ++j) {
            float v = sR[p][lane + j * 32];
            s += v; s2 += v * v;
        }
#pragma unroll
        for (int off = 16; off > 0; off >>= 1) {
            s  += __shfl_xor_sync(0xffffffffu, s,  off);
            s2 += __shfl_xor_sync(0xffffffffu, s2, off);
        }
        if (lane == 0) {
            float m = s * (1.f / 128.f);
            smean[p] = m;
            srs[p]   = rsqrtf(s2 * (1.f / 128.f) - m * m + 1e-3f);
        }
    }
    __syncthreads();
#pragma unroll
    for (int it = 0; it < 8; ++it) {
        int lin = t + it * 256;
        int p = lin >> 7, c = lin & 127;
        sR[p][c] = (sR[p][c] - smean[p]) * srs[p] * sg[c] + sb[c];
    }
    __syncthreads();

    const int f2 = t & 63;
    const int pg = t >> 6;
    float acc0[4], acc1[4];
#pragma unroll
    for (int i = 0; i < 4; ++i) { acc0[i] = 0.f; acc1[i] = 0.f; }
    const float2* Wp2 = (const float2*)Wp;
    for (int cc = 0; cc < 128; cc += 4) {
        float4 a0 = *(const float4*)&sR[pg * 4 + 0][cc];
        float4 a1 = *(const float4*)&sR[pg * 4 + 1][cc];
        float4 a2 = *(const float4*)&sR[pg * 4 + 2][cc];
        float4 a3 = *(const float4*)&sR[pg * 4 + 3][cc];
        float2 w0 = Wp2[(cc + 0) * 64 + f2];
        float2 w1 = Wp2[(cc + 1) * 64 + f2];
        float2 w2 = Wp2[(cc + 2) * 64 + f2];
        float2 w3 = Wp2[(cc + 3) * 64 + f2];
        float4 av[4] = {a0, a1, a2, a3};
#pragma unroll
        for (int i = 0; i < 4; ++i) {
            acc0[i] = fmaf(av[i].x, w0.x, acc0[i]); acc1[i] = fmaf(av[i].x, w0.y, acc1[i]);
            acc0[i] = fmaf(av[i].y, w1.x, acc0[i]); acc1[i] = fmaf(av[i].y, w1.y, acc1[i]);
            acc0[i] = fmaf(av[i].z, w2.x, acc0[i]); acc1[i] = fmaf(av[i].z, w2.y, acc1[i]);
            acc0[i] = fmaf(av[i].w, w3.x, acc0[i]); acc1[i] = fmaf(av[i].w, w3.y, acc1[i]);
        }
    }
    const float2 wb = ((const float2*)bp)[f2];
    const int branch = (f2 >= 32) ? 1 : 0;
    const int cloc = 2 * (f2 & 31);

    float vv0[4], vv1[4];
    int ridx[4], nidx[4];
#pragma unroll
    for (int i = 0; i < 4; ++i) {
        int p = pbase + pg * 4 + i;
        int b = p >> 16, h = (p >> 8) & 255, w = p & 255;
        int g  = ((h >> 4) << 4) | (w >> 4);
        int nn = ((h & 15) << 4) | (w & 15);
        vv0[i] = gelu_exact(acc0[i] + wb.x);
        vv1[i] = gelu_exact(acc1[i] + wb.y);
        int r = branch * 512 + (b << 8) + g;
        ridx[i] = r; nidx[i] = nn;
        *(float2*)&g_bufin[(((r << 8) + nn) << 6) + cloc] = make_float2(vv0[i], vv1[i]);
    }
#pragma unroll
    for (int i = 0; i < 4; ++i) {
        float s  = vv0[i] + vv1[i];
        float s2 = vv0[i] * vv0[i] + vv1[i] * vv1[i];
#pragma unroll
        for (int off = 16; off > 0; off >>= 1) {
            s  += __shfl_xor_sync(0xffffffffu, s,  off);
            s2 += __shfl_xor_sync(0xffffffffu, s2, off);
        }
        if (lane == 0) {
            float m  = s * (1.f / 64.f);
            float rs = rsqrtf(s2 * (1.f / 64.f) - m * m + 1e-3f);
            g_stat[(ridx[i] << 8) + nidx[i]] = make_float2(m, rs);
        }
    }
}

// ---------------------------------------------------------------------------
// K2: tf32 wmma (RN rounding): y = gelu(ln2(bufin) @ W1[n] + b1[n]);
// u -> bf16, v -> fp32. grid (3 ftiles, 8 rtiles, 256 n) x 256 thr.
// ---------------------------------------------------------------------------
__global__ __launch_bounds__(256) void k2_gmlp_in(
    const float* __restrict__ W1, const float* __restrict__ b1_,
    const float* __restrict__ ln2g, const float* __restrict__ ln2b)
{
    __shared__ float sA[64 * 128];
    __shared__ float sB[16 * 128];
    __shared__ float sg[64], sb[64];
    const int t = threadIdx.x;
    const int wid = t >> 5, lane = t & 31;
    const int fbase = blockIdx.x * 128;
    const int rbase = blockIdx.y * 128;
    const int n = blockIdx.z;

    if (t < 64) { sg[t] = ln2g[t]; sb[t] = ln2b[t]; }
    __syncthreads();

    {
        const int row = t >> 1, half = t & 1;
        const float* src = g_bufin + ((size_t)((rbase + row) << 8) + n) * 64;
        float2 st = g_stat[((rbase + row) << 8) + n];
#pragma unroll
        for (int j = 0; j < 8; ++j) {
            int k = j * 8 + half * 4;
            float4 v = *(const float4*)&src[k];
            sA[(k + 0) * 128 + row] = (v.x - st.x) * st.y * sg[k + 0] + sb[k + 0];
            sA[(k + 1) * 128 + row] = (v.y - st.x) * st.y * sg[k + 1] + sb[k + 1];
            sA[(k + 2) * 128 + row] = (v.z - st.x) * st.y * sg[k + 2] + sb[k + 2];
            sA[(k + 3) * 128 + row] = (v.w - st.x) * st.y * sg[k + 3] + sb[k + 3];
        }
    }

    const int wr = (wid >> 1) * 32;
    const int wm = (wid & 1) * 64;
    wmma::fragment<wmma::accumulator, 16, 16, 8, float> acc[2][4];
#pragma unroll
    for (int i = 0; i < 2; ++i)
#pragma unroll
        for (int j = 0; j < 4; ++j) wmma::fill_fragment(acc[i][j], 0.0f);

    const float* Wn = W1 + (size_t)n * 64 * 384 + fbase;
    const int bk = t >> 4, bf8 = (t & 15) * 8;
    float4 rB0 = *(const float4*)&Wn[bk * 384 + bf8];
    float4 rB1 = *(const float4*)&Wn[bk * 384 + bf8 + 4];

    for (int s = 0; s < 4; ++s) {
        __syncthreads();
        *(float4*)&sB[bk * 128 + bf8]     = rB0;
        *(float4*)&sB[bk * 128 + bf8 + 4] = rB1;
        __syncthreads();
        if (s < 3) {
            rB0 = *(const float4*)&Wn[((s + 1) * 16 + bk) * 384 + bf8];
            rB1 = *(const float4*)&Wn[((s + 1) * 16 + bk) * 384 + bf8 + 4];
        }
#pragma unroll
        for (int kk = 0; kk < 2; ++kk) {
            wmma::fragment<wmma::matrix_a, 16, 16, 8, wmma::precision::tf32, wmma::col_major> fa[2];
#pragma unroll
            for (int fr = 0; fr < 2; ++fr) {
                wmma::load_matrix_sync(fa[fr], &sA[(s * 16 + kk * 8) * 128 + wr + fr * 16], 128);
#pragma unroll
                for (int e = 0; e < fa[fr].num_elements; ++e)
                    fa[fr].x[e] = wmma::__float_to_tf32(fa[fr].x[e]);
            }
#pragma unroll
            for (int fc = 0; fc < 4; ++fc) {
                wmma::fragment<wmma::matrix_b, 16, 16, 8, wmma::precision::tf32, wmma::row_major> fb;
                wmma::load_matrix_sync(fb, &sB[(kk * 8) * 128 + wm + fc * 16], 128);
#pragma unroll
                for (int e = 0; e < fb.num_elements; ++e)
                    fb.x[e] = wmma::__float_to_tf32(fb.x[e]);
                wmma::mma_sync(acc[0][fc], fa[0], fb, acc[0][fc]);
                wmma::mma_sync(acc[1][fc], fa[1], fb, acc[1][fc]);
            }
        }
    }
    __syncthreads();

    float* scr = sA + wid * 320;
#pragma unroll
    for (int fr = 0; fr < 2; ++fr) {
#pragma unroll
        for (int fc = 0; fc < 4; ++fc) {
            wmma::store_matrix_sync(scr, acc[fr][fc], 20, wmma::mem_row_major);
            __syncwarp();
            int rl = lane >> 1, half = lane & 1;
            int grow = rbase + wr + fr * 16 + rl;
            int f0 = fbase + wm + fc * 16 + half * 8;
            float vals[8];
            float4 b0 = *(const float4*)&b1_[n * 384 + f0];
            float4 b1v = *(const float4*)&b1_[n * 384 + f0 + 4];
            const float bias[8] = {b0.x, b0.y, b0.z, b0.w, b1v.x, b1v.y, b1v.z, b1v.w};
#pragma unroll
            for (int e = 0; e < 8; ++e)
                vals[e] = gelu_exact(scr[rl * 20 + half * 8 + e] + bias[e]);
            if (f0 < 192) {
                *(uint4*)&g_upreb[((size_t)(grow << 8) + n) * 192 + f0] = pack8bf(vals);
            } else {
                int fo = f0 - 192;
                float* dst = &g_v[((size_t)(grow << 8) + n) * 192 + fo];
                *(float4*)&dst[0] = make_float4(vals[0], vals[1], vals[2], vals[3]);
                *(float4*)&dst[4] = make_float4(vals[4], vals[5], vals[6], vals[7]);
            }
            __syncwarp();
        }
    }
}

// ---------------------------------------------------------------------------
// K2b: ln3 over u bf16 (HF=192) + transpose -> g_utb[r][c][n] (bf16)
// ---------------------------------------------------------------------------
__global__ __launch_bounds__(256) void k2b_ln3_t(
    const float* __restrict__ ln3g, const float* __restrict__ ln3b)
{
    __shared__ float s[32][193];
    __shared__ float sm[32], sr[32];
    const int t = threadIdx.x;
    const int r = blockIdx.x;
    const int nb = blockIdx.y * 32;
    const __nv_bfloat16* src = g_upreb + (((size_t)r << 8) + nb) * 192;
#pragma unroll
    for (int it = 0; it < 24; ++it) {
        int lin = t + it * 256;
        s[lin / 192][lin % 192] = __bfloat162float(src[lin]);
    }
    __syncthreads();
    const int warp = t >> 5, lane = t & 31;
#pragma unroll
    for (int j = 0; j < 4; ++j) {
        int row = warp * 4 + j;
        float su = 0.f, s2 = 0.f;
#pragma unroll
        for (int k = 0; k < 6; ++k) { float v = s[row][lane + k * 32]; su += v; s2 += v * v; }
#pragma unroll
        for (int off = 16; off > 0; off >>= 1) {
            su += __shfl_xor_sync(0xffffffffu, su, off);
            s2 += __shfl_xor_sync(0xffffffffu, s2, off);
        }
        if (lane == 0) {
            float m = su * (1.f / 192.f);
            sm[row] = m;
            sr[row] = rsqrtf(s2 * (1.f / 192.f) - m * m + 1e-3f);
        }
    }
    __syncthreads();
    const int n_l = t & 31, c0 = t >> 5;
#pragma unroll
    for (int it = 0; it < 24; ++it) {
        int c = c0 + it * 8;
        float v = (s[n_l][c] - sm[n_l]) * sr[n_l] * ln3g[c] + ln3b[c];
        g_utb[((r * 192 + c) << 8) + nb + n_l] = __float2bfloat16(v);
    }
}

// ---------------------------------------------------------------------------
// K3: spatial gating via wmma bf16, cp.async double-buffered.
// raw gate (no bias) -> g_upreb bf16 [r][c][n].
// grid (8 rtiles, 2 mtiles, 192 c) x 256 thr.
// ---------------------------------------------------------------------------
#define K3_LD 40
__global__ __launch_bounds__(256) void k3_wmma()
{
    __shared__ __align__(16) char smemraw[2 * 128 * K3_LD * 2 * 2];
    __nv_bfloat16* sA = (__nv_bfloat16*)smemraw;
    __nv_bfloat16* sB = sA + 2 * 128 * K3_LD;
    const int t = threadIdx.x;
    const int wid = t >> 5, lane = t & 31;
    const int rbase = blockIdx.x * 128;
    const int mbase = blockIdx.y * 128;
    const int c = blockIdx.z;

    const __nv_bfloat16* abase = g_utb + ((size_t)rbase * 192 + c) * 256;
    const __nv_bfloat16* bbase = g_wsgub + ((size_t)c << 16) + (size_t)mbase * 256;

    const int lr = t >> 1;
    const int lk = (t & 1) * 16;

    wmma::fragment<wmma::accumulator, 16, 16, 16, float> acc[2][4];
#pragma unroll
    for (int i = 0; i < 2; ++i)
#pragma unroll
        for (int j = 0; j < 4; ++j)
            wmma::fill_fragment(acc[i][j], 0.0f);

    const int wr = (wid >> 1) * 32;
    const int wm = (wid & 1) * 64;

    {
        const __nv_bfloat16* as = abase + (size_t)lr * (192 * 256) + lk;
        cp16(&sA[lr * K3_LD + lk], as);
        cp16(&sA[lr * K3_LD + lk + 8], as + 8);
        const __nv_bfloat16* bs = bbase + (size_t)lr * 256 + lk;
        cp16(&sB[lr * K3_LD + lk], bs);
        cp16(&sB[lr * K3_LD + lk + 8], bs + 8);
        CP_COMMIT();
    }

#pragma unroll
    for (int kb = 0; kb < 8; ++kb) {
        const int st = kb & 1;
        if (kb < 7) {
            const int kn = (kb + 1) * 32;
            const __nv_bfloat16* as = abase + (size_t)lr * (192 * 256) + kn + lk;
            cp16(&sA[(st ^ 1) * 128 * K3_LD + lr * K3_LD + lk], as);
            cp16(&sA[(st ^ 1) * 128 * K3_LD + lr * K3_LD + lk + 8], as + 8);
            const __nv_bfloat16* bs = bbase + (size_t)lr * 256 + kn + lk;
            cp16(&sB[(st ^ 1) * 128 * K3_LD + lr * K3_LD + lk], bs);
            cp16(&sB[(st ^ 1) * 128 * K3_LD + lr * K3_LD + lk + 8], bs + 8);
            CP_COMMIT();
            CP_WAIT(1);
        } else {
            CP_WAIT(0);
        }
        __syncthreads();

        const __nv_bfloat16* cA = sA + st * 128 * K3_LD;
        const __nv_bfloat16* cB = sB + st * 128 * K3_LD;
#pragma unroll
        for (int kk = 0; kk < 32; kk += 16) {
            wmma::fragment<wmma::matrix_a, 16, 16, 16, __nv_bfloat16, wmma::row_major> fa[2];
            wmma::load_matrix_sync(fa[0], &cA[(wr     ) * K3_LD + kk], K3_LD);
            wmma::load_matrix_sync(fa[1], &cA[(wr + 16) * K3_LD + kk], K3_LD);
#pragma unroll
            for (int j = 0; j < 4; ++j) {
                wmma::fragment<wmma::matrix_b, 16, 16, 16, __nv_bfloat16, wmma::col_major> fb;
                wmma::load_matrix_sync(fb, &cB[(wm + j * 16) * K3_LD + kk], K3_LD);
                wmma::mma_sync(acc[0][j], fa[0], fb, acc[0][j]);
                wmma::mma_sync(acc[1][j], fa[1], fb, acc[1][j]);
            }
        }
        __syncthreads();
    }

    float* scr = (float*)smemraw + wid * 320;
#pragma unroll
    for (int fr = 0; fr < 2; ++fr) {
#pragma unroll
        for (int fc = 0; fc < 4; ++fc) {
            wmma::store_matrix_sync(scr, acc[fr][fc], 20, wmma::mem_row_major);
            __syncwarp();
            int rl = lane >> 1, half = lane & 1;
            int grow = rbase + wr + fr * 16 + rl;
            int m0 = mbase + wm + fc * 16 + half * 8;
            float vals[8];
#pragma unroll
            for (int e = 0; e < 8; ++e) vals[e] = scr[rl * 20 + half * 8 + e];
            *(uint4*)&g_upreb[((size_t)grow * 192 + c) * 256 + m0] = pack8bf(vals);
            __syncwarp();
        }
    }
}

// ---------------------------------------------------------------------------
// K3b: uv[r][n][c] = (gate_bf16[r][c][n] + bsgu[c][n]) * v[r][n][c]
// ---------------------------------------------------------------------------
__global__ __launch_bounds__(256) void k3b_gate_mul(const float* __restrict__ bsgu)
{
    __shared__ float s[32][33];
    const int t = threadIdx.x;
    const int r = blockIdx.x;
    const int nb = blockIdx.y * 32;
    const int cb = blockIdx.z * 32;
    {
        int n_l = t & 31, c0 = t >> 5;
#pragma unroll
        for (int it = 0; it < 4; ++it) {
            int cc = c0 + it * 8;
            s[cc][n_l] = __bfloat162float(
                             g_upreb[((size_t)(r * 192 + cb + cc) << 8) + nb + n_l])
                       + bsgu[((cb + cc) << 8) + nb + n_l];
        }
    }
    __syncthreads();
    {
        int c_l = t & 31, n0 = t >> 5;
#pragma unroll
        for (int it = 0; it < 4; ++it) {
            int nn = n0 + it * 8;
            int idx = (((r << 8) + nb + nn) * 192) + cb + c_l;
            g_ut[idx] = s[c_l][nn] * g_v[idx];
        }
    }
}

// ---------------------------------------------------------------------------
// K4: tf32 wmma (RN rounding): z = uv @ W2[n] + b2[n] + bufin, with fused
// recon/concat/residual epilogue (K5 eliminated, g_z deleted).
// grid (8 rtiles, 256 n) x 256 thr.
// ---------------------------------------------------------------------------
__global__ __launch_bounds__(256) void k4_gmlp_out(
    const float* __restrict__ W2, const float* __restrict__ b2_,
    const float* __restrict__ x, float* __restrict__ out,
    float* __restrict__ gout, int write_glob)
{
    __shared__ float smemf[16 * 128 + 16 * 64];
    float* sA = smemf;
    float* sB = smemf + 16 * 128;
    const int t = threadIdx.x;
    const int wid = t >> 5, lane = t & 31;
    const int rbase = blockIdx.x * 128;
    const int n = blockIdx.y;

    const int wr = (wid >> 1) * 32;
    const int wm = (wid & 1) * 32;
    wmma::fragment<wmma::accumulator, 16, 16, 8, float> acc[2][2];
#pragma unroll
    for (int i = 0; i < 2; ++i)
#pragma unroll
        for (int j = 0; j < 2; ++j) wmma::fill_fragment(acc[i][j], 0.0f);

    const int arow = t >> 1, ahalf = t & 1;
    const float* asrc = g_ut + ((size_t)((rbase + arow) << 8) + n) * 192;
    const int bkr = t >> 4, bf4 = (t & 15) * 4;
    const float* bsrc = W2 + (size_t)n * 192 * 64;

    float4 rA0 = *(const float4*)&asrc[ahalf * 8];
    float4 rA1 = *(const float4*)&asrc[ahalf * 8 + 4];
    float4 rB  = *(const float4*)&bsrc[bkr * 64 + bf4];

    for (int s = 0; s < 12; ++s) {
        __syncthreads();
        {
            int k0 = ahalf * 8;
            sA[(k0 + 0) * 128 + arow] = rA0.x; sA[(k0 + 1) * 128 + arow] = rA0.y;
            sA[(k0 + 2) * 128 + arow] = rA0.z; sA[(k0 + 3) * 128 + arow] = rA0.w;
            sA[(k0 + 4) * 128 + arow] = rA1.x; sA[(k0 + 5) * 128 + arow] = rA1.y;
            sA[(k0 + 6) * 128 + arow] = rA1.z; sA[(k0 + 7) * 128 + arow] = rA1.w;
            *(float4*)&sB[bkr * 64 + bf4] = rB;
        }
        __syncthreads();
        if (s < 11) {
            rA0 = *(const float4*)&asrc[(s + 1) * 16 + ahalf * 8];
            rA1 = *(const float4*)&asrc[(s + 1) * 16 + ahalf * 8 + 4];
            rB  = *(const float4*)&bsrc[((s + 1) * 16 + bkr) * 64 + bf4];
        }
#pragma unroll
        for (int kk = 0; kk < 2; ++kk) {
            wmma::fragment<wmma::matrix_a, 16, 16, 8, wmma::precision::tf32, wmma::col_major> fa[2];
#pragma unroll
            for (int fr = 0; fr < 2; ++fr) {
                wmma::load_matrix_sync(fa[fr], &sA[(kk * 8) * 128 + wr + fr * 16], 128);
#pragma unroll
                for (int e = 0; e < fa[fr].num_elements; ++e)
                    fa[fr].x[e] = wmma::__float_to_tf32(fa[fr].x[e]);
            }
#pragma unroll
            for (int fc = 0; fc < 2; ++fc) {
                wmma::fragment<wmma::matrix_b, 16, 16, 8, wmma::precision::tf32, wmma::row_major> fb;
                wmma::load_matrix_sync(fb, &sB[(kk * 8) * 64 + wm + fc * 16], 64);
#pragma unroll
                for (int e = 0; e < fb.num_elements; ++e)
                    fb.x[e] = wmma::__float_to_tf32(fb.x[e]);
                wmma::mma_sync(acc[0][fc], fa[0], fb, acc[0][fc]);
                wmma::mma_sync(acc[1][fc], fa[1], fb, acc[1][fc]);
            }
        }
    }
    __syncthreads();

    float* scr = smemf + wid * 320;
#pragma unroll
    for (int fr = 0; fr < 2; ++fr) {
#pragma unroll
        for (int fc = 0; fc < 2; ++fc) {
            wmma::store_matrix_sync(scr, acc[fr][fc], 20, wmma::mem_row_major);
            __syncwarp();
            int rl = lane >> 1, half = lane & 1;
            int grow = rbase + wr + fr * 16 + rl;
            int f0 = wm + fc * 16 + half * 8;
            int idx = (((grow << 8) + n) << 6) + f0;
            float4 b0 = *(const float4*)&b2_[(n << 6) + f0];
            float4 b1v = *(const float4*)&b2_[(n << 6) + f0 + 4];
            float4 i0 = *(const float4*)&g_bufin[idx];
            float4 i1 = *(const float4*)&g_bufin[idx + 4];
            float z[8];
            z[0] = scr[rl * 20 + half * 8 + 0] + b0.x + i0.x;
            z[1] = scr[rl * 20 + half * 8 + 1] + b0.y + i0.y;
            z[2] = scr[rl * 20 + half * 8 + 2] + b0.z + i0.z;
            z[3] = scr[rl * 20 + half * 8 + 3] + b0.w + i0.w;
            z[4] = scr[rl * 20 + half * 8 + 4] + b1v.x + i1.x;
            z[5] = scr[rl * 20 + half * 8 + 5] + b1v.y + i1.y;
            z[6] = scr[rl * 20 + half * 8 + 6] + b1v.z + i1.z;
            z[7] = scr[rl * 20 + half * 8 + 7] + b1v.w + i1.w;

            // recon scatter: pixel from (grow, n, branch)
            const int branch = grow >> 9;
            const int b = (grow >> 8) & 1;
            const int g = grow & 255;
            int h, w;
            if (branch == 0) { h = ((n >> 4) << 4) | (g >> 4); w = ((n & 15) << 4) | (g & 15); }
            else             { h = ((g >> 4) << 4) | (n >> 4); w = ((g & 15) << 4) | (n & 15); }
            const int pix = (b << 16) | (h << 8) | w;
            const int obase = pix * 128 + branch * 64 + f0;
            float4 x0 = *(const float4*)&x[obase];
            float4 x1 = *(const float4*)&x[obase + 4];
            *(float4*)&out[obase]     = make_float4(z[0] + x0.x, z[1] + x0.y,
                                                    z[2] + x0.z, z[3] + x0.w);
            *(float4*)&out[obase + 4] = make_float4(z[4] + x1.x, z[5] + x1.y,
                                                    z[6] + x1.z, z[7] + x1.w);
            if (branch && write_glob) {
                *(float4*)&gout[pix * 64 + f0]     = make_float4(z[0], z[1], z[2], z[3]);
                *(float4*)&gout[pix * 64 + f0 + 4] = make_float4(z[4], z[5], z[6], z[7]);
            }
            __syncwarp();
        }
    }
}

// ---------------------------------------------------------------------------
extern "C" void kernel_launch(void* const* d_in, const int* in_sizes, int n_in,
                              void* d_out, int out_size)
{
    const float* x    = (const float*)d_in[0];
    const float* ln1g = (const float*)d_in[1];
    const float* ln1b = (const float*)d_in[2];
    const float* Wp   = (const float*)d_in[3];
    const float* bp   = (const float*)d_in[4];
    const float* ln2g = (const float*)d_in[5];
    const float* ln2b = (const float*)d_in[6];
    const float* W1   = (const float*)d_in[7];
    const float* b1   = (const float*)d_in[8];
    const float* ln3g = (const float*)d_in[9];
    const float* ln3b = (const float*)d_in[10];
    const float* Wsgu = (const float*)d_in[11];
    const float* bsgu = (const float*)d_in[12];
    const float* W2   = (const float*)d_in[13];
    const float* b2   = (const float*)d_in[14];

    float* out = (float*)d_out;
    const int OUT_MAIN = 2 * 256 * 256 * 128;
    const int OUT_GLOB = 2 * 256 * 256 * 64;
    int write_glob = (out_size >= OUT_MAIN + OUT_GLOB) ? 1 : 0;
    float* gout = out + OUT_MAIN;

    k0_wsgu_t    <<<dim3(8, 8, 192), dim3(32, 8)>>>(Wsgu);
    k1_ln_proj   <<<8192, 256>>>(x, ln1g, ln1b, Wp, bp);
    k2_gmlp_in   <<<dim3(3, 8, 256), 256>>>(W1, b1, ln2g, ln2b);
    k2b_ln3_t    <<<dim3(1024, 8, 1), 256>>>(ln3g, ln3b);
    k3_wmma      <<<dim3(8, 2, 192), 256>>>();
    k3b_gate_mul <<<dim3(1024, 8, 6), 256>>>(bsgu);
    k4_gmlp_out  <<<dim3(8, 256, 1), 256>>>(W2, b2, x, out, gout, write_glob);
}

// round 12
// speedup vs baseline: 1.5838x; 1.0162x over previous
#include <cuda_runtime.h>
#include <cuda_bf16.h>
#include <mma.h>
#include <math.h>
#include <cstdint>

using namespace nvcuda;

// ---------------------------------------------------------------------------
// Shapes: B=2, H=W=256, C=128, S=16 -> G=256, N=256, CI=64, F1=384, HF=192
// R = 2 branches * B * G = 1024
// ---------------------------------------------------------------------------
#define R_TOT   1024
#define NPATCH  256
#define CI_DIM  64
#define HF_DIM  192

__device__ float  g_bufin[R_TOT * NPATCH * CI_DIM];   // blocked gmlp input (fp32)
__device__ float2 g_stat [R_TOT * NPATCH];            // ln2 (mean, rstd) per (r,n)
__device__ float  g_v    [R_TOT * NPATCH * HF_DIM];   // v (fp32)
__device__ float  g_ut   [R_TOT * HF_DIM * NPATCH];   // uv [R][N][HF] (fp32)
__device__ __align__(16) __nv_bfloat16 g_upreb [R_TOT * NPATCH * HF_DIM]; // u bf16; later raw gate [r][c][n]
__device__ __align__(16) __nv_bfloat16 g_utb   [R_TOT * HF_DIM * NPATCH]; // ln3'd u^T bf16
__device__ __align__(16) __nv_bfloat16 g_wsgub [HF_DIM * NPATCH * NPATCH];// Wsgu^T bf16 [c][m][k]

__device__ __forceinline__ float gelu_exact(float x) {
    return 0.5f * x * (1.0f + erff(x * 0.7071067811865476f));
}

// ---- cp.async helpers ----
__device__ __forceinline__ void cp16(void* smem_dst, const void* gsrc) {
    uint32_t d = (uint32_t)__cvta_generic_to_shared(smem_dst);
    asm volatile("cp.async.cg.shared.global [%0], [%1], 16;"
                 :: "r"(d), "l"(gsrc) : "memory");
}
#define CP_COMMIT()  asm volatile("cp.async.commit_group;" ::: "memory")
#define CP_WAIT(n)   asm volatile("cp.async.wait_group %0;" :: "n"(n) : "memory")

__device__ __forceinline__ uint4 pack8bf(const float* v) {
    union { __nv_bfloat16 h[8]; uint4 u; } r;
#pragma unroll
    for (int i = 0; i < 8; ++i) r.h[i] = __float2bfloat16(v[i]);
    return r.u;
}

// ---------------------------------------------------------------------------
// K0: Wsgu [c][n][m] fp32 -> g_wsgub [c][m][n] bf16
// ---------------------------------------------------------------------------
__global__ __launch_bounds__(256) void k0_wsgu_t(const float* __restrict__ Wsgu)
{
    __shared__ float tile[32][33];
    const int c  = blockIdx.z;
    const int mb = blockIdx.x * 32;
    const int nb = blockIdx.y * 32;
    const int tx = threadIdx.x, ty = threadIdx.y;
#pragma unroll
    for (int j = 0; j < 4; ++j) {
        int n = ty + j * 8;
        tile[n][tx] = Wsgu[(((size_t)c << 8) + nb + n) * 256 + mb + tx];
    }
    __syncthreads();
#pragma unroll
    for (int j = 0; j < 4; ++j) {
        int m = ty + j * 8;
        g_wsgub[(((size_t)c << 8) + mb + m) * 256 + nb + tx] =
            __float2bfloat16(tile[tx][m]);
    }
}

// ---------------------------------------------------------------------------
// K1: tf32 wmma (RN): ln1 + Dense(W_proj) + GELU, scatter blocked + ln2 stats
// grid 1024 x 256 thr; 128 pixels/CTA; block 128x128, K=128.
// ---------------------------------------------------------------------------
#define K1_SMEM ((128 * 128 + 16 * 128) * 4)
__global__ __launch_bounds__(256) void k1_ln_proj(
    const float* __restrict__ x, const float* __restrict__ ln1g,
    const float* __restrict__ ln1b, const float* __restrict__ Wp,
    const float* __restrict__ bp)
{
    extern __shared__ float dsm[];
    float* sA = dsm;                 // [c][row] 128x128
    float* sB = dsm + 128 * 128;     // [k][f]   16x128
    __shared__ float sg[128], sb[128];
    const int t = threadIdx.x;
    const int wid = t >> 5, lane = t & 31;
    const int pbase = blockIdx.x * 128;

    if (t < 128) { sg[t] = ln1g[t]; sb[t] = ln1b[t]; }
    __syncthreads();

    // ---- A load + ln1 (2 threads/row, 64 ch each) ----
    {
        const int row = t >> 1, half = t & 1;
        const float* src = x + (size_t)(pbase + row) * 128 + half * 64;
        float4 v[16];
        float s = 0.f, s2 = 0.f;
#pragma unroll
        for (int j = 0; j < 16; ++j) {
            v[j] = *(const float4*)&src[j * 4];
            s  += v[j].x + v[j].y + v[j].z + v[j].w;
            s2 += v[j].x * v[j].x + v[j].y * v[j].y + v[j].z * v[j].z + v[j].w * v[j].w;
        }
        s  += __shfl_xor_sync(0xffffffffu, s,  1);
        s2 += __shfl_xor_sync(0xffffffffu, s2, 1);
        float m  = s * (1.f / 128.f);
        float rs = rsqrtf(s2 * (1.f / 128.f) - m * m + 1e-3f);
#pragma unroll
        for (int j = 0; j < 16; ++j) {
            int c = half * 64 + j * 4;
            sA[(c + 0) * 128 + row] = (v[j].x - m) * rs * sg[c + 0] + sb[c + 0];
            sA[(c + 1) * 128 + row] = (v[j].y - m) * rs * sg[c + 1] + sb[c + 1];
            sA[(c + 2) * 128 + row] = (v[j].z - m) * rs * sg[c + 2] + sb[c + 2];
            sA[(c + 3) * 128 + row] = (v[j].w - m) * rs * sg[c + 3] + sb[c + 3];
        }
    }

    const int wr = (wid >> 1) * 32;  // warp rows
    const int wm = (wid & 1) * 64;   // warp f
    wmma::fragment<wmma::accumulator, 16, 16, 8, float> acc[2][4];
#pragma unroll
    for (int i = 0; i < 2; ++i)
#pragma unroll
        for (int j = 0; j < 4; ++j) wmma::fill_fragment(acc[i][j], 0.0f);

    const int bk = t >> 4, bf8 = (t & 15) * 8;
    float4 rB0 = *(const float4*)&Wp[bk * 128 + bf8];
    float4 rB1 = *(const float4*)&Wp[bk * 128 + bf8 + 4];

    for (int s = 0; s < 8; ++s) {
        __syncthreads();
        *(float4*)&sB[bk * 128 + bf8]     = rB0;
        *(float4*)&sB[bk * 128 + bf8 + 4] = rB1;
        __syncthreads();
        if (s < 7) {
            rB0 = *(const float4*)&Wp[((s + 1) * 16 + bk) * 128 + bf8];
            rB1 = *(const float4*)&Wp[((s + 1) * 16 + bk) * 128 + bf8 + 4];
        }
#pragma unroll
        for (int kk = 0; kk < 2; ++kk) {
            wmma::fragment<wmma::matrix_a, 16, 16, 8, wmma::precision::tf32, wmma::col_major> fa[2];
#pragma unroll
            for (int fr = 0; fr < 2; ++fr) {
                wmma::load_matrix_sync(fa[fr], &sA[(s * 16 + kk * 8) * 128 + wr + fr * 16], 128);
#pragma unroll
                for (int e = 0; e < fa[fr].num_elements; ++e)
                    fa[fr].x[e] = wmma::__float_to_tf32(fa[fr].x[e]);
            }
#pragma unroll
            for (int fc = 0; fc < 4; ++fc) {
                wmma::fragment<wmma::matrix_b, 16, 16, 8, wmma::precision::tf32, wmma::row_major> fb;
                wmma::load_matrix_sync(fb, &sB[(kk * 8) * 128 + wm + fc * 16], 128);
#pragma unroll
                for (int e = 0; e < fb.num_elements; ++e)
                    fb.x[e] = wmma::__float_to_tf32(fb.x[e]);
                wmma::mma_sync(acc[0][fc], fa[0], fb, acc[0][fc]);
                wmma::mma_sync(acc[1][fc], fa[1], fb, acc[1][fc]);
            }
        }
    }
    __syncthreads();

    // ---- epilogue: bias+gelu, scatter to g_bufin, ln2 stats ----
    float* scr = dsm + wid * 320;
    const int branch = wm >> 6;
#pragma unroll
    for (int fr = 0; fr < 2; ++fr) {
        const int rl = lane >> 1, half = lane & 1;
        const int p = pbase + wr + fr * 16 + rl;
        const int b = p >> 16, h = (p >> 8) & 255, w = p & 255;
        const int g  = ((h >> 4) << 4) | (w >> 4);
        const int nn = ((h & 15) << 4) | (w & 15);
        const int r = branch * 512 + (b << 8) + g;
        float ss = 0.f, ss2 = 0.f;
#pragma unroll
        for (int fc = 0; fc < 4; ++fc) {
            wmma::store_matrix_sync(scr, acc[fr][fc], 20, wmma::mem_row_major);
            __syncwarp();
            const int f0 = wm + fc * 16 + half * 8;
            float4 b0 = *(const float4*)&bp[f0];
            float4 b1 = *(const float4*)&bp[f0 + 4];
            const float bias[8] = {b0.x, b0.y, b0.z, b0.w, b1.x, b1.y, b1.z, b1.w};
            float vals[8];
#pragma unroll
            for (int e = 0; e < 8; ++e) {
                vals[e] = gelu_exact(scr[rl * 20 + half * 8 + e] + bias[e]);
                ss += vals[e]; ss2 += vals[e] * vals[e];
            }
            const int cloc = f0 & 63;
            float* dst = &g_bufin[((size_t)(r << 8) + nn) * 64 + cloc];
            *(float4*)&dst[0] = make_float4(vals[0], vals[1], vals[2], vals[3]);
            *(float4*)&dst[4] = make_float4(vals[4], vals[5], vals[6], vals[7]);
            __syncwarp();
        }
        ss  += __shfl_xor_sync(0xffffffffu, ss,  1);
        ss2 += __shfl_xor_sync(0xffffffffu, ss2, 1);
        if ((lane & 1) == 0) {
            float m  = ss * (1.f / 64.f);
            float rs = rsqrtf(ss2 * (1.f / 64.f) - m * m + 1e-3f);
            g_stat[(r << 8) + nn] = make_float2(m, rs);
        }
    }
}

// ---------------------------------------------------------------------------
// K2: tf32 wmma (RN): y = gelu(ln2(bufin) @ W1[n] + b1[n])
// Block 128 rows x 192 f; ftile0 -> u (bf16), ftile1 -> v (fp32).
// grid (2 ftiles, 8 rtiles, 256 n) x 256 thr. Warp tile 32x96.
// ---------------------------------------------------------------------------
__global__ __launch_bounds__(256) void k2_gmlp_in(
    const float* __restrict__ W1, const float* __restrict__ b1_,
    const float* __restrict__ ln2g, const float* __restrict__ ln2b)
{
    __shared__ float sA[64 * 128];     // A^T [k][row]; reused as epilogue scratch
    __shared__ float sB[16 * 192];     // B stage [k][f]
    __shared__ float sg[64], sb[64];
    const int t = threadIdx.x;
    const int wid = t >> 5, lane = t & 31;
    const int ftile = blockIdx.x;          // 0 -> u, 1 -> v
    const int fbase = ftile * 192;
    const int rbase = blockIdx.y * 128;
    const int n = blockIdx.z;

    if (t < 64) { sg[t] = ln2g[t]; sb[t] = ln2b[t]; }
    __syncthreads();

    // A load + ln2 (2 threads/row)
    {
        const int row = t >> 1, half = t & 1;
        const float* src = g_bufin + ((size_t)((rbase + row) << 8) + n) * 64;
        float2 st = g_stat[((rbase + row) << 8) + n];
#pragma unroll
        for (int j = 0; j < 8; ++j) {
            int k = j * 8 + half * 4;
            float4 v = *(const float4*)&src[k];
            sA[(k + 0) * 128 + row] = (v.x - st.x) * st.y * sg[k + 0] + sb[k + 0];
            sA[(k + 1) * 128 + row] = (v.y - st.x) * st.y * sg[k + 1] + sb[k + 1];
            sA[(k + 2) * 128 + row] = (v.z - st.x) * st.y * sg[k + 2] + sb[k + 2];
            sA[(k + 3) * 128 + row] = (v.w - st.x) * st.y * sg[k + 3] + sb[k + 3];
        }
    }

    const int wr = (wid >> 1) * 32;    // warp rows (4 groups)
    const int wm = (wid & 1) * 96;     // warp f (2 groups x 96)
    wmma::fragment<wmma::accumulator, 16, 16, 8, float> acc[2][6];
#pragma unroll
    for (int i = 0; i < 2; ++i)
#pragma unroll
        for (int j = 0; j < 6; ++j) wmma::fill_fragment(acc[i][j], 0.0f);

    const float* Wn = W1 + (size_t)n * 64 * 384 + fbase;
    const int bk = t >> 4, bf4 = (t & 15) * 4;   // B loader: 16 rows x 3 chunks of 64
    float4 rB[3];
#pragma unroll
    for (int j = 0; j < 3; ++j)
        rB[j] = *(const float4*)&Wn[bk * 384 + j * 64 + bf4];

    for (int s = 0; s < 4; ++s) {
        __syncthreads();
#pragma unroll
        for (int j = 0; j < 3; ++j)
            *(float4*)&sB[bk * 192 + j * 64 + bf4] = rB[j];
        __syncthreads();
        if (s < 3) {
#pragma unroll
            for (int j = 0; j < 3; ++j)
                rB[j] = *(const float4*)&Wn[((s + 1) * 16 + bk) * 384 + j * 64 + bf4];
        }
#pragma unroll
        for (int kk = 0; kk < 2; ++kk) {
            wmma::fragment<wmma::matrix_a, 16, 16, 8, wmma::precision::tf32, wmma::col_major> fa[2];
#pragma unroll
            for (int fr = 0; fr < 2; ++fr) {
                wmma::load_matrix_sync(fa[fr], &sA[(s * 16 + kk * 8) * 128 + wr + fr * 16], 128);
#pragma unroll
                for (int e = 0; e < fa[fr].num_elements; ++e)
                    fa[fr].x[e] = wmma::__float_to_tf32(fa[fr].x[e]);
            }
#pragma unroll
            for (int fc = 0; fc < 6; ++fc) {
                wmma::fragment<wmma::matrix_b, 16, 16, 8, wmma::precision::tf32, wmma::row_major> fb;
                wmma::load_matrix_sync(fb, &sB[(kk * 8) * 192 + wm + fc * 16], 192);
#pragma unroll
                for (int e = 0; e < fb.num_elements; ++e)
                    fb.x[e] = wmma::__float_to_tf32(fb.x[e]);
                wmma::mma_sync(acc[0][fc], fa[0], fb, acc[0][fc]);
                wmma::mma_sync(acc[1][fc], fa[1], fb, acc[1][fc]);
            }
        }
    }
    __syncthreads();

    float* scr = sA + wid * 320;
#pragma unroll
    for (int fr = 0; fr < 2; ++fr) {
#pragma unroll
        for (int fc = 0; fc < 6; ++fc) {
            wmma::store_matrix_sync(scr, acc[fr][fc], 20, wmma::mem_row_major);
            __syncwarp();
            int rl = lane >> 1, half = lane & 1;
            int grow = rbase + wr + fr * 16 + rl;
            int flocal = wm + fc * 16 + half * 8;       // 0..191 within ftile
            float vals[8];
            float4 b0 = *(const float4*)&b1_[n * 384 + fbase + flocal];
            float4 b1v = *(const float4*)&b1_[n * 384 + fbase + flocal + 4];
            const float bias[8] = {b0.x, b0.y, b0.z, b0.w, b1v.x, b1v.y, b1v.z, b1v.w};
#pragma unroll
            for (int e = 0; e < 8; ++e)
                vals[e] = gelu_exact(scr[rl * 20 + half * 8 + e] + bias[e]);
            if (ftile == 0) {
                *(uint4*)&g_upreb[((size_t)(grow << 8) + n) * 192 + flocal] = pack8bf(vals);
            } else {
                float* dst = &g_v[((size_t)(grow << 8) + n) * 192 + flocal];
                *(float4*)&dst[0] = make_float4(vals[0], vals[1], vals[2], vals[3]);
                *(float4*)&dst[4] = make_float4(vals[4], vals[5], vals[6], vals[7]);
            }
            __syncwarp();
        }
    }
}

// ---------------------------------------------------------------------------
// K2b: ln3 over u bf16 (HF=192) + transpose -> g_utb[r][c][n] (bf16)
// vectorized uint4 loads (8 bf16 each)
// ---------------------------------------------------------------------------
__global__ __launch_bounds__(256) void k2b_ln3_t(
    const float* __restrict__ ln3g, const float* __restrict__ ln3b)
{
    __shared__ float s[32][193];
    __shared__ float sm[32], sr[32];
    const int t = threadIdx.x;
    const int r = blockIdx.x;
    const int nb = blockIdx.y * 32;
    const uint4* src4 = (const uint4*)(g_upreb + (((size_t)r << 8) + nb) * 192);
#pragma unroll
    for (int it = 0; it < 3; ++it) {
        int u = t + it * 256;            // 0..767, 8 bf16 each
        int row = u / 24;
        int col = (u % 24) * 8;
        union { uint4 raw; __nv_bfloat16 h[8]; } d;
        d.raw = src4[u];
#pragma unroll
        for (int e = 0; e < 8; ++e)
            s[row][col + e] = __bfloat162float(d.h[e]);
    }
    __syncthreads();
    const int warp = t >> 5, lane = t & 31;
#pragma unroll
    for (int j = 0; j < 4; ++j) {
        int row = warp * 4 + j;
        float su = 0.f, s2 = 0.f;
#pragma unroll
        for (int k = 0; k < 6; ++k) { float v = s[row][lane + k * 32]; su += v; s2 += v * v; }
#pragma unroll
        for (int off = 16; off > 0; off >>= 1) {
            su += __shfl_xor_sync(0xffffffffu, su, off);
            s2 += __shfl_xor_sync(0xffffffffu, s2, off);
        }
        if (lane == 0) {
            float m = su * (1.f / 192.f);
            sm[row] = m;
            sr[row] = rsqrtf(s2 * (1.f / 192.f) - m * m + 1e-3f);
        }
    }
    __syncthreads();
    const int n_l = t & 31, c0 = t >> 5;
#pragma unroll
    for (int it = 0; it < 24; ++it) {
        int c = c0 + it * 8;
        float v = (s[n_l][c] - sm[n_l]) * sr[n_l] * ln3g[c] + ln3b[c];
        g_utb[((r * 192 + c) << 8) + nb + n_l] = __float2bfloat16(v);
    }
}

// ---------------------------------------------------------------------------
// K3: spatial gating via wmma bf16, cp.async double-buffered.
// raw gate (no bias) -> g_upreb bf16 [r][c][n].
// grid (8 rtiles, 2 mtiles, 192 c) x 256 thr.
// ---------------------------------------------------------------------------
#define K3_LD 40
__global__ __launch_bounds__(256) void k3_wmma()
{
    __shared__ __align__(16) char smemraw[2 * 128 * K3_LD * 2 * 2];
    __nv_bfloat16* sA = (__nv_bfloat16*)smemraw;
    __nv_bfloat16* sB = sA + 2 * 128 * K3_LD;
    const int t = threadIdx.x;
    const int wid = t >> 5, lane = t & 31;
    const int rbase = blockIdx.x * 128;
    const int mbase = blockIdx.y * 128;
    const int c = blockIdx.z;

    const __nv_bfloat16* abase = g_utb + ((size_t)rbase * 192 + c) * 256;
    const __nv_bfloat16* bbase = g_wsgub + ((size_t)c << 16) + (size_t)mbase * 256;

    const int lr = t >> 1;
    const int lk = (t & 1) * 16;

    wmma::fragment<wmma::accumulator, 16, 16, 16, float> acc[2][4];
#pragma unroll
    for (int i = 0; i < 2; ++i)
#pragma unroll
        for (int j = 0; j < 4; ++j)
            wmma::fill_fragment(acc[i][j], 0.0f);

    const int wr = (wid >> 1) * 32;
    const int wm = (wid & 1) * 64;

    {
        const __nv_bfloat16* as = abase + (size_t)lr * (192 * 256) + lk;
        cp16(&sA[lr * K3_LD + lk], as);
        cp16(&sA[lr * K3_LD + lk + 8], as + 8);
        const __nv_bfloat16* bs = bbase + (size_t)lr * 256 + lk;
        cp16(&sB[lr * K3_LD + lk], bs);
        cp16(&sB[lr * K3_LD + lk + 8], bs + 8);
        CP_COMMIT();
    }

#pragma unroll
    for (int kb = 0; kb < 8; ++kb) {
        const int st = kb & 1;
        if (kb < 7) {
            const int kn = (kb + 1) * 32;
            const __nv_bfloat16* as = abase + (size_t)lr * (192 * 256) + kn + lk;
            cp16(&sA[(st ^ 1) * 128 * K3_LD + lr * K3_LD + lk], as);
            cp16(&sA[(st ^ 1) * 128 * K3_LD + lr * K3_LD + lk + 8], as + 8);
            const __nv_bfloat16* bs = bbase + (size_t)lr * 256 + kn + lk;
            cp16(&sB[(st ^ 1) * 128 * K3_LD + lr * K3_LD + lk], bs);
            cp16(&sB[(st ^ 1) * 128 * K3_LD + lr * K3_LD + lk + 8], bs + 8);
            CP_COMMIT();
            CP_WAIT(1);
        } else {
            CP_WAIT(0);
        }
        __syncthreads();

        const __nv_bfloat16* cA = sA + st * 128 * K3_LD;
        const __nv_bfloat16* cB = sB + st * 128 * K3_LD;
#pragma unroll
        for (int kk = 0; kk < 32; kk += 16) {
            wmma::fragment<wmma::matrix_a, 16, 16, 16, __nv_bfloat16, wmma::row_major> fa[2];
            wmma::load_matrix_sync(fa[0], &cA[(wr     ) * K3_LD + kk], K3_LD);
            wmma::load_matrix_sync(fa[1], &cA[(wr + 16) * K3_LD + kk], K3_LD);
#pragma unroll
            for (int j = 0; j < 4; ++j) {
                wmma::fragment<wmma::matrix_b, 16, 16, 16, __nv_bfloat16, wmma::col_major> fb;
                wmma::load_matrix_sync(fb, &cB[(wm + j * 16) * K3_LD + kk], K3_LD);
                wmma::mma_sync(acc[0][j], fa[0], fb, acc[0][j]);
                wmma::mma_sync(acc[1][j], fa[1], fb, acc[1][j]);
            }
        }
        __syncthreads();
    }

    float* scr = (float*)smemraw + wid * 320;
#pragma unroll
    for (int fr = 0; fr < 2; ++fr) {
#pragma unroll
        for (int fc = 0; fc < 4; ++fc) {
            wmma::store_matrix_sync(scr, acc[fr][fc], 20, wmma::mem_row_major);
            __syncwarp();
            int rl = lane >> 1, half = lane & 1;
            int grow = rbase + wr + fr * 16 + rl;
            int m0 = mbase + wm + fc * 16 + half * 8;
            float vals[8];
#pragma unroll
            for (int e = 0; e < 8; ++e) vals[e] = scr[rl * 20 + half * 8 + e];
            *(uint4*)&g_upreb[((size_t)grow * 192 + c) * 256 + m0] = pack8bf(vals);
            __syncwarp();
        }
    }
}

// ---------------------------------------------------------------------------
// K3b: uv[r][n][c] = (gate_bf16[r][c][n] + bsgu[c][n]) * v[r][n][c]
// vectorized loads both phases
// ---------------------------------------------------------------------------
__global__ __launch_bounds__(256) void k3b_gate_mul(const float* __restrict__ bsgu)
{
    __shared__ float s[32][33];
    const int t = threadIdx.x;
    const int r = blockIdx.x;
    const int nb = blockIdx.y * 32;
    const int cb = blockIdx.z * 32;
    {
        const int cc = t >> 3, n0 = (t & 7) * 4;
        union { uint2 raw; __nv_bfloat16 h[4]; } gt;
        gt.raw = *(const uint2*)&g_upreb[((size_t)(r * 192 + cb + cc) << 8) + nb + n0];
        float4 bs = *(const float4*)&bsgu[((cb + cc) << 8) + nb + n0];
        s[cc][n0 + 0] = __bfloat162float(gt.h[0]) + bs.x;
        s[cc][n0 + 1] = __bfloat162float(gt.h[1]) + bs.y;
        s[cc][n0 + 2] = __bfloat162float(gt.h[2]) + bs.z;
        s[cc][n0 + 3] = __bfloat162float(gt.h[3]) + bs.w;
    }
    __syncthreads();
    {
        const int nn = t >> 3, c4 = (t & 7) * 4;
        int idx = (((r << 8) + nb + nn) * 192) + cb + c4;
        float4 vv = *(const float4*)&g_v[idx];
        float4 o = make_float4(s[c4 + 0][nn] * vv.x, s[c4 + 1][nn] * vv.y,
                               s[c4 + 2][nn] * vv.z, s[c4 + 3][nn] * vv.w);
        *(float4*)&g_ut[idx] = o;
    }
}

// ---------------------------------------------------------------------------
// K4: tf32 wmma (RN): z = uv @ W2[n] + b2[n] + bufin, fused
// recon/concat/residual epilogue. grid (8 rtiles, 256 n) x 256 thr.
// ---------------------------------------------------------------------------
__global__ __launch_bounds__(256) void k4_gmlp_out(
    const float* __restrict__ W2, const float* __restrict__ b2_,
    const float* __restrict__ x, float* __restrict__ out,
    float* __restrict__ gout, int write_glob)
{
    __shared__ float smemf[16 * 128 + 16 * 64];
    float* sA = smemf;
    float* sB = smemf + 16 * 128;
    const int t = threadIdx.x;
    const int wid = t >> 5, lane = t & 31;
    const int rbase = blockIdx.x * 128;
    const int n = blockIdx.y;

    const int wr = (wid >> 1) * 32;
    const int wm = (wid & 1) * 32;
    wmma::fragment<wmma::accumulator, 16, 16, 8, float> acc[2][2];
#pragma unroll
    for (int i = 0; i < 2; ++i)
#pragma unroll
        for (int j = 0; j < 2; ++j) wmma::fill_fragment(acc[i][j], 0.0f);

    const int arow = t >> 1, ahalf = t & 1;
    const float* asrc = g_ut + ((size_t)((rbase + arow) << 8) + n) * 192;
    const int bkr = t >> 4, bf4 = (t & 15) * 4;
    const float* bsrc = W2 + (size_t)n * 192 * 64;

    float4 rA0 = *(const float4*)&asrc[ahalf * 8];
    float4 rA1 = *(const float4*)&asrc[ahalf * 8 + 4];
    float4 rB  = *(const float4*)&bsrc[bkr * 64 + bf4];

    for (int s = 0; s < 12; ++s) {
        __syncthreads();
        {
            int k0 = ahalf * 8;
            sA[(k0 + 0) * 128 + arow] = rA0.x; sA[(k0 + 1) * 128 + arow] = rA0.y;
            sA[(k0 + 2) * 128 + arow] = rA0.z; sA[(k0 + 3) * 128 + arow] = rA0.w;
            sA[(k0 + 4) * 128 + arow] = rA1.x; sA[(k0 + 5) * 128 + arow] = rA1.y;
            sA[(k0 + 6) * 128 + arow] = rA1.z; sA[(k0 + 7) * 128 + arow] = rA1.w;
            *(float4*)&sB[bkr * 64 + bf4] = rB;
        }
        __syncthreads();
        if (s < 11) {
            rA0 = *(const float4*)&asrc[(s + 1) * 16 + ahalf * 8];
            rA1 = *(const float4*)&asrc[(s + 1) * 16 + ahalf * 8 + 4];
            rB  = *(const float4*)&bsrc[((s + 1) * 16 + bkr) * 64 + bf4];
        }
#pragma unroll
        for (int kk = 0; kk < 2; ++kk) {
            wmma::fragment<wmma::matrix_a, 16, 16, 8, wmma::precision::tf32, wmma::col_major> fa[2];
#pragma unroll
            for (int fr = 0; fr < 2; ++fr) {
                wmma::load_matrix_sync(fa[fr], &sA[(kk * 8) * 128 + wr + fr * 16], 128);
#pragma unroll
                for (int e = 0; e < fa[fr].num_elements; ++e)
                    fa[fr].x[e] = wmma::__float_to_tf32(fa[fr].x[e]);
            }
#pragma unroll
            for (int fc = 0; fc < 2; ++fc) {
                wmma::fragment<wmma::matrix_b, 16, 16, 8, wmma::precision::tf32, wmma::row_major> fb;
                wmma::load_matrix_sync(fb, &sB[(kk * 8) * 64 + wm + fc * 16], 64);
#pragma unroll
                for (int e = 0; e < fb.num_elements; ++e)
                    fb.x[e] = wmma::__float_to_tf32(fb.x[e]);
                wmma::mma_sync(acc[0][fc], fa[0], fb, acc[0][fc]);
                wmma::mma_sync(acc[1][fc], fa[1], fb, acc[1][fc]);
            }
        }
    }
    __syncthreads();

    float* scr = smemf + wid * 320;
#pragma unroll
    for (int fr = 0; fr < 2; ++fr) {
#pragma unroll
        for (int fc = 0; fc < 2; ++fc) {
            wmma::store_matrix_sync(scr, acc[fr][fc], 20, wmma::mem_row_major);
            __syncwarp();
            int rl = lane >> 1, half = lane & 1;
            int grow = rbase + wr + fr * 16 + rl;
            int f0 = wm + fc * 16 + half * 8;
            int idx = (((grow << 8) + n) << 6) + f0;
            float4 b0 = *(const float4*)&b2_[(n << 6) + f0];
            float4 b1v = *(const float4*)&b2_[(n << 6) + f0 + 4];
            float4 i0 = *(const float4*)&g_bufin[idx];
            float4 i1 = *(const float4*)&g_bufin[idx + 4];
            float z[8];
            z[0] = scr[rl * 20 + half * 8 + 0] + b0.x + i0.x;
            z[1] = scr[rl * 20 + half * 8 + 1] + b0.y + i0.y;
            z[2] = scr[rl * 20 + half * 8 + 2] + b0.z + i0.z;
            z[3] = scr[rl * 20 + half * 8 + 3] + b0.w + i0.w;
            z[4] = scr[rl * 20 + half * 8 + 4] + b1v.x + i1.x;
            z[5] = scr[rl * 20 + half * 8 + 5] + b1v.y + i1.y;
            z[6] = scr[rl * 20 + half * 8 + 6] + b1v.z + i1.z;
            z[7] = scr[rl * 20 + half * 8 + 7] + b1v.w + i1.w;

            const int branch = grow >> 9;
            const int b = (grow >> 8) & 1;
            const int g = grow & 255;
            int h, w;
            if (branch == 0) { h = ((n >> 4) << 4) | (g >> 4); w = ((n & 15) << 4) | (g & 15); }
            else             { h = ((g >> 4) << 4) | (n >> 4); w = ((g & 15) << 4) | (n & 15); }
            const int pix = (b << 16) | (h << 8) | w;
            const int obase = pix * 128 + branch * 64 + f0;
            float4 x0 = *(const float4*)&x[obase];
            float4 x1 = *(const float4*)&x[obase + 4];
            *(float4*)&out[obase]     = make_float4(z[0] + x0.x, z[1] + x0.y,
                                                    z[2] + x0.z, z[3] + x0.w);
            *(float4*)&out[obase + 4] = make_float4(z[4] + x1.x, z[5] + x1.y,
                                                    z[6] + x1.z, z[7] + x1.w);
            if (branch && write_glob) {
                *(float4*)&gout[pix * 64 + f0]     = make_float4(z[0], z[1], z[2], z[3]);
                *(float4*)&gout[pix * 64 + f0 + 4] = make_float4(z[4], z[5], z[6], z[7]);
            }
            __syncwarp();
        }
    }
}

// ---------------------------------------------------------------------------
extern "C" void kernel_launch(void* const* d_in, const int* in_sizes, int n_in,
                              void* d_out, int out_size)
{
    const float* x    = (const float*)d_in[0];
    const float* ln1g = (const float*)d_in[1];
    const float* ln1b = (const float*)d_in[2];
    const float* Wp   = (const float*)d_in[3];
    const float* bp   = (const float*)d_in[4];
    const float* ln2g = (const float*)d_in[5];
    const float* ln2b = (const float*)d_in[6];
    const float* W1   = (const float*)d_in[7];
    const float* b1   = (const float*)d_in[8];
    const float* ln3g = (const float*)d_in[9];
    const float* ln3b = (const float*)d_in[10];
    const float* Wsgu = (const float*)d_in[11];
    const float* bsgu = (const float*)d_in[12];
    const float* W2   = (const float*)d_in[13];
    const float* b2   = (const float*)d_in[14];

    float* out = (float*)d_out;
    const int OUT_MAIN = 2 * 256 * 256 * 128;
    const int OUT_GLOB = 2 * 256 * 256 * 64;
    int write_glob = (out_size >= OUT_MAIN + OUT_GLOB) ? 1 : 0;
    float* gout = out + OUT_MAIN;

    static int configured = 0;
    if (!configured) {
        cudaFuncSetAttribute(k1_ln_proj,
            cudaFuncAttributeMaxDynamicSharedMemorySize, K1_SMEM);
        configured = 1;
    }

    k0_wsgu_t    <<<dim3(8, 8, 192), dim3(32, 8)>>>(Wsgu);
    k1_ln_proj   <<<1024, 256, K1_SMEM>>>(x, ln1g, ln1b, Wp, bp);
    k2_gmlp_in   <<<dim3(2, 8, 256), 256>>>(W1, b1, ln2g, ln2b);
    k2b_ln3_t    <<<dim3(1024, 8, 1), 256>>>(ln3g, ln3b);
    k3_wmma      <<<dim3(8, 2, 192), 256>>>();
    k3b_gate_mul <<<dim3(1024, 8, 6), 256>>>(bsgu);
    k4_gmlp_out  <<<dim3(8, 256, 1), 256>>>(W2, b2, x, out, gout, write_glob);
}

// round 13
// speedup vs baseline: 1.6197x; 1.0227x over previous
#include <cuda_runtime.h>
#include <cuda_bf16.h>
#include <mma.h>
#include <math.h>
#include <cstdint>

using namespace nvcuda;

// ---------------------------------------------------------------------------
// Shapes: B=2, H=W=256, C=128, S=16 -> G=256, N=256, CI=64, F1=384, HF=192
// R = 2 branches * B * G = 1024
// ---------------------------------------------------------------------------
#define R_TOT   1024
#define NPATCH  256
#define CI_DIM  64
#define HF_DIM  192

__device__ float  g_bufin[R_TOT * NPATCH * CI_DIM];   // blocked gmlp input (fp32)
__device__ float2 g_stat [R_TOT * NPATCH];            // ln2 (mean, rstd) per (r,n)
__device__ float  g_v    [R_TOT * NPATCH * HF_DIM];   // v (fp32)
__device__ float  g_ut   [R_TOT * HF_DIM * NPATCH];   // uv [R][N][HF] (fp32)
__device__ __align__(16) __nv_bfloat16 g_upreb [R_TOT * NPATCH * HF_DIM]; // u bf16; later raw gate [r][c][n]
__device__ __align__(16) __nv_bfloat16 g_utb   [R_TOT * HF_DIM * NPATCH]; // ln3'd u^T bf16
__device__ __align__(16) __nv_bfloat16 g_wsgub [HF_DIM * NPATCH * NPATCH];// Wsgu^T bf16 [c][m][k]

__device__ __forceinline__ float gelu_exact(float x) {
    return 0.5f * x * (1.0f + erff(x * 0.7071067811865476f));
}

// ---- cp.async helpers ----
__device__ __forceinline__ void cp16(void* smem_dst, const void* gsrc) {
    uint32_t d = (uint32_t)__cvta_generic_to_shared(smem_dst);
    asm volatile("cp.async.cg.shared.global [%0], [%1], 16;"
                 :: "r"(d), "l"(gsrc) : "memory");
}
#define CP_COMMIT()  asm volatile("cp.async.commit_group;" ::: "memory")
#define CP_WAIT(n)   asm volatile("cp.async.wait_group %0;" :: "n"(n) : "memory")

__device__ __forceinline__ uint4 pack8bf(const float* v) {
    union { __nv_bfloat16 h[8]; uint4 u; } r;
#pragma unroll
    for (int i = 0; i < 8; ++i) r.h[i] = __float2bfloat16(v[i]);
    return r.u;
}

// ---------------------------------------------------------------------------
// K0: Wsgu [c][n][m] fp32 -> g_wsgub [c][m][n] bf16
// ---------------------------------------------------------------------------
__global__ __launch_bounds__(256) void k0_wsgu_t(const float* __restrict__ Wsgu)
{
    __shared__ float tile[32][33];
    const int c  = blockIdx.z;
    const int mb = blockIdx.x * 32;
    const int nb = blockIdx.y * 32;
    const int tx = threadIdx.x, ty = threadIdx.y;
#pragma unroll
    for (int j = 0; j < 4; ++j) {
        int n = ty + j * 8;
        tile[n][tx] = Wsgu[(((size_t)c << 8) + nb + n) * 256 + mb + tx];
    }
    __syncthreads();
#pragma unroll
    for (int j = 0; j < 4; ++j) {
        int m = ty + j * 8;
        g_wsgub[(((size_t)c << 8) + mb + m) * 256 + nb + tx] =
            __float2bfloat16(tile[tx][m]);
    }
}

// ---------------------------------------------------------------------------
// K1: tf32 wmma (RN): ln1 + Dense(W_proj) + GELU, scatter blocked + ln2 stats
// grid 1024 x 256 thr; 128 pixels/CTA; block 128x128, K=128.
// ---------------------------------------------------------------------------
#define K1_SMEM ((128 * 128 + 16 * 128) * 4)
__global__ __launch_bounds__(256) void k1_ln_proj(
    const float* __restrict__ x, const float* __restrict__ ln1g,
    const float* __restrict__ ln1b, const float* __restrict__ Wp,
    const float* __restrict__ bp)
{
    extern __shared__ float dsm[];
    float* sA = dsm;                 // [c][row] 128x128
    float* sB = dsm + 128 * 128;     // [k][f]   16x128
    __shared__ float sg[128], sb[128];
    const int t = threadIdx.x;
    const int wid = t >> 5, lane = t & 31;
    const int pbase = blockIdx.x * 128;

    if (t < 128) { sg[t] = ln1g[t]; sb[t] = ln1b[t]; }
    __syncthreads();

    {
        const int row = t >> 1, half = t & 1;
        const float* src = x + (size_t)(pbase + row) * 128 + half * 64;
        float4 v[16];
        float s = 0.f, s2 = 0.f;
#pragma unroll
        for (int j = 0; j < 16; ++j) {
            v[j] = *(const float4*)&src[j * 4];
            s  += v[j].x + v[j].y + v[j].z + v[j].w;
            s2 += v[j].x * v[j].x + v[j].y * v[j].y + v[j].z * v[j].z + v[j].w * v[j].w;
        }
        s  += __shfl_xor_sync(0xffffffffu, s,  1);
        s2 += __shfl_xor_sync(0xffffffffu, s2, 1);
        float m  = s * (1.f / 128.f);
        float rs = rsqrtf(s2 * (1.f / 128.f) - m * m + 1e-3f);
#pragma unroll
        for (int j = 0; j < 16; ++j) {
            int c = half * 64 + j * 4;
            sA[(c + 0) * 128 + row] = (v[j].x - m) * rs * sg[c + 0] + sb[c + 0];
            sA[(c + 1) * 128 + row] = (v[j].y - m) * rs * sg[c + 1] + sb[c + 1];
            sA[(c + 2) * 128 + row] = (v[j].z - m) * rs * sg[c + 2] + sb[c + 2];
            sA[(c + 3) * 128 + row] = (v[j].w - m) * rs * sg[c + 3] + sb[c + 3];
        }
    }

    const int wr = (wid >> 1) * 32;
    const int wm = (wid & 1) * 64;
    wmma::fragment<wmma::accumulator, 16, 16, 8, float> acc[2][4];
#pragma unroll
    for (int i = 0; i < 2; ++i)
#pragma unroll
        for (int j = 0; j < 4; ++j) wmma::fill_fragment(acc[i][j], 0.0f);

    const int bk = t >> 4, bf8 = (t & 15) * 8;
    float4 rB0 = *(const float4*)&Wp[bk * 128 + bf8];
    float4 rB1 = *(const float4*)&Wp[bk * 128 + bf8 + 4];

    for (int s = 0; s < 8; ++s) {
        __syncthreads();
        *(float4*)&sB[bk * 128 + bf8]     = rB0;
        *(float4*)&sB[bk * 128 + bf8 + 4] = rB1;
        __syncthreads();
        if (s < 7) {
            rB0 = *(const float4*)&Wp[((s + 1) * 16 + bk) * 128 + bf8];
            rB1 = *(const float4*)&Wp[((s + 1) * 16 + bk) * 128 + bf8 + 4];
        }
#pragma unroll
        for (int kk = 0; kk < 2; ++kk) {
            wmma::fragment<wmma::matrix_a, 16, 16, 8, wmma::precision::tf32, wmma::col_major> fa[2];
#pragma unroll
            for (int fr = 0; fr < 2; ++fr) {
                wmma::load_matrix_sync(fa[fr], &sA[(s * 16 + kk * 8) * 128 + wr + fr * 16], 128);
#pragma unroll
                for (int e = 0; e < fa[fr].num_elements; ++e)
                    fa[fr].x[e] = wmma::__float_to_tf32(fa[fr].x[e]);
            }
#pragma unroll
            for (int fc = 0; fc < 4; ++fc) {
                wmma::fragment<wmma::matrix_b, 16, 16, 8, wmma::precision::tf32, wmma::row_major> fb;
                wmma::load_matrix_sync(fb, &sB[(kk * 8) * 128 + wm + fc * 16], 128);
#pragma unroll
                for (int e = 0; e < fb.num_elements; ++e)
                    fb.x[e] = wmma::__float_to_tf32(fb.x[e]);
                wmma::mma_sync(acc[0][fc], fa[0], fb, acc[0][fc]);
                wmma::mma_sync(acc[1][fc], fa[1], fb, acc[1][fc]);
            }
        }
    }
    __syncthreads();

    float* scr = dsm + wid * 320;
    const int branch = wm >> 6;
#pragma unroll
    for (int fr = 0; fr < 2; ++fr) {
        const int rl = lane >> 1, half = lane & 1;
        const int p = pbase + wr + fr * 16 + rl;
        const int b = p >> 16, h = (p >> 8) & 255, w = p & 255;
        const int g  = ((h >> 4) << 4) | (w >> 4);
        const int nn = ((h & 15) << 4) | (w & 15);
        const int r = branch * 512 + (b << 8) + g;
        float ss = 0.f, ss2 = 0.f;
#pragma unroll
        for (int fc = 0; fc < 4; ++fc) {
            wmma::store_matrix_sync(scr, acc[fr][fc], 20, wmma::mem_row_major);
            __syncwarp();
            const int f0 = wm + fc * 16 + half * 8;
            float4 b0 = *(const float4*)&bp[f0];
            float4 b1 = *(const float4*)&bp[f0 + 4];
            const float bias[8] = {b0.x, b0.y, b0.z, b0.w, b1.x, b1.y, b1.z, b1.w};
            float vals[8];
#pragma unroll
            for (int e = 0; e < 8; ++e) {
                vals[e] = gelu_exact(scr[rl * 20 + half * 8 + e] + bias[e]);
                ss += vals[e]; ss2 += vals[e] * vals[e];
            }
            const int cloc = f0 & 63;
            float* dst = &g_bufin[((size_t)(r << 8) + nn) * 64 + cloc];
            *(float4*)&dst[0] = make_float4(vals[0], vals[1], vals[2], vals[3]);
            *(float4*)&dst[4] = make_float4(vals[4], vals[5], vals[6], vals[7]);
            __syncwarp();
        }
        ss  += __shfl_xor_sync(0xffffffffu, ss,  1);
        ss2 += __shfl_xor_sync(0xffffffffu, ss2, 1);
        if ((lane & 1) == 0) {
            float m  = ss * (1.f / 64.f);
            float rs = rsqrtf(ss2 * (1.f / 64.f) - m * m + 1e-3f);
            g_stat[(r << 8) + nn] = make_float2(m, rs);
        }
    }
}

// ---------------------------------------------------------------------------
// K2: tf32 wmma (RN): y = gelu(ln2(bufin) @ W1[n] + b1[n])
// Block 128 rows x 192 f; ftile0 -> u (bf16), ftile1 -> v (fp32).
// grid (2 ftiles, 8 rtiles, 256 n) x 256 thr. Warp tile 32x96.
// ---------------------------------------------------------------------------
__global__ __launch_bounds__(256) void k2_gmlp_in(
    const float* __restrict__ W1, const float* __restrict__ b1_,
    const float* __restrict__ ln2g, const float* __restrict__ ln2b)
{
    __shared__ float sA[64 * 128];
    __shared__ float sB[16 * 192];
    __shared__ float sg[64], sb[64];
    const int t = threadIdx.x;
    const int wid = t >> 5, lane = t & 31;
    const int ftile = blockIdx.x;
    const int fbase = ftile * 192;
    const int rbase = blockIdx.y * 128;
    const int n = blockIdx.z;

    if (t < 64) { sg[t] = ln2g[t]; sb[t] = ln2b[t]; }
    __syncthreads();

    {
        const int row = t >> 1, half = t & 1;
        const float* src = g_bufin + ((size_t)((rbase + row) << 8) + n) * 64;
        float2 st = g_stat[((rbase + row) << 8) + n];
#pragma unroll
        for (int j = 0; j < 8; ++j) {
            int k = j * 8 + half * 4;
            float4 v = *(const float4*)&src[k];
            sA[(k + 0) * 128 + row] = (v.x - st.x) * st.y * sg[k + 0] + sb[k + 0];
            sA[(k + 1) * 128 + row] = (v.y - st.x) * st.y * sg[k + 1] + sb[k + 1];
            sA[(k + 2) * 128 + row] = (v.z - st.x) * st.y * sg[k + 2] + sb[k + 2];
            sA[(k + 3) * 128 + row] = (v.w - st.x) * st.y * sg[k + 3] + sb[k + 3];
        }
    }

    const int wr = (wid >> 1) * 32;
    const int wm = (wid & 1) * 96;
    wmma::fragment<wmma::accumulator, 16, 16, 8, float> acc[2][6];
#pragma unroll
    for (int i = 0; i < 2; ++i)
#pragma unroll
        for (int j = 0; j < 6; ++j) wmma::fill_fragment(acc[i][j], 0.0f);

    const float* Wn = W1 + (size_t)n * 64 * 384 + fbase;
    const int bk = t >> 4, bf4 = (t & 15) * 4;
    float4 rB[3];
#pragma unroll
    for (int j = 0; j < 3; ++j)
        rB[j] = *(const float4*)&Wn[bk * 384 + j * 64 + bf4];

    for (int s = 0; s < 4; ++s) {
        __syncthreads();
#pragma unroll
        for (int j = 0; j < 3; ++j)
            *(float4*)&sB[bk * 192 + j * 64 + bf4] = rB[j];
        __syncthreads();
        if (s < 3) {
#pragma unroll
            for (int j = 0; j < 3; ++j)
                rB[j] = *(const float4*)&Wn[((s + 1) * 16 + bk) * 384 + j * 64 + bf4];
        }
#pragma unroll
        for (int kk = 0; kk < 2; ++kk) {
            wmma::fragment<wmma::matrix_a, 16, 16, 8, wmma::precision::tf32, wmma::col_major> fa[2];
#pragma unroll
            for (int fr = 0; fr < 2; ++fr) {
                wmma::load_matrix_sync(fa[fr], &sA[(s * 16 + kk * 8) * 128 + wr + fr * 16], 128);
#pragma unroll
                for (int e = 0; e < fa[fr].num_elements; ++e)
                    fa[fr].x[e] = wmma::__float_to_tf32(fa[fr].x[e]);
            }
#pragma unroll
            for (int fc = 0; fc < 6; ++fc) {
                wmma::fragment<wmma::matrix_b, 16, 16, 8, wmma::precision::tf32, wmma::row_major> fb;
                wmma::load_matrix_sync(fb, &sB[(kk * 8) * 192 + wm + fc * 16], 192);
#pragma unroll
                for (int e = 0; e < fb.num_elements; ++e)
                    fb.x[e] = wmma::__float_to_tf32(fb.x[e]);
                wmma::mma_sync(acc[0][fc], fa[0], fb, acc[0][fc]);
                wmma::mma_sync(acc[1][fc], fa[1], fb, acc[1][fc]);
            }
        }
    }
    __syncthreads();

    float* scr = sA + wid * 320;
#pragma unroll
    for (int fr = 0; fr < 2; ++fr) {
#pragma unroll
        for (int fc = 0; fc < 6; ++fc) {
            wmma::store_matrix_sync(scr, acc[fr][fc], 20, wmma::mem_row_major);
            __syncwarp();
            int rl = lane >> 1, half = lane & 1;
            int grow = rbase + wr + fr * 16 + rl;
            int flocal = wm + fc * 16 + half * 8;
            float vals[8];
            float4 b0 = *(const float4*)&b1_[n * 384 + fbase + flocal];
            float4 b1v = *(const float4*)&b1_[n * 384 + fbase + flocal + 4];
            const float bias[8] = {b0.x, b0.y, b0.z, b0.w, b1v.x, b1v.y, b1v.z, b1v.w};
#pragma unroll
            for (int e = 0; e < 8; ++e)
                vals[e] = gelu_exact(scr[rl * 20 + half * 8 + e] + bias[e]);
            if (ftile == 0) {
                *(uint4*)&g_upreb[((size_t)(grow << 8) + n) * 192 + flocal] = pack8bf(vals);
            } else {
                float* dst = &g_v[((size_t)(grow << 8) + n) * 192 + flocal];
                *(float4*)&dst[0] = make_float4(vals[0], vals[1], vals[2], vals[3]);
                *(float4*)&dst[4] = make_float4(vals[4], vals[5], vals[6], vals[7]);
            }
            __syncwarp();
        }
    }
}

// ---------------------------------------------------------------------------
// K2b: ln3 over u bf16 (HF=192) + transpose -> g_utb[r][c][n] (bf16)
// (R11 proven version: scalar conflict-free staging)
// ---------------------------------------------------------------------------
__global__ __launch_bounds__(256) void k2b_ln3_t(
    const float* __restrict__ ln3g, const float* __restrict__ ln3b)
{
    __shared__ float s[32][193];
    __shared__ float sm[32], sr[32];
    const int t = threadIdx.x;
    const int r = blockIdx.x;
    const int nb = blockIdx.y * 32;
    const __nv_bfloat16* src = g_upreb + (((size_t)r << 8) + nb) * 192;
#pragma unroll
    for (int it = 0; it < 24; ++it) {
        int lin = t + it * 256;
        s[lin / 192][lin % 192] = __bfloat162float(src[lin]);
    }
    __syncthreads();
    const int warp = t >> 5, lane = t & 31;
#pragma unroll
    for (int j = 0; j < 4; ++j) {
        int row = warp * 4 + j;
        float su = 0.f, s2 = 0.f;
#pragma unroll
        for (int k = 0; k < 6; ++k) { float v = s[row][lane + k * 32]; su += v; s2 += v * v; }
#pragma unroll
        for (int off = 16; off > 0; off >>= 1) {
            su += __shfl_xor_sync(0xffffffffu, su, off);
            s2 += __shfl_xor_sync(0xffffffffu, s2, off);
        }
        if (lane == 0) {
            float m = su * (1.f / 192.f);
            sm[row] = m;
            sr[row] = rsqrtf(s2 * (1.f / 192.f) - m * m + 1e-3f);
        }
    }
    __syncthreads();
    const int n_l = t & 31, c0 = t >> 5;
#pragma unroll
    for (int it = 0; it < 24; ++it) {
        int c = c0 + it * 8;
        float v = (s[n_l][c] - sm[n_l]) * sr[n_l] * ln3g[c] + ln3b[c];
        g_utb[((r * 192 + c) << 8) + nb + n_l] = __float2bfloat16(v);
    }
}

// ---------------------------------------------------------------------------
// K3: spatial gating via wmma bf16, cp.async double-buffered.
// raw gate (no bias) -> g_upreb bf16 [r][c][n].
// grid (8 rtiles, 2 mtiles, 192 c) x 256 thr.
// ---------------------------------------------------------------------------
#define K3_LD 40
__global__ __launch_bounds__(256) void k3_wmma()
{
    __shared__ __align__(16) char smemraw[2 * 128 * K3_LD * 2 * 2];
    __nv_bfloat16* sA = (__nv_bfloat16*)smemraw;
    __nv_bfloat16* sB = sA + 2 * 128 * K3_LD;
    const int t = threadIdx.x;
    const int wid = t >> 5, lane = t & 31;
    const int rbase = blockIdx.x * 128;
    const int mbase = blockIdx.y * 128;
    const int c = blockIdx.z;

    const __nv_bfloat16* abase = g_utb + ((size_t)rbase * 192 + c) * 256;
    const __nv_bfloat16* bbase = g_wsgub + ((size_t)c << 16) + (size_t)mbase * 256;

    const int lr = t >> 1;
    const int lk = (t & 1) * 16;

    wmma::fragment<wmma::accumulator, 16, 16, 16, float> acc[2][4];
#pragma unroll
    for (int i = 0; i < 2; ++i)
#pragma unroll
        for (int j = 0; j < 4; ++j)
            wmma::fill_fragment(acc[i][j], 0.0f);

    const int wr = (wid >> 1) * 32;
    const int wm = (wid & 1) * 64;

    {
        const __nv_bfloat16* as = abase + (size_t)lr * (192 * 256) + lk;
        cp16(&sA[lr * K3_LD + lk], as);
        cp16(&sA[lr * K3_LD + lk + 8], as + 8);
        const __nv_bfloat16* bs = bbase + (size_t)lr * 256 + lk;
        cp16(&sB[lr * K3_LD + lk], bs);
        cp16(&sB[lr * K3_LD + lk + 8], bs + 8);
        CP_COMMIT();
    }

#pragma unroll
    for (int kb = 0; kb < 8; ++kb) {
        const int st = kb & 1;
        if (kb < 7) {
            const int kn = (kb + 1) * 32;
            const __nv_bfloat16* as = abase + (size_t)lr * (192 * 256) + kn + lk;
            cp16(&sA[(st ^ 1) * 128 * K3_LD + lr * K3_LD + lk], as);
            cp16(&sA[(st ^ 1) * 128 * K3_LD + lr * K3_LD + lk + 8], as + 8);
            const __nv_bfloat16* bs = bbase + (size_t)lr * 256 + kn + lk;
            cp16(&sB[(st ^ 1) * 128 * K3_LD + lr * K3_LD + lk], bs);
            cp16(&sB[(st ^ 1) * 128 * K3_LD + lr * K3_LD + lk + 8], bs + 8);
            CP_COMMIT();
            CP_WAIT(1);
        } else {
            CP_WAIT(0);
        }
        __syncthreads();

        const __nv_bfloat16* cA = sA + st * 128 * K3_LD;
        const __nv_bfloat16* cB = sB + st * 128 * K3_LD;
#pragma unroll
        for (int kk = 0; kk < 32; kk += 16) {
            wmma::fragment<wmma::matrix_a, 16, 16, 16, __nv_bfloat16, wmma::row_major> fa[2];
            wmma::load_matrix_sync(fa[0], &cA[(wr     ) * K3_LD + kk], K3_LD);
            wmma::load_matrix_sync(fa[1], &cA[(wr + 16) * K3_LD + kk], K3_LD);
#pragma unroll
            for (int j = 0; j < 4; ++j) {
                wmma::fragment<wmma::matrix_b, 16, 16, 16, __nv_bfloat16, wmma::col_major> fb;
                wmma::load_matrix_sync(fb, &cB[(wm + j * 16) * K3_LD + kk], K3_LD);
                wmma::mma_sync(acc[0][j], fa[0], fb, acc[0][j]);
                wmma::mma_sync(acc[1][j], fa[1], fb, acc[1][j]);
            }
        }
        __syncthreads();
    }

    float* scr = (float*)smemraw + wid * 320;
#pragma unroll
    for (int fr = 0; fr < 2; ++fr) {
#pragma unroll
        for (int fc = 0; fc < 4; ++fc) {
            wmma::store_matrix_sync(scr, acc[fr][fc], 20, wmma::mem_row_major);
            __syncwarp();
            int rl = lane >> 1, half = lane & 1;
            int grow = rbase + wr + fr * 16 + rl;
            int m0 = mbase + wm + fc * 16 + half * 8;
            float vals[8];
#pragma unroll
            for (int e = 0; e < 8; ++e) vals[e] = scr[rl * 20 + half * 8 + e];
            *(uint4*)&g_upreb[((size_t)grow * 192 + c) * 256 + m0] = pack8bf(vals);
            __syncwarp();
        }
    }
}

// ---------------------------------------------------------------------------
// K3b: uv[r][n][c] = (gate_bf16[r][c][n] + bsgu[c][n]) * v[r][n][c]
// ---------------------------------------------------------------------------
__global__ __launch_bounds__(256) void k3b_gate_mul(const float* __restrict__ bsgu)
{
    __shared__ float s[32][33];
    const int t = threadIdx.x;
    const int r = blockIdx.x;
    const int nb = blockIdx.y * 32;
    const int cb = blockIdx.z * 32;
    {
        const int cc = t >> 3, n0 = (t & 7) * 4;
        union { uint2 raw; __nv_bfloat16 h[4]; } gt;
        gt.raw = *(const uint2*)&g_upreb[((size_t)(r * 192 + cb + cc) << 8) + nb + n0];
        float4 bs = *(const float4*)&bsgu[((cb + cc) << 8) + nb + n0];
        s[cc][n0 + 0] = __bfloat162float(gt.h[0]) + bs.x;
        s[cc][n0 + 1] = __bfloat162float(gt.h[1]) + bs.y;
        s[cc][n0 + 2] = __bfloat162float(gt.h[2]) + bs.z;
        s[cc][n0 + 3] = __bfloat162float(gt.h[3]) + bs.w;
    }
    __syncthreads();
    {
        const int nn = t >> 3, c4 = (t & 7) * 4;
        int idx = (((r << 8) + nb + nn) * 192) + cb + c4;
        float4 vv = *(const float4*)&g_v[idx];
        float4 o = make_float4(s[c4 + 0][nn] * vv.x, s[c4 + 1][nn] * vv.y,
                               s[c4 + 2][nn] * vv.z, s[c4 + 3][nn] * vv.w);
        *(float4*)&g_ut[idx] = o;
    }
}

// ---------------------------------------------------------------------------
// K4: tf32 wmma (RN), cp.async double-buffered: z = uv @ W2[n] + b2[n] +
// bufin, fused recon/concat/residual epilogue.
// A row-major [128][20], B [16][68], 2 stages. grid (8 rtiles, 256 n) x 256.
// ---------------------------------------------------------------------------
#define K4_LDA 20
#define K4_LDB 68
__global__ __launch_bounds__(256) void k4_gmlp_out(
    const float* __restrict__ W2, const float* __restrict__ b2_,
    const float* __restrict__ x, float* __restrict__ out,
    float* __restrict__ gout, int write_glob)
{
    __shared__ __align__(16) float smemf[2 * 128 * K4_LDA + 2 * 16 * K4_LDB];
    float* sA = smemf;                       // [2][128][K4_LDA]
    float* sB = smemf + 2 * 128 * K4_LDA;    // [2][16][K4_LDB]
    const int t = threadIdx.x;
    const int wid = t >> 5, lane = t & 31;
    const int rbase = blockIdx.x * 128;
    const int n = blockIdx.y;

    const int wr = (wid >> 1) * 32;
    const int wm = (wid & 1) * 32;
    wmma::fragment<wmma::accumulator, 16, 16, 8, float> acc[2][2];
#pragma unroll
    for (int i = 0; i < 2; ++i)
#pragma unroll
        for (int j = 0; j < 2; ++j) wmma::fill_fragment(acc[i][j], 0.0f);

    const int ar = t >> 1, ak = (t & 1) * 8;      // A loader: 2 thr/row, 8 floats each
    const float* asrc = g_ut + ((size_t)((rbase + ar) << 8) + n) * 192;
    const int bk = t >> 4, bf4 = (t & 15) * 4;    // B loader
    const float* bsrc = W2 + (size_t)n * 192 * 64;

    // prefetch stage 0
    cp16(&sA[ar * K4_LDA + ak], asrc + ak);
    cp16(&sA[ar * K4_LDA + ak + 4], asrc + ak + 4);
    cp16(&sB[bk * K4_LDB + bf4], bsrc + bk * 64 + bf4);
    CP_COMMIT();

#pragma unroll
    for (int s = 0; s < 12; ++s) {
        const int st = s & 1;
        if (s < 11) {
            const int kn = (s + 1) * 16;
            float* dA = sA + (st ^ 1) * 128 * K4_LDA;
            cp16(&dA[ar * K4_LDA + ak], asrc + kn + ak);
            cp16(&dA[ar * K4_LDA + ak + 4], asrc + kn + ak + 4);
            float* dB = sB + (st ^ 1) * 16 * K4_LDB;
            cp16(&dB[bk * K4_LDB + bf4], bsrc + (kn + bk) * 64 + bf4);
            CP_COMMIT();
            CP_WAIT(1);
        } else {
            CP_WAIT(0);
        }
        __syncthreads();

        const float* cA = sA + st * 128 * K4_LDA;
        const float* cB = sB + st * 16 * K4_LDB;
#pragma unroll
        for (int kk = 0; kk < 2; ++kk) {
            wmma::fragment<wmma::matrix_a, 16, 16, 8, wmma::precision::tf32, wmma::row_major> fa[2];
#pragma unroll
            for (int fr = 0; fr < 2; ++fr) {
                wmma::load_matrix_sync(fa[fr], &cA[(wr + fr * 16) * K4_LDA + kk * 8], K4_LDA);
#pragma unroll
                for (int e = 0; e < fa[fr].num_elements; ++e)
                    fa[fr].x[e] = wmma::__float_to_tf32(fa[fr].x[e]);
            }
#pragma unroll
            for (int fc = 0; fc < 2; ++fc) {
                wmma::fragment<wmma::matrix_b, 16, 16, 8, wmma::precision::tf32, wmma::row_major> fb;
                wmma::load_matrix_sync(fb, &cB[(kk * 8) * K4_LDB + wm + fc * 16], K4_LDB);
#pragma unroll
                for (int e = 0; e < fb.num_elements; ++e)
                    fb.x[e] = wmma::__float_to_tf32(fb.x[e]);
                wmma::mma_sync(acc[0][fc], fa[0], fb, acc[0][fc]);
                wmma::mma_sync(acc[1][fc], fa[1], fb, acc[1][fc]);
            }
        }
        __syncthreads();
    }

    float* scr = smemf + wid * 320;
#pragma unroll
    for (int fr = 0; fr < 2; ++fr) {
#pragma unroll
        for (int fc = 0; fc < 2; ++fc) {
            wmma::store_matrix_sync(scr, acc[fr][fc], 20, wmma::mem_row_major);
            __syncwarp();
            int rl = lane >> 1, half = lane & 1;
            int grow = rbase + wr + fr * 16 + rl;
            int f0 = wm + fc * 16 + half * 8;
            int idx = (((grow << 8) + n) << 6) + f0;
            float4 b0 = *(const float4*)&b2_[(n << 6) + f0];
            float4 b1v = *(const float4*)&b2_[(n << 6) + f0 + 4];
            float4 i0 = *(const float4*)&g_bufin[idx];
            float4 i1 = *(const float4*)&g_bufin[idx + 4];
            float z[8];
            z[0] = scr[rl * 20 + half * 8 + 0] + b0.x + i0.x;
            z[1] = scr[rl * 20 + half * 8 + 1] + b0.y + i0.y;
            z[2] = scr[rl * 20 + half * 8 + 2] + b0.z + i0.z;
            z[3] = scr[rl * 20 + half * 8 + 3] + b0.w + i0.w;
            z[4] = scr[rl * 20 + half * 8 + 4] + b1v.x + i1.x;
            z[5] = scr[rl * 20 + half * 8 + 5] + b1v.y + i1.y;
            z[6] = scr[rl * 20 + half * 8 + 6] + b1v.z + i1.z;
            z[7] = scr[rl * 20 + half * 8 + 7] + b1v.w + i1.w;

            const int branch = grow >> 9;
            const int b = (grow >> 8) & 1;
            const int g = grow & 255;
            int h, w;
            if (branch == 0) { h = ((n >> 4) << 4) | (g >> 4); w = ((n & 15) << 4) | (g & 15); }
            else             { h = ((g >> 4) << 4) | (n >> 4); w = ((g & 15) << 4) | (n & 15); }
            const int pix = (b << 16) | (h << 8) | w;
            const int obase = pix * 128 + branch * 64 + f0;
            float4 x0 = *(const float4*)&x[obase];
            float4 x1 = *(const float4*)&x[obase + 4];
            *(float4*)&out[obase]     = make_float4(z[0] + x0.x, z[1] + x0.y,
                                                    z[2] + x0.z, z[3] + x0.w);
            *(float4*)&out[obase + 4] = make_float4(z[4] + x1.x, z[5] + x1.y,
                                                    z[6] + x1.z, z[7] + x1.w);
            if (branch && write_glob) {
                *(float4*)&gout[pix * 64 + f0]     = make_float4(z[0], z[1], z[2], z[3]);
                *(float4*)&gout[pix * 64 + f0 + 4] = make_float4(z[4], z[5], z[6], z[7]);
            }
            __syncwarp();
        }
    }
}

// ---------------------------------------------------------------------------
extern "C" void kernel_launch(void* const* d_in, const int* in_sizes, int n_in,
                              void* d_out, int out_size)
{
    const float* x    = (const float*)d_in[0];
    const float* ln1g = (const float*)d_in[1];
    const float* ln1b = (const float*)d_in[2];
    const float* Wp   = (const float*)d_in[3];
    const float* bp   = (const float*)d_in[4];
    const float* ln2g = (const float*)d_in[5];
    const float* ln2b = (const float*)d_in[6];
    const float* W1   = (const float*)d_in[7];
    const float* b1   = (const float*)d_in[8];
    const float* ln3g = (const float*)d_in[9];
    const float* ln3b = (const float*)d_in[10];
    const float* Wsgu = (const float*)d_in[11];
    const float* bsgu = (const float*)d_in[12];
    const float* W2   = (const float*)d_in[13];
    const float* b2   = (const float*)d_in[14];

    float* out = (float*)d_out;
    const int OUT_MAIN = 2 * 256 * 256 * 128;
    const int OUT_GLOB = 2 * 256 * 256 * 64;
    int write_glob = (out_size >= OUT_MAIN + OUT_GLOB) ? 1 : 0;
    float* gout = out + OUT_MAIN;

    static int configured = 0;
    if (!configured) {
        cudaFuncSetAttribute(k1_ln_proj,
            cudaFuncAttributeMaxDynamicSharedMemorySize, K1_SMEM);
        configured = 1;
    }

    k0_wsgu_t    <<<dim3(8, 8, 192), dim3(32, 8)>>>(Wsgu);
    k1_ln_proj   <<<1024, 256, K1_SMEM>>>(x, ln1g, ln1b, Wp, bp);
    k2_gmlp_in   <<<dim3(2, 8, 256), 256>>>(W1, b1, ln2g, ln2b);
    k2b_ln3_t    <<<dim3(1024, 8, 1), 256>>>(ln3g, ln3b);
    k3_wmma      <<<dim3(8, 2, 192), 256>>>();
    k3b_gate_mul <<<dim3(1024, 8, 6), 256>>>(bsgu);
    k4_gmlp_out  <<<dim3(8, 256, 1), 256>>>(W2, b2, x, out, gout, write_glob);
}

// round 15
// speedup vs baseline: 1.6846x; 1.0400x over previous
#include <cuda_runtime.h>
#include <cuda_bf16.h>
#include <mma.h>
#include <math.h>
#include <cstdint>

using namespace nvcuda;

// ---------------------------------------------------------------------------
// Shapes: B=2, H=W=256, C=128, S=16 -> G=256, N=256, CI=64, F1=384, HF=192
// R = 2 branches * B * G = 1024
// ---------------------------------------------------------------------------
#define R_TOT   1024
#define NPATCH  256
#define CI_DIM  64
#define HF_DIM  192

__device__ float  g_bufin[R_TOT * NPATCH * CI_DIM];   // blocked gmlp input (fp32)
__device__ float2 g_stat [R_TOT * NPATCH];            // ln2 (mean, rstd) per (r,n)
__device__ float  g_v    [R_TOT * NPATCH * HF_DIM];   // v (fp32)
__device__ float  g_ut   [R_TOT * HF_DIM * NPATCH];   // uv [R][N][HF] (fp32)
__device__ __align__(16) __nv_bfloat16 g_upreb [R_TOT * NPATCH * HF_DIM]; // u bf16; later raw gate [r][c][n]
__device__ __align__(16) __nv_bfloat16 g_utb   [R_TOT * HF_DIM * NPATCH]; // ln3'd u^T bf16
__device__ __align__(16) __nv_bfloat16 g_wsgub [HF_DIM * NPATCH * NPATCH];// Wsgu^T bf16 [c][m][k]

__device__ __forceinline__ float gelu_exact(float x) {
    return 0.5f * x * (1.0f + erff(x * 0.7071067811865476f));
}

// ---- cp.async helpers ----
__device__ __forceinline__ void cp16(void* smem_dst, const void* gsrc) {
    uint32_t d = (uint32_t)__cvta_generic_to_shared(smem_dst);
    asm volatile("cp.async.cg.shared.global [%0], [%1], 16;"
                 :: "r"(d), "l"(gsrc) : "memory");
}
#define CP_COMMIT()  asm volatile("cp.async.commit_group;" ::: "memory")
#define CP_WAIT(n)   asm volatile("cp.async.wait_group %0;" :: "n"(n) : "memory")

__device__ __forceinline__ uint4 pack8bf(const float* v) {
    union { __nv_bfloat16 h[8]; uint4 u; } r;
#pragma unroll
    for (int i = 0; i < 8; ++i) r.h[i] = __float2bfloat16(v[i]);
    return r.u;
}

// ---------------------------------------------------------------------------
// K0: Wsgu [c][n][m] fp32 -> g_wsgub [c][m][n] bf16
// ---------------------------------------------------------------------------
__global__ __launch_bounds__(256) void k0_wsgu_t(const float* __restrict__ Wsgu)
{
    __shared__ float tile[32][33];
    const int c  = blockIdx.z;
    const int mb = blockIdx.x * 32;
    const int nb = blockIdx.y * 32;
    const int tx = threadIdx.x, ty = threadIdx.y;
#pragma unroll
    for (int j = 0; j < 4; ++j) {
        int n = ty + j * 8;
        tile[n][tx] = Wsgu[(((size_t)c << 8) + nb + n) * 256 + mb + tx];
    }
    __syncthreads();
#pragma unroll
    for (int j = 0; j < 4; ++j) {
        int m = ty + j * 8;
        g_wsgub[(((size_t)c << 8) + mb + m) * 256 + nb + tx] =
            __float2bfloat16(tile[tx][m]);
    }
}

// ---------------------------------------------------------------------------
// K1: tf32 wmma (RN): ln1 + Dense(W_proj) + GELU, scatter blocked + ln2 stats
// grid 1024 x 256 thr; 128 pixels/CTA; block 128x128, K=128.
// ---------------------------------------------------------------------------
#define K1_SMEM ((128 * 128 + 16 * 128) * 4)
__global__ __launch_bounds__(256) void k1_ln_proj(
    const float* __restrict__ x, const float* __restrict__ ln1g,
    const float* __restrict__ ln1b, const float* __restrict__ Wp,
    const float* __restrict__ bp)
{
    extern __shared__ float dsm[];
    float* sA = dsm;                 // [c][row] 128x128
    float* sB = dsm + 128 * 128;     // [k][f]   16x128
    __shared__ float sg[128], sb[128];
    const int t = threadIdx.x;
    const int wid = t >> 5, lane = t & 31;
    const int pbase = blockIdx.x * 128;

    if (t < 128) { sg[t] = ln1g[t]; sb[t] = ln1b[t]; }
    __syncthreads();

    {
        const int row = t >> 1, half = t & 1;
        const float* src = x + (size_t)(pbase + row) * 128 + half * 64;
        float4 v[16];
        float s = 0.f, s2 = 0.f;
#pragma unroll
        for (int j = 0; j < 16; ++j) {
            v[j] = *(const float4*)&src[j * 4];
            s  += v[j].x + v[j].y + v[j].z + v[j].w;
            s2 += v[j].x * v[j].x + v[j].y * v[j].y + v[j].z * v[j].z + v[j].w * v[j].w;
        }
        s  += __shfl_xor_sync(0xffffffffu, s,  1);
        s2 += __shfl_xor_sync(0xffffffffu, s2, 1);
        float m  = s * (1.f / 128.f);
        float rs = rsqrtf(s2 * (1.f / 128.f) - m * m + 1e-3f);
#pragma unroll
        for (int j = 0; j < 16; ++j) {
            int c = half * 64 + j * 4;
            sA[(c + 0) * 128 + row] = (v[j].x - m) * rs * sg[c + 0] + sb[c + 0];
            sA[(c + 1) * 128 + row] = (v[j].y - m) * rs * sg[c + 1] + sb[c + 1];
            sA[(c + 2) * 128 + row] = (v[j].z - m) * rs * sg[c + 2] + sb[c + 2];
            sA[(c + 3) * 128 + row] = (v[j].w - m) * rs * sg[c + 3] + sb[c + 3];
        }
    }

    const int wr = (wid >> 1) * 32;
    const int wm = (wid & 1) * 64;
    wmma::fragment<wmma::accumulator, 16, 16, 8, float> acc[2][4];
#pragma unroll
    for (int i = 0; i < 2; ++i)
#pragma unroll
        for (int j = 0; j < 4; ++j) wmma::fill_fragment(acc[i][j], 0.0f);

    const int bk = t >> 4, bf8 = (t & 15) * 8;
    float4 rB0 = *(const float4*)&Wp[bk * 128 + bf8];
    float4 rB1 = *(const float4*)&Wp[bk * 128 + bf8 + 4];

    for (int s = 0; s < 8; ++s) {
        __syncthreads();
        *(float4*)&sB[bk * 128 + bf8]     = rB0;
        *(float4*)&sB[bk * 128 + bf8 + 4] = rB1;
        __syncthreads();
        if (s < 7) {
            rB0 = *(const float4*)&Wp[((s + 1) * 16 + bk) * 128 + bf8];
            rB1 = *(const float4*)&Wp[((s + 1) * 16 + bk) * 128 + bf8 + 4];
        }
#pragma unroll
        for (int kk = 0; kk < 2; ++kk) {
            wmma::fragment<wmma::matrix_a, 16, 16, 8, wmma::precision::tf32, wmma::col_major> fa[2];
#pragma unroll
            for (int fr = 0; fr < 2; ++fr) {
                wmma::load_matrix_sync(fa[fr], &sA[(s * 16 + kk * 8) * 128 + wr + fr * 16], 128);
#pragma unroll
                for (int e = 0; e < fa[fr].num_elements; ++e)
                    fa[fr].x[e] = wmma::__float_to_tf32(fa[fr].x[e]);
            }
#pragma unroll
            for (int fc = 0; fc < 4; ++fc) {
                wmma::fragment<wmma::matrix_b, 16, 16, 8, wmma::precision::tf32, wmma::row_major> fb;
                wmma::load_matrix_sync(fb, &sB[(kk * 8) * 128 + wm + fc * 16], 128);
#pragma unroll
                for (int e = 0; e < fb.num_elements; ++e)
                    fb.x[e] = wmma::__float_to_tf32(fb.x[e]);
                wmma::mma_sync(acc[0][fc], fa[0], fb, acc[0][fc]);
                wmma::mma_sync(acc[1][fc], fa[1], fb, acc[1][fc]);
            }
        }
    }
    __syncthreads();

    float* scr = dsm + wid * 320;
    const int branch = wm >> 6;
#pragma unroll
    for (int fr = 0; fr < 2; ++fr) {
        const int rl = lane >> 1, half = lane & 1;
        const int p = pbase + wr + fr * 16 + rl;
        const int b = p >> 16, h = (p >> 8) & 255, w = p & 255;
        const int g  = ((h >> 4) << 4) | (w >> 4);
        const int nn = ((h & 15) << 4) | (w & 15);
        const int r = branch * 512 + (b << 8) + g;
        float ss = 0.f, ss2 = 0.f;
#pragma unroll
        for (int fc = 0; fc < 4; ++fc) {
            wmma::store_matrix_sync(scr, acc[fr][fc], 20, wmma::mem_row_major);
            __syncwarp();
            const int f0 = wm + fc * 16 + half * 8;
            float4 b0 = *(const float4*)&bp[f0];
            float4 b1 = *(const float4*)&bp[f0 + 4];
            const float bias[8] = {b0.x, b0.y, b0.z, b0.w, b1.x, b1.y, b1.z, b1.w};
            float vals[8];
#pragma unroll
            for (int e = 0; e < 8; ++e) {
                vals[e] = gelu_exact(scr[rl * 20 + half * 8 + e] + bias[e]);
                ss += vals[e]; ss2 += vals[e] * vals[e];
            }
            const int cloc = f0 & 63;
            float* dst = &g_bufin[((size_t)(r << 8) + nn) * 64 + cloc];
            *(float4*)&dst[0] = make_float4(vals[0], vals[1], vals[2], vals[3]);
            *(float4*)&dst[4] = make_float4(vals[4], vals[5], vals[6], vals[7]);
            __syncwarp();
        }
        ss  += __shfl_xor_sync(0xffffffffu, ss,  1);
        ss2 += __shfl_xor_sync(0xffffffffu, ss2, 1);
        if ((lane & 1) == 0) {
            float m  = ss * (1.f / 64.f);
            float rs = rsqrtf(ss2 * (1.f / 64.f) - m * m + 1e-3f);
            g_stat[(r << 8) + nn] = make_float2(m, rs);
        }
    }
}

// ---------------------------------------------------------------------------
// K2: tf32 wmma (RN): y = gelu(ln2(bufin) @ W1[n] + b1[n]), FULL 384 f in
// one pass (A read once). Block 64 rows x 384 f, K=64 resident.
// grid (16 rtiles, 256 n) x 256 thr. Warps 2x4, warp tile 32x96, acc[2][6].
// u (f<192) -> bf16, v (f>=192) -> fp32; per-warp routing is uniform.
// ---------------------------------------------------------------------------
#define K2_LDA 68
#define K2_LDB 392
__global__ __launch_bounds__(256) void k2_gmlp_in(
    const float* __restrict__ W1, const float* __restrict__ b1_,
    const float* __restrict__ ln2g, const float* __restrict__ ln2b)
{
    __shared__ float sA[64 * K2_LDA];   // [k][row]; reused as epilogue scratch
    __shared__ float sB[16 * K2_LDB];   // [k][f]
    __shared__ float sg[64], sb[64];
    const int t = threadIdx.x;
    const int wid = t >> 5, lane = t & 31;
    const int rbase = blockIdx.x * 64;
    const int n = blockIdx.y;

    if (t < 64) { sg[t] = ln2g[t]; sb[t] = ln2b[t]; }
    __syncthreads();

    // A load + ln2 (4 threads/row, 16 k each)
    {
        const int row = t >> 2, q = t & 3;
        const float* src = g_bufin + ((size_t)((rbase + row) << 8) + n) * 64;
        float2 st = g_stat[((rbase + row) << 8) + n];
#pragma unroll
        for (int j = 0; j < 4; ++j) {
            int k = q * 16 + j * 4;
            float4 v = *(const float4*)&src[k];
            sA[(k + 0) * K2_LDA + row] = (v.x - st.x) * st.y * sg[k + 0] + sb[k + 0];
            sA[(k + 1) * K2_LDA + row] = (v.y - st.x) * st.y * sg[k + 1] + sb[k + 1];
            sA[(k + 2) * K2_LDA + row] = (v.z - st.x) * st.y * sg[k + 2] + sb[k + 2];
            sA[(k + 3) * K2_LDA + row] = (v.w - st.x) * st.y * sg[k + 3] + sb[k + 3];
        }
    }

    const int wr = (wid >> 2) * 32;    // warp rows (2 groups)
    const int wm = (wid & 3) * 96;     // warp f (4 groups x 96)
    wmma::fragment<wmma::accumulator, 16, 16, 8, float> acc[2][6];
#pragma unroll
    for (int i = 0; i < 2; ++i)
#pragma unroll
        for (int j = 0; j < 6; ++j) wmma::fill_fragment(acc[i][j], 0.0f);

    const float* Wn = W1 + (size_t)n * 64 * 384;
    const int bk = t >> 4, bf4 = (t & 15) * 4;   // 16 k-rows x 6 chunks of 64
    float4 rB[6];
#pragma unroll
    for (int j = 0; j < 6; ++j)
        rB[j] = *(const float4*)&Wn[bk * 384 + j * 64 + bf4];

    for (int s = 0; s < 4; ++s) {
        __syncthreads();
#pragma unroll
        for (int j = 0; j < 6; ++j)
            *(float4*)&sB[bk * K2_LDB + j * 64 + bf4] = rB[j];
        __syncthreads();
        if (s < 3) {
#pragma unroll
            for (int j = 0; j < 6; ++j)
                rB[j] = *(const float4*)&Wn[((s + 1) * 16 + bk) * 384 + j * 64 + bf4];
        }
#pragma unroll
        for (int kk = 0; kk < 2; ++kk) {
            wmma::fragment<wmma::matrix_a, 16, 16, 8, wmma::precision::tf32, wmma::col_major> fa[2];
#pragma unroll
            for (int fr = 0; fr < 2; ++fr) {
                wmma::load_matrix_sync(fa[fr], &sA[(s * 16 + kk * 8) * K2_LDA + wr + fr * 16], K2_LDA);
#pragma unroll
                for (int e = 0; e < fa[fr].num_elements; ++e)
                    fa[fr].x[e] = wmma::__float_to_tf32(fa[fr].x[e]);
            }
#pragma unroll
            for (int fc = 0; fc < 6; ++fc) {
                wmma::fragment<wmma::matrix_b, 16, 16, 8, wmma::precision::tf32, wmma::row_major> fb;
                wmma::load_matrix_sync(fb, &sB[(kk * 8) * K2_LDB + wm + fc * 16], K2_LDB);
#pragma unroll
                for (int e = 0; e < fb.num_elements; ++e)
                    fb.x[e] = wmma::__float_to_tf32(fb.x[e]);
                wmma::mma_sync(acc[0][fc], fa[0], fb, acc[0][fc]);
                wmma::mma_sync(acc[1][fc], fa[1], fb, acc[1][fc]);
            }
        }
    }
    __syncthreads();

    float* scr = sA + wid * 320;
#pragma unroll
    for (int fr = 0; fr < 2; ++fr) {
#pragma unroll
        for (int fc = 0; fc < 6; ++fc) {
            wmma::store_matrix_sync(scr, acc[fr][fc], 20, wmma::mem_row_major);
            __syncwarp();
            int rl = lane >> 1, half = lane & 1;
            int grow = rbase + wr + fr * 16 + rl;
            int f0 = wm + fc * 16 + half * 8;        // 0..383
            float vals[8];
            float4 b0 = *(const float4*)&b1_[n * 384 + f0];
            float4 b1v = *(const float4*)&b1_[n * 384 + f0 + 4];
            const float bias[8] = {b0.x, b0.y, b0.z, b0.w, b1v.x, b1v.y, b1v.z, b1v.w};
#pragma unroll
            for (int e = 0; e < 8; ++e)
                vals[e] = gelu_exact(scr[rl * 20 + half * 8 + e] + bias[e]);
            if (f0 < 192) {
                *(uint4*)&g_upreb[((size_t)(grow << 8) + n) * 192 + f0] = pack8bf(vals);
            } else {
                int fo = f0 - 192;
                float* dst = &g_v[((size_t)(grow << 8) + n) * 192 + fo];
                *(float4*)&dst[0] = make_float4(vals[0], vals[1], vals[2], vals[3]);
                *(float4*)&dst[4] = make_float4(vals[4], vals[5], vals[6], vals[7]);
            }
            __syncwarp();
        }
    }
}

// ---------------------------------------------------------------------------
// K2b: ln3 over u bf16 (HF=192) + transpose -> g_utb[r][c][n] (bf16)
// ---------------------------------------------------------------------------
__global__ __launch_bounds__(256) void k2b_ln3_t(
    const float* __restrict__ ln3g, const float* __restrict__ ln3b)
{
    __shared__ float s[32][193];
    __shared__ float sm[32], sr[32];
    const int t = threadIdx.x;
    const int r = blockIdx.x;
    const int nb = blockIdx.y * 32;
    const __nv_bfloat16* src = g_upreb + (((size_t)r << 8) + nb) * 192;
#pragma unroll
    for (int it = 0; it < 24; ++it) {
        int lin = t + it * 256;
        s[lin / 192][lin % 192] = __bfloat162float(src[lin]);
    }
    __syncthreads();
    const int warp = t >> 5, lane = t & 31;
#pragma unroll
    for (int j = 0; j < 4; ++j) {
        int row = warp * 4 + j;
        float su = 0.f, s2 = 0.f;
#pragma unroll
        for (int k = 0; k < 6; ++k) { float v = s[row][lane + k * 32]; su += v; s2 += v * v; }
#pragma unroll
        for (int off = 16; off > 0; off >>= 1) {
            su += __shfl_xor_sync(0xffffffffu, su, off);
            s2 += __shfl_xor_sync(0xffffffffu, s2, off);
        }
        if (lane == 0) {
            float m = su * (1.f / 192.f);
            sm[row] = m;
            sr[row] = rsqrtf(s2 * (1.f / 192.f) - m * m + 1e-3f);
        }
    }
    __syncthreads();
    const int n_l = t & 31, c0 = t >> 5;
#pragma unroll
    for (int it = 0; it < 24; ++it) {
        int c = c0 + it * 8;
        float v = (s[n_l][c] - sm[n_l]) * sr[n_l] * ln3g[c] + ln3b[c];
        g_utb[((r * 192 + c) << 8) + nb + n_l] = __float2bfloat16(v);
    }
}

// ---------------------------------------------------------------------------
// K3: spatial gating via wmma bf16, cp.async double-buffered.
// raw gate (no bias) -> g_upreb bf16 [r][c][n].
// grid (8 rtiles, 2 mtiles, 192 c) x 256 thr.
// ---------------------------------------------------------------------------
#define K3_LD 40
__global__ __launch_bounds__(256) void k3_wmma()
{
    __shared__ __align__(16) char smemraw[2 * 128 * K3_LD * 2 * 2];
    __nv_bfloat16* sA = (__nv_bfloat16*)smemraw;
    __nv_bfloat16* sB = sA + 2 * 128 * K3_LD;
    const int t = threadIdx.x;
    const int wid = t >> 5, lane = t & 31;
    const int rbase = blockIdx.x * 128;
    const int mbase = blockIdx.y * 128;
    const int c = blockIdx.z;

    const __nv_bfloat16* abase = g_utb + ((size_t)rbase * 192 + c) * 256;
    const __nv_bfloat16* bbase = g_wsgub + ((size_t)c << 16) + (size_t)mbase * 256;

    const int lr = t >> 1;
    const int lk = (t & 1) * 16;

    wmma::fragment<wmma::accumulator, 16, 16, 16, float> acc[2][4];
#pragma unroll
    for (int i = 0; i < 2; ++i)
#pragma unroll
        for (int j = 0; j < 4; ++j)
            wmma::fill_fragment(acc[i][j], 0.0f);

    const int wr = (wid >> 1) * 32;
    const int wm = (wid & 1) * 64;

    {
        const __nv_bfloat16* as = abase + (size_t)lr * (192 * 256) + lk;
        cp16(&sA[lr * K3_LD + lk], as);
        cp16(&sA[lr * K3_LD + lk + 8], as + 8);
        const __nv_bfloat16* bs = bbase + (size_t)lr * 256 + lk;
        cp16(&sB[lr * K3_LD + lk], bs);
        cp16(&sB[lr * K3_LD + lk + 8], bs + 8);
        CP_COMMIT();
    }

#pragma unroll
    for (int kb = 0; kb < 8; ++kb) {
        const int st = kb & 1;
        if (kb < 7) {
            const int kn = (kb + 1) * 32;
            const __nv_bfloat16* as = abase + (size_t)lr * (192 * 256) + kn + lk;
            cp16(&sA[(st ^ 1) * 128 * K3_LD + lr * K3_LD + lk], as);
            cp16(&sA[(st ^ 1) * 128 * K3_LD + lr * K3_LD + lk + 8], as + 8);
            const __nv_bfloat16* bs = bbase + (size_t)lr * 256 + kn + lk;
            cp16(&sB[(st ^ 1) * 128 * K3_LD + lr * K3_LD + lk], bs);
            cp16(&sB[(st ^ 1) * 128 * K3_LD + lr * K3_LD + lk + 8], bs + 8);
            CP_COMMIT();
            CP_WAIT(1);
        } else {
            CP_WAIT(0);
        }
        __syncthreads();

        const __nv_bfloat16* cA = sA + st * 128 * K3_LD;
        const __nv_bfloat16* cB = sB + st * 128 * K3_LD;
#pragma unroll
        for (int kk = 0; kk < 32; kk += 16) {
            wmma::fragment<wmma::matrix_a, 16, 16, 16, __nv_bfloat16, wmma::row_major> fa[2];
            wmma::load_matrix_sync(fa[0], &cA[(wr     ) * K3_LD + kk], K3_LD);
            wmma::load_matrix_sync(fa[1], &cA[(wr + 16) * K3_LD + kk], K3_LD);
#pragma unroll
            for (int j = 0; j < 4; ++j) {
                wmma::fragment<wmma::matrix_b, 16, 16, 16, __nv_bfloat16, wmma::col_major> fb;
                wmma::load_matrix_sync(fb, &cB[(wm + j * 16) * K3_LD + kk], K3_LD);
                wmma::mma_sync(acc[0][j], fa[0], fb, acc[0][j]);
                wmma::mma_sync(acc[1][j], fa[1], fb, acc[1][j]);
            }
        }
        __syncthreads();
    }

    float* scr = (float*)smemraw + wid * 320;
#pragma unroll
    for (int fr = 0; fr < 2; ++fr) {
#pragma unroll
        for (int fc = 0; fc < 4; ++fc) {
            wmma::store_matrix_sync(scr, acc[fr][fc], 20, wmma::mem_row_major);
            __syncwarp();
            int rl = lane >> 1, half = lane & 1;
            int grow = rbase + wr + fr * 16 + rl;
            int m0 = mbase + wm + fc * 16 + half * 8;
            float vals[8];
#pragma unroll
            for (int e = 0; e < 8; ++e) vals[e] = scr[rl * 20 + half * 8 + e];
            *(uint4*)&g_upreb[((size_t)grow * 192 + c) * 256 + m0] = pack8bf(vals);
            __syncwarp();
        }
    }
}

// ---------------------------------------------------------------------------
// K3b: uv[r][n][c] = (gate_bf16[r][c][n] + bsgu[c][n]) * v[r][n][c]
// ---------------------------------------------------------------------------
__global__ __launch_bounds__(256) void k3b_gate_mul(const float* __restrict__ bsgu)
{
    __shared__ float s[32][33];
    const int t = threadIdx.x;
    const int r = blockIdx.x;
    const int nb = blockIdx.y * 32;
    const int cb = blockIdx.z * 32;
    {
        const int cc = t >> 3, n0 = (t & 7) * 4;
        union { uint2 raw; __nv_bfloat16 h[4]; } gt;
        gt.raw = *(const uint2*)&g_upreb[((size_t)(r * 192 + cb + cc) << 8) + nb + n0];
        float4 bs = *(const float4*)&bsgu[((cb + cc) << 8) + nb + n0];
        s[cc][n0 + 0] = __bfloat162float(gt.h[0]) + bs.x;
        s[cc][n0 + 1] = __bfloat162float(gt.h[1]) + bs.y;
        s[cc][n0 + 2] = __bfloat162float(gt.h[2]) + bs.z;
        s[cc][n0 + 3] = __bfloat162float(gt.h[3]) + bs.w;
    }
    __syncthreads();
    {
        const int nn = t >> 3, c4 = (t & 7) * 4;
        int idx = (((r << 8) + nb + nn) * 192) + cb + c4;
        float4 vv = *(const float4*)&g_v[idx];
        float4 o = make_float4(s[c4 + 0][nn] * vv.x, s[c4 + 1][nn] * vv.y,
                               s[c4 + 2][nn] * vv.z, s[c4 + 3][nn] * vv.w);
        *(float4*)&g_ut[idx] = o;
    }
}

// ---------------------------------------------------------------------------
// K4: tf32 wmma (RN), cp.async double-buffered: z = uv @ W2[n] + b2[n] +
// bufin, fused recon/concat/residual epilogue.
// ---------------------------------------------------------------------------
#define K4_LDA 20
#define K4_LDB 68
__global__ __launch_bounds__(256) void k4_gmlp_out(
    const float* __restrict__ W2, const float* __restrict__ b2_,
    const float* __restrict__ x, float* __restrict__ out,
    float* __restrict__ gout, int write_glob)
{
    __shared__ __align__(16) float smemf[2 * 128 * K4_LDA + 2 * 16 * K4_LDB];
    float* sA = smemf;
    float* sB = smemf + 2 * 128 * K4_LDA;
    const int t = threadIdx.x;
    const int wid = t >> 5, lane = t & 31;
    const int rbase = blockIdx.x * 128;
    const int n = blockIdx.y;

    const int wr = (wid >> 1) * 32;
    const int wm = (wid & 1) * 32;
    wmma::fragment<wmma::accumulator, 16, 16, 8, float> acc[2][2];
#pragma unroll
    for (int i = 0; i < 2; ++i)
#pragma unroll
        for (int j = 0; j < 2; ++j) wmma::fill_fragment(acc[i][j], 0.0f);

    const int ar = t >> 1, ak = (t & 1) * 8;
    const float* asrc = g_ut + ((size_t)((rbase + ar) << 8) + n) * 192;
    const int bk = t >> 4, bf4 = (t & 15) * 4;
    const float* bsrc = W2 + (size_t)n * 192 * 64;

    cp16(&sA[ar * K4_LDA + ak], asrc + ak);
    cp16(&sA[ar * K4_LDA + ak + 4], asrc + ak + 4);
    cp16(&sB[bk * K4_LDB + bf4], bsrc + bk * 64 + bf4);
    CP_COMMIT();

#pragma unroll
    for (int s = 0; s < 12; ++s) {
        const int st = s & 1;
        if (s < 11) {
            const int kn = (s + 1) * 16;
            float* dA = sA + (st ^ 1) * 128 * K4_LDA;
            cp16(&dA[ar * K4_LDA + ak], asrc + kn + ak);
            cp16(&dA[ar * K4_LDA + ak + 4], asrc + kn + ak + 4);
            float* dB = sB + (st ^ 1) * 16 * K4_LDB;
            cp16(&dB[bk * K4_LDB + bf4], bsrc + (kn + bk) * 64 + bf4);
            CP_COMMIT();
            CP_WAIT(1);
        } else {
            CP_WAIT(0);
        }
        __syncthreads();

        const float* cA = sA + st * 128 * K4_LDA;
        const float* cB = sB + st * 16 * K4_LDB;
#pragma unroll
        for (int kk = 0; kk < 2; ++kk) {
            wmma::fragment<wmma::matrix_a, 16, 16, 8, wmma::precision::tf32, wmma::row_major> fa[2];
#pragma unroll
            for (int fr = 0; fr < 2; ++fr) {
                wmma::load_matrix_sync(fa[fr], &cA[(wr + fr * 16) * K4_LDA + kk * 8], K4_LDA);
#pragma unroll
                for (int e = 0; e < fa[fr].num_elements; ++e)
                    fa[fr].x[e] = wmma::__float_to_tf32(fa[fr].x[e]);
            }
#pragma unroll
            for (int fc = 0; fc < 2; ++fc) {
                wmma::fragment<wmma::matrix_b, 16, 16, 8, wmma::precision::tf32, wmma::row_major> fb;
                wmma::load_matrix_sync(fb, &cB[(kk * 8) * K4_LDB + wm + fc * 16], K4_LDB);
#pragma unroll
                for (int e = 0; e < fb.num_elements; ++e)
                    fb.x[e] = wmma::__float_to_tf32(fb.x[e]);
                wmma::mma_sync(acc[0][fc], fa[0], fb, acc[0][fc]);
                wmma::mma_sync(acc[1][fc], fa[1], fb, acc[1][fc]);
            }
        }
        __syncthreads();
    }

    float* scr = smemf + wid * 320;
#pragma unroll
    for (int fr = 0; fr < 2; ++fr) {
#pragma unroll
        for (int fc = 0; fc < 2; ++fc) {
            wmma::store_matrix_sync(scr, acc[fr][fc], 20, wmma::mem_row_major);
            __syncwarp();
            int rl = lane >> 1, half = lane & 1;
            int grow = rbase + wr + fr * 16 + rl;
            int f0 = wm + fc * 16 + half * 8;
            int idx = (((grow << 8) + n) << 6) + f0;
            float4 b0 = *(const float4*)&b2_[(n << 6) + f0];
            float4 b1v = *(const float4*)&b2_[(n << 6) + f0 + 4];
            float4 i0 = *(const float4*)&g_bufin[idx];
            float4 i1 = *(const float4*)&g_bufin[idx + 4];
            float z[8];
            z[0] = scr[rl * 20 + half * 8 + 0] + b0.x + i0.x;
            z[1] = scr[rl * 20 + half * 8 + 1] + b0.y + i0.y;
            z[2] = scr[rl * 20 + half * 8 + 2] + b0.z + i0.z;
            z[3] = scr[rl * 20 + half * 8 + 3] + b0.w + i0.w;
            z[4] = scr[rl * 20 + half * 8 + 4] + b1v.x + i1.x;
            z[5] = scr[rl * 20 + half * 8 + 5] + b1v.y + i1.y;
            z[6] = scr[rl * 20 + half * 8 + 6] + b1v.z + i1.z;
            z[7] = scr[rl * 20 + half * 8 + 7] + b1v.w + i1.w;

            const int branch = grow >> 9;
            const int b = (grow >> 8) & 1;
            const int g = grow & 255;
            int h, w;
            if (branch == 0) { h = ((n >> 4) << 4) | (g >> 4); w = ((n & 15) << 4) | (g & 15); }
            else             { h = ((g >> 4) << 4) | (n >> 4); w = ((g & 15) << 4) | (n & 15); }
            const int pix = (b << 16) | (h << 8) | w;
            const int obase = pix * 128 + branch * 64 + f0;
            float4 x0 = *(const float4*)&x[obase];
            float4 x1 = *(const float4*)&x[obase + 4];
            *(float4*)&out[obase]     = make_float4(z[0] + x0.x, z[1] + x0.y,
                                                    z[2] + x0.z, z[3] + x0.w);
            *(float4*)&out[obase + 4] = make_float4(z[4] + x1.x, z[5] + x1.y,
                                                    z[6] + x1.z, z[7] + x1.w);
            if (branch && write_glob) {
                *(float4*)&gout[pix * 64 + f0]     = make_float4(z[0], z[1], z[2], z[3]);
                *(float4*)&gout[pix * 64 + f0 + 4] = make_float4(z[4], z[5], z[6], z[7]);
            }
            __syncwarp();
        }
    }
}

// ---------------------------------------------------------------------------
extern "C" void kernel_launch(void* const* d_in, const int* in_sizes, int n_in,
                              void* d_out, int out_size)
{
    const float* x    = (const float*)d_in[0];
    const float* ln1g = (const float*)d_in[1];
    const float* ln1b = (const float*)d_in[2];
    const float* Wp   = (const float*)d_in[3];
    const float* bp   = (const float*)d_in[4];
    const float* ln2g = (const float*)d_in[5];
    const float* ln2b = (const float*)d_in[6];
    const float* W1   = (const float*)d_in[7];
    const float* b1   = (const float*)d_in[8];
    const float* ln3g = (const float*)d_in[9];
    const float* ln3b = (const float*)d_in[10];
    const float* Wsgu = (const float*)d_in[11];
    const float* bsgu = (const float*)d_in[12];
    const float* W2   = (const float*)d_in[13];
    const float* b2   = (const float*)d_in[14];

    float* out = (float*)d_out;
    const int OUT_MAIN = 2 * 256 * 256 * 128;
    const int OUT_GLOB = 2 * 256 * 256 * 64;
    int write_glob = (out_size >= OUT_MAIN + OUT_GLOB) ? 1 : 0;
    float* gout = out + OUT_MAIN;

    static int configured = 0;
    if (!configured) {
        cudaFuncSetAttribute(k1_ln_proj,
            cudaFuncAttributeMaxDynamicSharedMemorySize, K1_SMEM);
        configured = 1;
    }

    k0_wsgu_t    <<<dim3(8, 8, 192), dim3(32, 8)>>>(Wsgu);
    k1_ln_proj   <<<1024, 256, K1_SMEM>>>(x, ln1g, ln1b, Wp, bp);
    k2_gmlp_in   <<<dim3(16, 256), 256>>>(W1, b1, ln2g, ln2b);
    k2b_ln3_t    <<<dim3(1024, 8, 1), 256>>>(ln3g, ln3b);
    k3_wmma      <<<dim3(8, 2, 192), 256>>>();
    k3b_gate_mul <<<dim3(1024, 8, 6), 256>>>(bsgu);
    k4_gmlp_out  <<<dim3(8, 256, 1), 256>>>(W2, b2, x, out, gout, write_glob);
}

// round 16
// speedup vs baseline: 1.7004x; 1.0094x over previous
#include <cuda_runtime.h>
#include <cuda_bf16.h>
#include <mma.h>
#include <math.h>
#include <cstdint>

using namespace nvcuda;

// ---------------------------------------------------------------------------
// Shapes: B=2, H=W=256, C=128, S=16 -> G=256, N=256, CI=64, F1=384, HF=192
// R = 2 branches * B * G = 1024
// ---------------------------------------------------------------------------
#define R_TOT   1024
#define NPATCH  256
#define CI_DIM  64
#define HF_DIM  192

__device__ float  g_bufin[R_TOT * NPATCH * CI_DIM];   // blocked gmlp input (fp32)
__device__ float2 g_stat [R_TOT * NPATCH];            // ln2 (mean, rstd) per (r,n)
__device__ float  g_v    [R_TOT * NPATCH * HF_DIM];   // v (fp32)
__device__ float  g_ut   [R_TOT * HF_DIM * NPATCH];   // uv [R][N][HF] (fp32)
__device__ __align__(16) __nv_bfloat16 g_upreb [R_TOT * NPATCH * HF_DIM]; // u bf16; later raw gate [r][c][n]
__device__ __align__(16) __nv_bfloat16 g_utb   [R_TOT * HF_DIM * NPATCH]; // ln3'd u^T bf16
__device__ __align__(16) __nv_bfloat16 g_wsgub [HF_DIM * NPATCH * NPATCH];// Wsgu^T bf16 [c][m][k]

__device__ __forceinline__ float gelu_exact(float x) {
    return 0.5f * x * (1.0f + erff(x * 0.7071067811865476f));
}

// ---- cp.async helpers ----
__device__ __forceinline__ void cp16(void* smem_dst, const void* gsrc) {
    uint32_t d = (uint32_t)__cvta_generic_to_shared(smem_dst);
    asm volatile("cp.async.cg.shared.global [%0], [%1], 16;"
                 :: "r"(d), "l"(gsrc) : "memory");
}
#define CP_COMMIT()  asm volatile("cp.async.commit_group;" ::: "memory")
#define CP_WAIT(n)   asm volatile("cp.async.wait_group %0;" :: "n"(n) : "memory")

__device__ __forceinline__ uint4 pack8bf(const float* v) {
    union { __nv_bfloat16 h[8]; uint4 u; } r;
#pragma unroll
    for (int i = 0; i < 8; ++i) r.h[i] = __float2bfloat16(v[i]);
    return r.u;
}

// ---------------------------------------------------------------------------
// K0: Wsgu [c][n][m] fp32 -> g_wsgub [c][m][n] bf16
// ---------------------------------------------------------------------------
__global__ __launch_bounds__(256) void k0_wsgu_t(const float* __restrict__ Wsgu)
{
    __shared__ float tile[32][33];
    const int c  = blockIdx.z;
    const int mb = blockIdx.x * 32;
    const int nb = blockIdx.y * 32;
    const int tx = threadIdx.x, ty = threadIdx.y;
#pragma unroll
    for (int j = 0; j < 4; ++j) {
        int n = ty + j * 8;
        tile[n][tx] = Wsgu[(((size_t)c << 8) + nb + n) * 256 + mb + tx];
    }
    __syncthreads();
#pragma unroll
    for (int j = 0; j < 4; ++j) {
        int m = ty + j * 8;
        g_wsgub[(((size_t)c << 8) + mb + m) * 256 + nb + tx] =
            __float2bfloat16(tile[tx][m]);
    }
}

// ---------------------------------------------------------------------------
// K1: tf32 wmma (RN): ln1 + Dense(W_proj) + GELU, scatter blocked + ln2 stats
// grid 1024 x 256 thr; 128 pixels/CTA; block 128x128, K=128.
// ---------------------------------------------------------------------------
#define K1_SMEM ((128 * 128 + 16 * 128) * 4)
__global__ __launch_bounds__(256) void k1_ln_proj(
    const float* __restrict__ x, const float* __restrict__ ln1g,
    const float* __restrict__ ln1b, const float* __restrict__ Wp,
    const float* __restrict__ bp)
{
    extern __shared__ float dsm[];
    float* sA = dsm;                 // [c][row] 128x128
    float* sB = dsm + 128 * 128;     // [k][f]   16x128
    __shared__ float sg[128], sb[128];
    const int t = threadIdx.x;
    const int wid = t >> 5, lane = t & 31;
    const int pbase = blockIdx.x * 128;

    if (t < 128) { sg[t] = ln1g[t]; sb[t] = ln1b[t]; }
    __syncthreads();

    {
        const int row = t >> 1, half = t & 1;
        const float* src = x + (size_t)(pbase + row) * 128 + half * 64;
        float4 v[16];
        float s = 0.f, s2 = 0.f;
#pragma unroll
        for (int j = 0; j < 16; ++j) {
            v[j] = *(const float4*)&src[j * 4];
            s  += v[j].x + v[j].y + v[j].z + v[j].w;
            s2 += v[j].x * v[j].x + v[j].y * v[j].y + v[j].z * v[j].z + v[j].w * v[j].w;
        }
        s  += __shfl_xor_sync(0xffffffffu, s,  1);
        s2 += __shfl_xor_sync(0xffffffffu, s2, 1);
        float m  = s * (1.f / 128.f);
        float rs = rsqrtf(s2 * (1.f / 128.f) - m * m + 1e-3f);
#pragma unroll
        for (int j = 0; j < 16; ++j) {
            int c = half * 64 + j * 4;
            sA[(c + 0) * 128 + row] = (v[j].x - m) * rs * sg[c + 0] + sb[c + 0];
            sA[(c + 1) * 128 + row] = (v[j].y - m) * rs * sg[c + 1] + sb[c + 1];
            sA[(c + 2) * 128 + row] = (v[j].z - m) * rs * sg[c + 2] + sb[c + 2];
            sA[(c + 3) * 128 + row] = (v[j].w - m) * rs * sg[c + 3] + sb[c + 3];
        }
    }

    const int wr = (wid >> 1) * 32;
    const int wm = (wid & 1) * 64;
    wmma::fragment<wmma::accumulator, 16, 16, 8, float> acc[2][4];
#pragma unroll
    for (int i = 0; i < 2; ++i)
#pragma unroll
        for (int j = 0; j < 4; ++j) wmma::fill_fragment(acc[i][j], 0.0f);

    const int bk = t >> 4, bf8 = (t & 15) * 8;
    float4 rB0 = *(const float4*)&Wp[bk * 128 + bf8];
    float4 rB1 = *(const float4*)&Wp[bk * 128 + bf8 + 4];

    for (int s = 0; s < 8; ++s) {
        __syncthreads();
        *(float4*)&sB[bk * 128 + bf8]     = rB0;
        *(float4*)&sB[bk * 128 + bf8 + 4] = rB1;
        __syncthreads();
        if (s < 7) {
            rB0 = *(const float4*)&Wp[((s + 1) * 16 + bk) * 128 + bf8];
            rB1 = *(const float4*)&Wp[((s + 1) * 16 + bk) * 128 + bf8 + 4];
        }
#pragma unroll
        for (int kk = 0; kk < 2; ++kk) {
            wmma::fragment<wmma::matrix_a, 16, 16, 8, wmma::precision::tf32, wmma::col_major> fa[2];
#pragma unroll
            for (int fr = 0; fr < 2; ++fr) {
                wmma::load_matrix_sync(fa[fr], &sA[(s * 16 + kk * 8) * 128 + wr + fr * 16], 128);
#pragma unroll
                for (int e = 0; e < fa[fr].num_elements; ++e)
                    fa[fr].x[e] = wmma::__float_to_tf32(fa[fr].x[e]);
            }
#pragma unroll
            for (int fc = 0; fc < 4; ++fc) {
                wmma::fragment<wmma::matrix_b, 16, 16, 8, wmma::precision::tf32, wmma::row_major> fb;
                wmma::load_matrix_sync(fb, &sB[(kk * 8) * 128 + wm + fc * 16], 128);
#pragma unroll
                for (int e = 0; e < fb.num_elements; ++e)
                    fb.x[e] = wmma::__float_to_tf32(fb.x[e]);
                wmma::mma_sync(acc[0][fc], fa[0], fb, acc[0][fc]);
                wmma::mma_sync(acc[1][fc], fa[1], fb, acc[1][fc]);
            }
        }
    }
    __syncthreads();

    float* scr = dsm + wid * 320;
    const int branch = wm >> 6;
#pragma unroll
    for (int fr = 0; fr < 2; ++fr) {
        const int rl = lane >> 1, half = lane & 1;
        const int p = pbase + wr + fr * 16 + rl;
        const int b = p >> 16, h = (p >> 8) & 255, w = p & 255;
        const int g  = ((h >> 4) << 4) | (w >> 4);
        const int nn = ((h & 15) << 4) | (w & 15);
        const int r = branch * 512 + (b << 8) + g;
        float ss = 0.f, ss2 = 0.f;
#pragma unroll
        for (int fc = 0; fc < 4; ++fc) {
            wmma::store_matrix_sync(scr, acc[fr][fc], 20, wmma::mem_row_major);
            __syncwarp();
            const int f0 = wm + fc * 16 + half * 8;
            float4 b0 = *(const float4*)&bp[f0];
            float4 b1 = *(const float4*)&bp[f0 + 4];
            const float bias[8] = {b0.x, b0.y, b0.z, b0.w, b1.x, b1.y, b1.z, b1.w};
            float vals[8];
#pragma unroll
            for (int e = 0; e < 8; ++e) {
                vals[e] = gelu_exact(scr[rl * 20 + half * 8 + e] + bias[e]);
                ss += vals[e]; ss2 += vals[e] * vals[e];
            }
            const int cloc = f0 & 63;
            float* dst = &g_bufin[((size_t)(r << 8) + nn) * 64 + cloc];
            *(float4*)&dst[0] = make_float4(vals[0], vals[1], vals[2], vals[3]);
            *(float4*)&dst[4] = make_float4(vals[4], vals[5], vals[6], vals[7]);
            __syncwarp();
        }
        ss  += __shfl_xor_sync(0xffffffffu, ss,  1);
        ss2 += __shfl_xor_sync(0xffffffffu, ss2, 1);
        if ((lane & 1) == 0) {
            float m  = ss * (1.f / 64.f);
            float rs = rsqrtf(ss2 * (1.f / 64.f) - m * m + 1e-3f);
            g_stat[(r << 8) + nn] = make_float2(m, rs);
        }
    }
}

// ---------------------------------------------------------------------------
// K2: tf32 wmma (RN): y = gelu(ln2(bufin) @ W1[n] + b1[n]), FULL 384 f in
// one pass. Block 64 rows x 384 f, K=64 resident.
// grid (16 rtiles, 256 n) x 256 thr. Warps 2x4, warp tile 32x96, acc[2][6].
// ---------------------------------------------------------------------------
#define K2_LDA 68
#define K2_LDB 392
__global__ __launch_bounds__(256) void k2_gmlp_in(
    const float* __restrict__ W1, const float* __restrict__ b1_,
    const float* __restrict__ ln2g, const float* __restrict__ ln2b)
{
    __shared__ float sA[64 * K2_LDA];
    __shared__ float sB[16 * K2_LDB];
    __shared__ float sg[64], sb[64];
    const int t = threadIdx.x;
    const int wid = t >> 5, lane = t & 31;
    const int rbase = blockIdx.x * 64;
    const int n = blockIdx.y;

    if (t < 64) { sg[t] = ln2g[t]; sb[t] = ln2b[t]; }
    __syncthreads();

    {
        const int row = t >> 2, q = t & 3;
        const float* src = g_bufin + ((size_t)((rbase + row) << 8) + n) * 64;
        float2 st = g_stat[((rbase + row) << 8) + n];
#pragma unroll
        for (int j = 0; j < 4; ++j) {
            int k = q * 16 + j * 4;
            float4 v = *(const float4*)&src[k];
            sA[(k + 0) * K2_LDA + row] = (v.x - st.x) * st.y * sg[k + 0] + sb[k + 0];
            sA[(k + 1) * K2_LDA + row] = (v.y - st.x) * st.y * sg[k + 1] + sb[k + 1];
            sA[(k + 2) * K2_LDA + row] = (v.z - st.x) * st.y * sg[k + 2] + sb[k + 2];
            sA[(k + 3) * K2_LDA + row] = (v.w - st.x) * st.y * sg[k + 3] + sb[k + 3];
        }
    }

    const int wr = (wid >> 2) * 32;
    const int wm = (wid & 3) * 96;
    wmma::fragment<wmma::accumulator, 16, 16, 8, float> acc[2][6];
#pragma unroll
    for (int i = 0; i < 2; ++i)
#pragma unroll
        for (int j = 0; j < 6; ++j) wmma::fill_fragment(acc[i][j], 0.0f);

    const float* Wn = W1 + (size_t)n * 64 * 384;
    const int bk = t >> 4, bf4 = (t & 15) * 4;
    float4 rB[6];
#pragma unroll
    for (int j = 0; j < 6; ++j)
        rB[j] = *(const float4*)&Wn[bk * 384 + j * 64 + bf4];

    for (int s = 0; s < 4; ++s) {
        __syncthreads();
#pragma unroll
        for (int j = 0; j < 6; ++j)
            *(float4*)&sB[bk * K2_LDB + j * 64 + bf4] = rB[j];
        __syncthreads();
        if (s < 3) {
#pragma unroll
            for (int j = 0; j < 6; ++j)
                rB[j] = *(const float4*)&Wn[((s + 1) * 16 + bk) * 384 + j * 64 + bf4];
        }
#pragma unroll
        for (int kk = 0; kk < 2; ++kk) {
            wmma::fragment<wmma::matrix_a, 16, 16, 8, wmma::precision::tf32, wmma::col_major> fa[2];
#pragma unroll
            for (int fr = 0; fr < 2; ++fr) {
                wmma::load_matrix_sync(fa[fr], &sA[(s * 16 + kk * 8) * K2_LDA + wr + fr * 16], K2_LDA);
#pragma unroll
                for (int e = 0; e < fa[fr].num_elements; ++e)
                    fa[fr].x[e] = wmma::__float_to_tf32(fa[fr].x[e]);
            }
#pragma unroll
            for (int fc = 0; fc < 6; ++fc) {
                wmma::fragment<wmma::matrix_b, 16, 16, 8, wmma::precision::tf32, wmma::row_major> fb;
                wmma::load_matrix_sync(fb, &sB[(kk * 8) * K2_LDB + wm + fc * 16], K2_LDB);
#pragma unroll
                for (int e = 0; e < fb.num_elements; ++e)
                    fb.x[e] = wmma::__float_to_tf32(fb.x[e]);
                wmma::mma_sync(acc[0][fc], fa[0], fb, acc[0][fc]);
                wmma::mma_sync(acc[1][fc], fa[1], fb, acc[1][fc]);
            }
        }
    }
    __syncthreads();

    float* scr = sA + wid * 320;
#pragma unroll
    for (int fr = 0; fr < 2; ++fr) {
#pragma unroll
        for (int fc = 0; fc < 6; ++fc) {
            wmma::store_matrix_sync(scr, acc[fr][fc], 20, wmma::mem_row_major);
            __syncwarp();
            int rl = lane >> 1, half = lane & 1;
            int grow = rbase + wr + fr * 16 + rl;
            int f0 = wm + fc * 16 + half * 8;
            float vals[8];
            float4 b0 = *(const float4*)&b1_[n * 384 + f0];
            float4 b1v = *(const float4*)&b1_[n * 384 + f0 + 4];
            const float bias[8] = {b0.x, b0.y, b0.z, b0.w, b1v.x, b1v.y, b1v.z, b1v.w};
#pragma unroll
            for (int e = 0; e < 8; ++e)
                vals[e] = gelu_exact(scr[rl * 20 + half * 8 + e] + bias[e]);
            if (f0 < 192) {
                *(uint4*)&g_upreb[((size_t)(grow << 8) + n) * 192 + f0] = pack8bf(vals);
            } else {
                int fo = f0 - 192;
                float* dst = &g_v[((size_t)(grow << 8) + n) * 192 + fo];
                *(float4*)&dst[0] = make_float4(vals[0], vals[1], vals[2], vals[3]);
                *(float4*)&dst[4] = make_float4(vals[4], vals[5], vals[6], vals[7]);
            }
            __syncwarp();
        }
    }
}

// ---------------------------------------------------------------------------
// K2b: ln3 over u bf16 (HF=192) + transpose -> g_utb[r][c][n] (bf16)
// Strength-reduced load indexing: 3 divisions (not 24); stride-768 walk.
// ---------------------------------------------------------------------------
__global__ __launch_bounds__(256) void k2b_ln3_t(
    const float* __restrict__ ln3g, const float* __restrict__ ln3b)
{
    __shared__ float s[32][193];
    __shared__ float sm[32], sr[32];
    const int t = threadIdx.x;
    const int r = blockIdx.x;
    const int nb = blockIdx.y * 32;
    const __nv_bfloat16* src = g_upreb + (((size_t)r << 8) + nb) * 192;
#pragma unroll
    for (int jj = 0; jj < 3; ++jj) {
        const int lin0 = t + jj * 256;
        const int row0 = lin0 / 192;
        const int col  = lin0 - row0 * 192;
#pragma unroll
        for (int i = 0; i < 8; ++i) {
            s[row0 + i * 4][col] = __bfloat162float(src[lin0 + i * 768]);
        }
    }
    __syncthreads();
    const int warp = t >> 5, lane = t & 31;
#pragma unroll
    for (int j = 0; j < 4; ++j) {
        int row = warp * 4 + j;
        float su = 0.f, s2 = 0.f;
#pragma unroll
        for (int k = 0; k < 6; ++k) { float v = s[row][lane + k * 32]; su += v; s2 += v * v; }
#pragma unroll
        for (int off = 16; off > 0; off >>= 1) {
            su += __shfl_xor_sync(0xffffffffu, su, off);
            s2 += __shfl_xor_sync(0xffffffffu, s2, off);
        }
        if (lane == 0) {
            float m = su * (1.f / 192.f);
            sm[row] = m;
            sr[row] = rsqrtf(s2 * (1.f / 192.f) - m * m + 1e-3f);
        }
    }
    __syncthreads();
    const int n_l = t & 31, c0 = t >> 5;
    __nv_bfloat16* dst = g_utb + ((r * 192 + c0) << 8) + nb + n_l;
#pragma unroll
    for (int it = 0; it < 24; ++it) {
        int c = c0 + it * 8;
        float v = (s[n_l][c] - sm[n_l]) * sr[n_l] * ln3g[c] + ln3b[c];
        dst[it * (8 << 8)] = __float2bfloat16(v);
    }
}

// ---------------------------------------------------------------------------
// K3: spatial gating via wmma bf16, cp.async double-buffered.
// raw gate (no bias) -> g_upreb bf16 [r][c][n].
// grid (8 rtiles, 2 mtiles, 192 c) x 256 thr.
// ---------------------------------------------------------------------------
#define K3_LD 40
__global__ __launch_bounds__(256) void k3_wmma()
{
    __shared__ __align__(16) char smemraw[2 * 128 * K3_LD * 2 * 2];
    __nv_bfloat16* sA = (__nv_bfloat16*)smemraw;
    __nv_bfloat16* sB = sA + 2 * 128 * K3_LD;
    const int t = threadIdx.x;
    const int wid = t >> 5, lane = t & 31;
    const int rbase = blockIdx.x * 128;
    const int mbase = blockIdx.y * 128;
    const int c = blockIdx.z;

    const __nv_bfloat16* abase = g_utb + ((size_t)rbase * 192 + c) * 256;
    const __nv_bfloat16* bbase = g_wsgub + ((size_t)c << 16) + (size_t)mbase * 256;

    const int lr = t >> 1;
    const int lk = (t & 1) * 16;

    wmma::fragment<wmma::accumulator, 16, 16, 16, float> acc[2][4];
#pragma unroll
    for (int i = 0; i < 2; ++i)
#pragma unroll
        for (int j = 0; j < 4; ++j)
            wmma::fill_fragment(acc[i][j], 0.0f);

    const int wr = (wid >> 1) * 32;
    const int wm = (wid & 1) * 64;

    {
        const __nv_bfloat16* as = abase + (size_t)lr * (192 * 256) + lk;
        cp16(&sA[lr * K3_LD + lk], as);
        cp16(&sA[lr * K3_LD + lk + 8], as + 8);
        const __nv_bfloat16* bs = bbase + (size_t)lr * 256 + lk;
        cp16(&sB[lr * K3_LD + lk], bs);
        cp16(&sB[lr * K3_LD + lk + 8], bs + 8);
        CP_COMMIT();
    }

#pragma unroll
    for (int kb = 0; kb < 8; ++kb) {
        const int st = kb & 1;
        if (kb < 7) {
            const int kn = (kb + 1) * 32;
            const __nv_bfloat16* as = abase + (size_t)lr * (192 * 256) + kn + lk;
            cp16(&sA[(st ^ 1) * 128 * K3_LD + lr * K3_LD + lk], as);
            cp16(&sA[(st ^ 1) * 128 * K3_LD + lr * K3_LD + lk + 8], as + 8);
            const __nv_bfloat16* bs = bbase + (size_t)lr * 256 + kn + lk;
            cp16(&sB[(st ^ 1) * 128 * K3_LD + lr * K3_LD + lk], bs);
            cp16(&sB[(st ^ 1) * 128 * K3_LD + lr * K3_LD + lk + 8], bs + 8);
            CP_COMMIT();
            CP_WAIT(1);
        } else {
            CP_WAIT(0);
        }
        __syncthreads();

        const __nv_bfloat16* cA = sA + st * 128 * K3_LD;
        const __nv_bfloat16* cB = sB + st * 128 * K3_LD;
#pragma unroll
        for (int kk = 0; kk < 32; kk += 16) {
            wmma::fragment<wmma::matrix_a, 16, 16, 16, __nv_bfloat16, wmma::row_major> fa[2];
            wmma::load_matrix_sync(fa[0], &cA[(wr     ) * K3_LD + kk], K3_LD);
            wmma::load_matrix_sync(fa[1], &cA[(wr + 16) * K3_LD + kk], K3_LD);
#pragma unroll
            for (int j = 0; j < 4; ++j) {
                wmma::fragment<wmma::matrix_b, 16, 16, 16, __nv_bfloat16, wmma::col_major> fb;
                wmma::load_matrix_sync(fb, &cB[(wm + j * 16) * K3_LD + kk], K3_LD);
                wmma::mma_sync(acc[0][j], fa[0], fb, acc[0][j]);
                wmma::mma_sync(acc[1][j], fa[1], fb, acc[1][j]);
            }
        }
        __syncthreads();
    }

    float* scr = (float*)smemraw + wid * 320;
#pragma unroll
    for (int fr = 0; fr < 2; ++fr) {
#pragma unroll
        for (int fc = 0; fc < 4; ++fc) {
            wmma::store_matrix_sync(scr, acc[fr][fc], 20, wmma::mem_row_major);
            __syncwarp();
            int rl = lane >> 1, half = lane & 1;
            int grow = rbase + wr + fr * 16 + rl;
            int m0 = mbase + wm + fc * 16 + half * 8;
            float vals[8];
#pragma unroll
            for (int e = 0; e < 8; ++e) vals[e] = scr[rl * 20 + half * 8 + e];
            *(uint4*)&g_upreb[((size_t)grow * 192 + c) * 256 + m0] = pack8bf(vals);
            __syncwarp();
        }
    }
}

// ---------------------------------------------------------------------------
// K3b: uv[r][n][c] = (gate_bf16[r][c][n] + bsgu[c][n]) * v[r][n][c]
// ---------------------------------------------------------------------------
__global__ __launch_bounds__(256) void k3b_gate_mul(const float* __restrict__ bsgu)
{
    __shared__ float s[32][33];
    const int t = threadIdx.x;
    const int r = blockIdx.x;
    const int nb = blockIdx.y * 32;
    const int cb = blockIdx.z * 32;
    {
        const int cc = t >> 3, n0 = (t & 7) * 4;
        union { uint2 raw; __nv_bfloat16 h[4]; } gt;
        gt.raw = *(const uint2*)&g_upreb[((size_t)(r * 192 + cb + cc) << 8) + nb + n0];
        float4 bs = *(const float4*)&bsgu[((cb + cc) << 8) + nb + n0];
        s[cc][n0 + 0] = __bfloat162float(gt.h[0]) + bs.x;
        s[cc][n0 + 1] = __bfloat162float(gt.h[1]) + bs.y;
        s[cc][n0 + 2] = __bfloat162float(gt.h[2]) + bs.z;
        s[cc][n0 + 3] = __bfloat162float(gt.h[3]) + bs.w;
    }
    __syncthreads();
    {
        const int nn = t >> 3, c4 = (t & 7) * 4;
        int idx = (((r << 8) + nb + nn) * 192) + cb + c4;
        float4 vv = *(const float4*)&g_v[idx];
        float4 o = make_float4(s[c4 + 0][nn] * vv.x, s[c4 + 1][nn] * vv.y,
                               s[c4 + 2][nn] * vv.z, s[c4 + 3][nn] * vv.w);
        *(float4*)&g_ut[idx] = o;
    }
}

// ---------------------------------------------------------------------------
// K4: tf32 wmma (RN), cp.async TRIPLE-buffered: z = uv @ W2[n] + b2[n] +
// bufin, fused recon/concat/residual epilogue.
// ---------------------------------------------------------------------------
#define K4_LDA 20
#define K4_LDB 68
__global__ __launch_bounds__(256) void k4_gmlp_out(
    const float* __restrict__ W2, const float* __restrict__ b2_,
    const float* __restrict__ x, float* __restrict__ out,
    float* __restrict__ gout, int write_glob)
{
    __shared__ __align__(16) float smemf[3 * 128 * K4_LDA + 3 * 16 * K4_LDB];
    float* sA = smemf;                       // [3][128][K4_LDA]
    float* sB = smemf + 3 * 128 * K4_LDA;    // [3][16][K4_LDB]
    const int t = threadIdx.x;
    const int wid = t >> 5, lane = t & 31;
    const int rbase = blockIdx.x * 128;
    const int n = blockIdx.y;

    const int wr = (wid >> 1) * 32;
    const int wm = (wid & 1) * 32;
    wmma::fragment<wmma::accumulator, 16, 16, 8, float> acc[2][2];
#pragma unroll
    for (int i = 0; i < 2; ++i)
#pragma unroll
        for (int j = 0; j < 2; ++j) wmma::fill_fragment(acc[i][j], 0.0f);

    const int ar = t >> 1, ak = (t & 1) * 8;
    const float* asrc = g_ut + ((size_t)((rbase + ar) << 8) + n) * 192;
    const int bk = t >> 4, bf4 = (t & 15) * 4;
    const float* bsrc = W2 + (size_t)n * 192 * 64;

    // prologue: prefetch stages 0, 1
#pragma unroll
    for (int p = 0; p < 2; ++p) {
        float* dA = sA + p * 128 * K4_LDA;
        cp16(&dA[ar * K4_LDA + ak], asrc + p * 16 + ak);
        cp16(&dA[ar * K4_LDA + ak + 4], asrc + p * 16 + ak + 4);
        float* dB = sB + p * 16 * K4_LDB;
        cp16(&dB[bk * K4_LDB + bf4], bsrc + (p * 16 + bk) * 64 + bf4);
        CP_COMMIT();
    }

#pragma unroll
    for (int s = 0; s < 12; ++s) {
        const int st = s % 3;
        if (s < 10) {
            CP_WAIT(1);     // stage s complete (≤1 group pending)
        } else {
            CP_WAIT(0);
        }
        __syncthreads();
        if (s + 2 < 12) {
            const int pn = (s + 2) % 3;
            const int kn = (s + 2) * 16;
            float* dA = sA + pn * 128 * K4_LDA;
            cp16(&dA[ar * K4_LDA + ak], asrc + kn + ak);
            cp16(&dA[ar * K4_LDA + ak + 4], asrc + kn + ak + 4);
            float* dB = sB + pn * 16 * K4_LDB;
            cp16(&dB[bk * K4_LDB + bf4], bsrc + (kn + bk) * 64 + bf4);
            CP_COMMIT();
        }

        const float* cA = sA + st * 128 * K4_LDA;
        const float* cB = sB + st * 16 * K4_LDB;
#pragma unroll
        for (int kk = 0; kk < 2; ++kk) {
            wmma::fragment<wmma::matrix_a, 16, 16, 8, wmma::precision::tf32, wmma::row_major> fa[2];
#pragma unroll
            for (int fr = 0; fr < 2; ++fr) {
                wmma::load_matrix_sync(fa[fr], &cA[(wr + fr * 16) * K4_LDA + kk * 8], K4_LDA);
#pragma unroll
                for (int e = 0; e < fa[fr].num_elements; ++e)
                    fa[fr].x[e] = wmma::__float_to_tf32(fa[fr].x[e]);
            }
#pragma unroll
            for (int fc = 0; fc < 2; ++fc) {
                wmma::fragment<wmma::matrix_b, 16, 16, 8, wmma::precision::tf32, wmma::row_major> fb;
                wmma::load_matrix_sync(fb, &cB[(kk * 8) * K4_LDB + wm + fc * 16], K4_LDB);
#pragma unroll
                for (int e = 0; e < fb.num_elements; ++e)
                    fb.x[e] = wmma::__float_to_tf32(fb.x[e]);
                wmma::mma_sync(acc[0][fc], fa[0], fb, acc[0][fc]);
                wmma::mma_sync(acc[1][fc], fa[1], fb, acc[1][fc]);
            }
        }
        __syncthreads();   // stage st fully consumed before its buffer is refilled
    }

    float* scr = smemf + wid * 320;
#pragma unroll
    for (int fr = 0; fr < 2; ++fr) {
#pragma unroll
        for (int fc = 0; fc < 2; ++fc) {
            wmma::store_matrix_sync(scr, acc[fr][fc], 20, wmma::mem_row_major);
            __syncwarp();
            int rl = lane >> 1, half = lane & 1;
            int grow = rbase + wr + fr * 16 + rl;
            int f0 = wm + fc * 16 + half * 8;
            int idx = (((grow << 8) + n) << 6) + f0;
            float4 b0 = *(const float4*)&b2_[(n << 6) + f0];
            float4 b1v = *(const float4*)&b2_[(n << 6) + f0 + 4];
            float4 i0 = *(const float4*)&g_bufin[idx];
            float4 i1 = *(const float4*)&g_bufin[idx + 4];
            float z[8];
            z[0] = scr[rl * 20 + half * 8 + 0] + b0.x + i0.x;
            z[1] = scr[rl * 20 + half * 8 + 1] + b0.y + i0.y;
            z[2] = scr[rl * 20 + half * 8 + 2] + b0.z + i0.z;
            z[3] = scr[rl * 20 + half * 8 + 3] + b0.w + i0.w;
            z[4] = scr[rl * 20 + half * 8 + 4] + b1v.x + i1.x;
            z[5] = scr[rl * 20 + half * 8 + 5] + b1v.y + i1.y;
            z[6] = scr[rl * 20 + half * 8 + 6] + b1v.z + i1.z;
            z[7] = scr[rl * 20 + half * 8 + 7] + b1v.w + i1.w;

            const int branch = grow >> 9;
            const int b = (grow >> 8) & 1;
            const int g = grow & 255;
            int h, w;
            if (branch == 0) { h = ((n >> 4) << 4) | (g >> 4); w = ((n & 15) << 4) | (g & 15); }
            else             { h = ((g >> 4) << 4) | (n >> 4); w = ((g & 15) << 4) | (n & 15); }
            const int pix = (b << 16) | (h << 8) | w;
            const int obase = pix * 128 + branch * 64 + f0;
            float4 x0 = *(const float4*)&x[obase];
            float4 x1 = *(const float4*)&x[obase + 4];
            *(float4*)&out[obase]     = make_float4(z[0] + x0.x, z[1] + x0.y,
                                                    z[2] + x0.z, z[3] + x0.w);
            *(float4*)&out[obase + 4] = make_float4(z[4] + x1.x, z[5] + x1.y,
                                                    z[6] + x1.z, z[7] + x1.w);
            if (branch && write_glob) {
                *(float4*)&gout[pix * 64 + f0]     = make_float4(z[0], z[1], z[2], z[3]);
                *(float4*)&gout[pix * 64 + f0 + 4] = make_float4(z[4], z[5], z[6], z[7]);
            }
            __syncwarp();
        }
    }
}

// ---------------------------------------------------------------------------
extern "C" void kernel_launch(void* const* d_in, const int* in_sizes, int n_in,
                              void* d_out, int out_size)
{
    const float* x    = (const float*)d_in[0];
    const float* ln1g = (const float*)d_in[1];
    const float* ln1b = (const float*)d_in[2];
    const float* Wp   = (const float*)d_in[3];
    const float* bp   = (const float*)d_in[4];
    const float* ln2g = (const float*)d_in[5];
    const float* ln2b = (const float*)d_in[6];
    const float* W1   = (const float*)d_in[7];
    const float* b1   = (const float*)d_in[8];
    const float* ln3g = (const float*)d_in[9];
    const float* ln3b = (const float*)d_in[10];
    const float* Wsgu = (const float*)d_in[11];
    const float* bsgu = (const float*)d_in[12];
    const float* W2   = (const float*)d_in[13];
    const float* b2   = (const float*)d_in[14];

    float* out = (float*)d_out;
    const int OUT_MAIN = 2 * 256 * 256 * 128;
    const int OUT_GLOB = 2 * 256 * 256 * 64;
    int write_glob = (out_size >= OUT_MAIN + OUT_GLOB) ? 1 : 0;
    float* gout = out + OUT_MAIN;

    static int configured = 0;
    if (!configured) {
        cudaFuncSetAttribute(k1_ln_proj,
            cudaFuncAttributeMaxDynamicSharedMemorySize, K1_SMEM);
        configured = 1;
    }

    k0_wsgu_t    <<<dim3(8, 8, 192), dim3(32, 8)>>>(Wsgu);
    k1_ln_proj   <<<1024, 256, K1_SMEM>>>(x, ln1g, ln1b, Wp, bp);
    k2_gmlp_in   <<<dim3(16, 256), 256>>>(W1, b1, ln2g, ln2b);
    k2b_ln3_t    <<<dim3(1024, 8, 1), 256>>>(ln3g, ln3b);
    k3_wmma      <<<dim3(8, 2, 192), 256>>>();
    k3b_gate_mul <<<dim3(1024, 8, 6), 256>>>(bsgu);
    k4_gmlp_out  <<<dim3(8, 256, 1), 256>>>(W2, b2, x, out, gout, write_glob);
}